// round 7
// baseline (speedup 1.0000x reference)
#include <cuda_runtime.h>
#include <cuda_bf16.h>
#include <cuda_fp16.h>
#include <math.h>
#include <stdint.h>

// Problem constants
#define BB 2
#define NN 2048
#define CC 1664
#define HH 16
#define DD 104
#define C3 (3 * CC)          // 4992
#define TOKENS (BB * NN)     // 4096

// ---------------------------------------------------------------------------
// Scratch (no allocations allowed)
// ---------------------------------------------------------------------------
__device__ __align__(256) float g_qkv[(size_t)TOKENS * C3];
__device__ __align__(256) __nv_bfloat16 g_xh[(size_t)TOKENS * CC];
__device__ __align__(256) __nv_bfloat16 g_xl[(size_t)TOKENS * CC];
__device__ __align__(256) __nv_bfloat16 g_ah[(size_t)TOKENS * CC];
__device__ __align__(256) __nv_bfloat16 g_al[(size_t)TOKENS * CC];
__device__ __align__(256) __nv_bfloat16 g_wqh[(size_t)C3 * CC];
__device__ __align__(256) __nv_bfloat16 g_wql[(size_t)C3 * CC];
__device__ __align__(256) __nv_bfloat16 g_wph[(size_t)CC * CC];
__device__ __align__(256) __nv_bfloat16 g_wpl[(size_t)CC * CC];
// attention operand buffers: Q/K padded to 128 dims (bf16), V transposed [d][n] (fp16)
__device__ __align__(256) __nv_bfloat16 g_qh[(size_t)BB * HH * NN * 128];
__device__ __align__(256) __nv_bfloat16 g_ql[(size_t)BB * HH * NN * 128];
__device__ __align__(256) __nv_bfloat16 g_kh[(size_t)BB * HH * NN * 128];
__device__ __align__(256) __nv_bfloat16 g_kl[(size_t)BB * HH * NN * 128];
__device__ __align__(256) __half g_vth[(size_t)BB * HH * DD * NN];
__device__ __align__(256) __half g_vtl[(size_t)BB * HH * DD * NN];

// ---------------------------------------------------------------------------
// Helpers
// ---------------------------------------------------------------------------
__device__ __forceinline__ uint32_t smem_u32(const void* p) {
    uint32_t a;
    asm("{ .reg .u64 t; cvta.to.shared.u64 t, %1; cvt.u32.u64 %0, t; }" : "=r"(a) : "l"(p));
    return a;
}
__device__ __forceinline__ void cp_async16(uint32_t dst, const void* src) {
    asm volatile("cp.async.cg.shared.global [%0], [%1], 16;" :: "r"(dst), "l"(src));
}
__device__ __forceinline__ void cp_commit() {
    asm volatile("cp.async.commit_group;");
}
__device__ __forceinline__ void ldmatrix_x4(uint32_t* r, uint32_t addr) {
    asm volatile("ldmatrix.sync.aligned.m8n8.x4.shared.b16 {%0,%1,%2,%3}, [%4];"
                 : "=r"(r[0]), "=r"(r[1]), "=r"(r[2]), "=r"(r[3]) : "r"(addr));
}
__device__ __forceinline__ void ldmatrix_x2(uint32_t* r, uint32_t addr) {
    asm volatile("ldmatrix.sync.aligned.m8n8.x2.shared.b16 {%0,%1}, [%2];"
                 : "=r"(r[0]), "=r"(r[1]) : "r"(addr));
}
__device__ __forceinline__ void mma_bf16(float* c, const uint32_t* a, const uint32_t* b) {
    asm volatile("mma.sync.aligned.m16n8k16.row.col.f32.bf16.bf16.f32 "
                 "{%0,%1,%2,%3}, {%4,%5,%6,%7}, {%8,%9}, {%0,%1,%2,%3};"
                 : "+f"(c[0]), "+f"(c[1]), "+f"(c[2]), "+f"(c[3])
                 : "r"(a[0]), "r"(a[1]), "r"(a[2]), "r"(a[3]), "r"(b[0]), "r"(b[1]));
}
__device__ __forceinline__ void mma_f16(float* c, const uint32_t* a, const uint32_t* b) {
    asm volatile("mma.sync.aligned.m16n8k16.row.col.f32.f16.f16.f32 "
                 "{%0,%1,%2,%3}, {%4,%5,%6,%7}, {%8,%9}, {%0,%1,%2,%3};"
                 : "+f"(c[0]), "+f"(c[1]), "+f"(c[2]), "+f"(c[3])
                 : "r"(a[0]), "r"(a[1]), "r"(a[2]), "r"(a[3]), "r"(b[0]), "r"(b[1]));
}
__device__ __forceinline__ void pack_hilo(float a, float b, uint32_t& hi, uint32_t& lo) {
    const __nv_bfloat16 ha = __float2bfloat16(a);
    const __nv_bfloat16 hb = __float2bfloat16(b);
    const __nv_bfloat16 la = __float2bfloat16(a - __bfloat162float(ha));
    const __nv_bfloat16 lb = __float2bfloat16(b - __bfloat162float(hb));
    hi = (uint32_t)*reinterpret_cast<const uint16_t*>(&ha) |
         ((uint32_t)*reinterpret_cast<const uint16_t*>(&hb) << 16);
    lo = (uint32_t)*reinterpret_cast<const uint16_t*>(&la) |
         ((uint32_t)*reinterpret_cast<const uint16_t*>(&lb) << 16);
}
__device__ __forceinline__ uint32_t pack_f16(float a, float b) {
    __half2 h = __floats2half2_rn(a, b);
    return *reinterpret_cast<uint32_t*>(&h);
}

// ---------------------------------------------------------------------------
// fp32 -> bf16 hi/lo split
// ---------------------------------------------------------------------------
__global__ void convert_split_kernel(const float* __restrict__ src,
                                     __nv_bfloat16* __restrict__ hi,
                                     __nv_bfloat16* __restrict__ lo, int n) {
    for (int i = blockIdx.x * blockDim.x + threadIdx.x; i < n; i += gridDim.x * blockDim.x) {
        const float v = src[i];
        const __nv_bfloat16 h = __float2bfloat16(v);
        hi[i] = h;
        lo[i] = __float2bfloat16(v - __bfloat162float(h));
    }
}

// ---------------------------------------------------------------------------
// W[Kr][Nc] row-major  ->  T[Nc][Kr] bf16 hi/lo
// ---------------------------------------------------------------------------
__global__ void transpose_split_kernel(const float* __restrict__ W,
                                       __nv_bfloat16* __restrict__ Th,
                                       __nv_bfloat16* __restrict__ Tl,
                                       int Kr, int Nc) {
    __shared__ float t[32][33];
    const int x = blockIdx.x * 32 + threadIdx.x;
    const int y0 = blockIdx.y * 32;
    for (int j = threadIdx.y; j < 32; j += 8)
        t[j][threadIdx.x] = W[(size_t)(y0 + j) * Nc + x];
    __syncthreads();
    const int ox = y0 + threadIdx.x;
    const int oy0 = blockIdx.x * 32;
    for (int j = threadIdx.y; j < 32; j += 8) {
        const float v = t[threadIdx.x][j];
        const __nv_bfloat16 h = __float2bfloat16(v);
        Th[(size_t)(oy0 + j) * Kr + ox] = h;
        Tl[(size_t)(oy0 + j) * Kr + ox] = __float2bfloat16(v - __bfloat162float(h));
    }
}

// ---------------------------------------------------------------------------
// mma.sync GEMM: 4-stage cp.async pipeline, one sync per chunk.
// ---------------------------------------------------------------------------
#define TILE_BYTES 8192
#define STAGE_BYTES 32768

__global__ __launch_bounds__(256, 1)
void mma_gemm_kernel(const __nv_bfloat16* __restrict__ Ah,
                     const __nv_bfloat16* __restrict__ Al,
                     const __nv_bfloat16* __restrict__ Bh,
                     const __nv_bfloat16* __restrict__ Bl,
                     const float* __restrict__ bias,
                     float* __restrict__ Cout,
                     int M, int N, int K) {
    extern __shared__ char smem[];
    const uint32_t sbase = smem_u32(smem);
    const int tid  = threadIdx.x;
    const int lane = tid & 31;
    const int wid  = tid >> 5;
    const int wm   = wid & 1;
    const int wn   = wid >> 1;
    const int crow = blockIdx.y * 128;
    const int ccol = blockIdx.x * 128;

    const __nv_bfloat16* gsrc[4];
    gsrc[0] = Ah + (size_t)crow * K;
    gsrc[1] = Al + (size_t)crow * K;
    gsrc[2] = Bh + (size_t)ccol * K;
    gsrc[3] = Bl + (size_t)ccol * K;

    const int lc  = tid & 3;
    const int lr0 = tid >> 2;
    const int lr1 = lr0 + 64;
    const uint32_t sw0 = (uint32_t)((lc ^ ((lr0 >> 1) & 3)) << 4);
    const uint32_t sw1 = (uint32_t)((lc ^ ((lr1 >> 1) & 3)) << 4);

    float acc[4][4][4];
#pragma unroll
    for (int mt = 0; mt < 4; ++mt)
#pragma unroll
        for (int nt = 0; nt < 4; ++nt)
#pragma unroll
            for (int j = 0; j < 4; ++j) acc[mt][nt][j] = 0.0f;

    const int nch = K / 32;

    auto load_stage = [&](int stage, int k0) {
        const uint32_t sb = sbase + (uint32_t)stage * STAGE_BYTES;
#pragma unroll
        for (int t = 0; t < 4; ++t) {
            const __nv_bfloat16* g = gsrc[t];
            cp_async16(sb + t * TILE_BYTES + lr0 * 64 + sw0,
                       g + (size_t)lr0 * K + k0 + lc * 8);
            cp_async16(sb + t * TILE_BYTES + lr1 * 64 + sw1,
                       g + (size_t)lr1 * K + k0 + lc * 8);
        }
        cp_commit();
    };

    load_stage(0, 0);
    load_stage(1, 32);
    load_stage(2, 64);

    const int a_lrow   = (lane & 7) + ((lane >> 3) & 1) * 8;
    const int a_lchunk = lane >> 4;
    const int b_lrow   = lane & 7;
    const int b_lchunk = (lane >> 3) & 1;

    for (int ch = 0; ch < nch; ++ch) {
        // pending loads: ch .. min(ch+2, nch-1); need chunk ch complete
        if (ch + 3 <= nch) {
            asm volatile("cp.async.wait_group 2;");
        } else if (ch + 2 <= nch) {
            asm volatile("cp.async.wait_group 1;");
        } else {
            asm volatile("cp.async.wait_group 0;");
        }
        __syncthreads();
        if (ch + 3 < nch) load_stage((ch + 3) & 3, (ch + 3) * 32);

        const uint32_t sb = sbase + (uint32_t)(ch & 3) * STAGE_BYTES;

#pragma unroll
        for (int ks = 0; ks < 2; ++ks) {
            uint32_t afh[4][4], afl[4][4], bfh[4][2], bfl[4][2];
#pragma unroll
            for (int mt = 0; mt < 4; ++mt) {
                const int row = wm * 64 + mt * 16 + a_lrow;
                const int chn = 2 * ks + a_lchunk;
                const uint32_t addr = sb + (uint32_t)(row * 64)
                                    + (uint32_t)((chn ^ ((row >> 1) & 3)) << 4);
                ldmatrix_x4(afh[mt], addr);
                ldmatrix_x4(afl[mt], addr + TILE_BYTES);
            }
#pragma unroll
            for (int nt = 0; nt < 4; ++nt) {
                const int row = wn * 32 + nt * 8 + b_lrow;
                const int chn = 2 * ks + b_lchunk;
                const uint32_t addr = sb + 2 * TILE_BYTES + (uint32_t)(row * 64)
                                    + (uint32_t)((chn ^ ((row >> 1) & 3)) << 4);
                ldmatrix_x2(bfh[nt], addr);
                ldmatrix_x2(bfl[nt], addr + TILE_BYTES);
            }
#pragma unroll
            for (int mt = 0; mt < 4; ++mt)
#pragma unroll
                for (int nt = 0; nt < 4; ++nt) {
                    mma_bf16(acc[mt][nt], afh[mt], bfh[nt]);
                    mma_bf16(acc[mt][nt], afh[mt], bfl[nt]);
                    mma_bf16(acc[mt][nt], afl[mt], bfh[nt]);
                }
        }
    }

    const int erow = lane >> 2;
    const int ecol = (lane & 3) * 2;
#pragma unroll
    for (int mt = 0; mt < 4; ++mt) {
#pragma unroll
        for (int nt = 0; nt < 4; ++nt) {
            const int col = ccol + wn * 32 + nt * 8 + ecol;
            const float b0 = bias[col], b1 = bias[col + 1];
            const int r0 = crow + wm * 64 + mt * 16 + erow;
            float2* p0 = reinterpret_cast<float2*>(Cout + (size_t)r0 * N + col);
            *p0 = make_float2(acc[mt][nt][0] + b0, acc[mt][nt][1] + b1);
            float2* p1 = reinterpret_cast<float2*>(Cout + (size_t)(r0 + 8) * N + col);
            *p1 = make_float2(acc[mt][nt][2] + b0, acc[mt][nt][3] + b1);
        }
    }
}

// ---------------------------------------------------------------------------
// qk_prep: fused RoPE + scale (q) + bf16 hi/lo split into padded [bh][n][128]
// ---------------------------------------------------------------------------
__global__ void qk_prep_kernel(const int* __restrict__ coords,
                               const float* __restrict__ qkv,
                               __nv_bfloat16* __restrict__ Qh, __nv_bfloat16* __restrict__ Ql,
                               __nv_bfloat16* __restrict__ Kh, __nv_bfloat16* __restrict__ Kl) {
    const int token = blockIdx.x;
    const int tid = threadIdx.x;   // 128
    __shared__ float cs[DD], sn[DD];

    const int c0 = coords[token * 3 + 0];
    const int c1 = coords[token * 3 + 1];
    const int c2 = coords[token * 3 + 2];
    if (tid < DD) {
        const int j = tid;
        int jj, dd, coord;
        if (j < 34)      { const int u = j;      jj = (u < 17) ? u : u - 17; dd = 34; coord = c0; }
        else if (j < 68) { const int u = j - 34; jj = (u < 17) ? u : u - 17; dd = 34; coord = c1; }
        else             { const int u = j - 68; jj = (u < 18) ? u : u - 18; dd = 36; coord = c2; }
        const float inv = powf(10000.0f, -(2.0f * (float)jj) / (float)dd);
        const float ang = (float)coord * inv;
        cs[j] = cosf(ang);
        sn[j] = sinf(ang);
    }
    __syncthreads();

    const int b = token >> 11, n = token & (NN - 1);
    const float scale = rsqrtf((float)DD);
    const float* base = qkv + (size_t)token * C3;

    for (int h = 0; h < HH; ++h) {
        const size_t o = ((size_t)(b * HH + h) * NN + n) * 128 + tid;
        if (tid < DD) {
            const int j = tid;
            const float qa = base[h * DD + j];
            const float qrot = (j < 52) ? -base[h * DD + j + 52] : base[h * DD + j - 52];
            const float qv = (qa * cs[j] + qrot * sn[j]) * scale;
            const __nv_bfloat16 qhv = __float2bfloat16(qv);
            Qh[o] = qhv;
            Ql[o] = __float2bfloat16(qv - __bfloat162float(qhv));

            const float ka = base[CC + h * DD + j];
            const float krot = (j < 52) ? -base[CC + h * DD + j + 52] : base[CC + h * DD + j - 52];
            const float kv = ka * cs[j] + krot * sn[j];
            const __nv_bfloat16 khv = __float2bfloat16(kv);
            Kh[o] = khv;
            Kl[o] = __float2bfloat16(kv - __bfloat162float(khv));
        } else {
            const __nv_bfloat16 z = __float2bfloat16(0.0f);
            Qh[o] = z; Ql[o] = z; Kh[o] = z; Kl[o] = z;
        }
    }
}

// ---------------------------------------------------------------------------
// vt_prep: V [token][h][d] fp32 -> Vt [bh][d][n] fp16 hi/lo (transpose)
// ---------------------------------------------------------------------------
__global__ void vt_prep_kernel(const float* __restrict__ qkv,
                               __half* __restrict__ Vth,
                               __half* __restrict__ Vtl) {
    __shared__ float t[32][33];
    const int bh = blockIdx.z;
    const int b = bh >> 4, h = bh & 15;
    const int n0 = blockIdx.x * 32;
    const int d0 = blockIdx.y * 32;
    const int tx = threadIdx.x, ty = threadIdx.y;
#pragma unroll
    for (int j = 0; j < 4; ++j) {
        const int d = d0 + tx, n = n0 + ty + 8 * j;
        if (d < DD)
            t[ty + 8 * j][tx] = qkv[(size_t)(b * NN + n) * C3 + 2 * CC + h * DD + d];
    }
    __syncthreads();
#pragma unroll
    for (int j = 0; j < 4; ++j) {
        const int d = d0 + ty + 8 * j, n = n0 + tx;
        if (d < DD) {
            const float v = t[tx][ty + 8 * j];
            const __half hv = __float2half_rn(v);
            const size_t o = ((size_t)bh * DD + d) * NN + n;
            Vth[o] = hv;
            Vtl[o] = __float2half_rn(v - __half2float(hv));
        }
    }
}

// ---------------------------------------------------------------------------
// Flash attention: QK^T in bf16 hi/lo (3-term), PV in fp16 (P single-precision
// fp16, V fp16 hi/lo) — P noise 2^-11 vs bf16's 2^-9. 3-stage pipeline.
// ---------------------------------------------------------------------------
#define AT_STAGE 59392
#define AT_KL 16384
#define AT_V 32768
#define AT_VL 46080

__global__ __launch_bounds__(256, 1)
void attn_mma_kernel(const __nv_bfloat16* __restrict__ Qh, const __nv_bfloat16* __restrict__ Ql,
                     const __nv_bfloat16* __restrict__ Kh, const __nv_bfloat16* __restrict__ Kl,
                     const __half* __restrict__ Vth, const __half* __restrict__ Vtl,
                     __nv_bfloat16* __restrict__ Oh, __nv_bfloat16* __restrict__ Ol) {
    extern __shared__ char smem[];
    const uint32_t sb = smem_u32(smem);
    const int tid = threadIdx.x, lane = tid & 31, wid = tid >> 5;
    const int qt = blockIdx.x, h = blockIdx.y, b = blockIdx.z;
    const int bh = b * HH + h;

    const __nv_bfloat16* qh_p = Qh + ((size_t)bh * NN + qt * 128) * 128;
    const __nv_bfloat16* ql_p = Ql + ((size_t)bh * NN + qt * 128) * 128;
    const __nv_bfloat16* kh_p = Kh + (size_t)bh * NN * 128;
    const __nv_bfloat16* kl_p = Kl + (size_t)bh * NN * 128;
    const __half* vh_p = Vth + (size_t)bh * DD * NN;
    const __half* vl_p = Vtl + (size_t)bh * DD * NN;

    // ---- stage Q (14 data chunks per 256B row), extract a-frags ----
    for (int i = tid; i < 128 * 14; i += 256) {
        const int row = i / 14, c = i % 14;
        const uint32_t off = row * 256 + ((c ^ (row & 7)) << 4);
        cp_async16(sb + off, qh_p + row * 128 + c * 8);
        cp_async16(sb + AT_STAGE + off, ql_p + row * 128 + c * 8);
    }
    cp_commit();
    asm volatile("cp.async.wait_group 0;");
    __syncthreads();

    uint32_t qah[7][4], qal[7][4];
    {
        const int arow = wid * 16 + (lane & 7) + ((lane >> 3) & 1) * 8;
#pragma unroll
        for (int j = 0; j < 7; ++j) {
            const int chn = 2 * j + (lane >> 4);
            const uint32_t addr = sb + arow * 256 + ((chn ^ (arow & 7)) << 4);
            ldmatrix_x4(qah[j], addr);
            ldmatrix_x4(qal[j], addr + AT_STAGE);
        }
    }
    __syncthreads();

    float oc[13][4];
#pragma unroll
    for (int i = 0; i < 13; ++i) { oc[i][0] = oc[i][1] = oc[i][2] = oc[i][3] = 0.0f; }
    float m0 = -1e30f, m1 = -1e30f, l0 = 0.0f, l1 = 0.0f;

    auto load_stage = [&](int s, int kt) {
        const uint32_t st = sb + (uint32_t)s * AT_STAGE;
        const __nv_bfloat16* kh_t = kh_p + (size_t)kt * 64 * 128;
        const __nv_bfloat16* kl_t = kl_p + (size_t)kt * 64 * 128;
        for (int i = tid; i < 64 * 14; i += 256) {
            const int row = i / 14, c = i % 14;
            const uint32_t off = row * 256 + ((c ^ (row & 7)) << 4);
            cp_async16(st + off, kh_t + row * 128 + c * 8);
            cp_async16(st + AT_KL + off, kl_t + row * 128 + c * 8);
        }
        const __half* vh_t = vh_p + kt * 64;
        const __half* vl_t = vl_p + kt * 64;
        for (int i = tid; i < 832; i += 256) {
            const int row = i >> 3, c = i & 7;
            const uint32_t off = row * 128 + ((c ^ (row & 7)) << 4);
            cp_async16(st + AT_V + off, vh_t + (size_t)row * NN + c * 8);
            cp_async16(st + AT_VL + off, vl_t + (size_t)row * NN + c * 8);
        }
        cp_commit();
    };

    const int nkt = NN / 64;
    load_stage(0, 0);
    load_stage(1, 1);

    for (int kt = 0; kt < nkt; ++kt) {
        if (kt + 2 <= nkt) {
            asm volatile("cp.async.wait_group 1;");
        } else {
            asm volatile("cp.async.wait_group 0;");
        }
        __syncthreads();
        if (kt + 2 < nkt) load_stage((kt + 2) % 3, kt + 2);

        const uint32_t st = sb + (uint32_t)(kt % 3) * AT_STAGE;

        // ---- S = Q K^T (scale pre-folded into Q), bf16 3-term ----
        float sc[8][4];
#pragma unroll
        for (int nt = 0; nt < 8; ++nt) { sc[nt][0] = sc[nt][1] = sc[nt][2] = sc[nt][3] = 0.0f; }

#pragma unroll
        for (int jp = 0; jp < 3; ++jp) {
#pragma unroll
            for (int nt = 0; nt < 8; ++nt) {
                const int brow = nt * 8 + (lane & 7);
                const int bchn = 4 * jp + (lane >> 3);
                const uint32_t addr = st + brow * 256 + ((bchn ^ (brow & 7)) << 4);
                uint32_t bh4[4], bl4[4];
                ldmatrix_x4(bh4, addr);
                ldmatrix_x4(bl4, addr + AT_KL);
                mma_bf16(sc[nt], qah[2 * jp], &bh4[0]);
                mma_bf16(sc[nt], qah[2 * jp], &bl4[0]);
                mma_bf16(sc[nt], qal[2 * jp], &bh4[0]);
                mma_bf16(sc[nt], qah[2 * jp + 1], &bh4[2]);
                mma_bf16(sc[nt], qah[2 * jp + 1], &bl4[2]);
                mma_bf16(sc[nt], qal[2 * jp + 1], &bh4[2]);
            }
        }
#pragma unroll
        for (int nt = 0; nt < 8; ++nt) {   // kstep j=6 (dims 96..111)
            const int brow = nt * 8 + (lane & 7);
            const int bchn = 12 + ((lane >> 3) & 1);
            const uint32_t addr = st + brow * 256 + ((bchn ^ (brow & 7)) << 4);
            uint32_t bh2[2], bl2[2];
            ldmatrix_x2(bh2, addr);
            ldmatrix_x2(bl2, addr + AT_KL);
            mma_bf16(sc[nt], qah[6], bh2);
            mma_bf16(sc[nt], qah[6], bl2);
            mma_bf16(sc[nt], qal[6], bh2);
        }

        // ---- online softmax ----
        float mx0 = m0, mx1 = m1;
#pragma unroll
        for (int nt = 0; nt < 8; ++nt) {
            mx0 = fmaxf(mx0, fmaxf(sc[nt][0], sc[nt][1]));
            mx1 = fmaxf(mx1, fmaxf(sc[nt][2], sc[nt][3]));
        }
        mx0 = fmaxf(mx0, __shfl_xor_sync(0xffffffffu, mx0, 1));
        mx0 = fmaxf(mx0, __shfl_xor_sync(0xffffffffu, mx0, 2));
        mx1 = fmaxf(mx1, __shfl_xor_sync(0xffffffffu, mx1, 1));
        mx1 = fmaxf(mx1, __shfl_xor_sync(0xffffffffu, mx1, 2));
        const float a0 = __expf(m0 - mx0), a1 = __expf(m1 - mx1);
        m0 = mx0; m1 = mx1;
        l0 *= a0; l1 *= a1;
#pragma unroll
        for (int i = 0; i < 13; ++i) {
            oc[i][0] *= a0; oc[i][1] *= a0; oc[i][2] *= a1; oc[i][3] *= a1;
        }

        uint32_t pah[4][4];
#pragma unroll
        for (int jp = 0; jp < 4; ++jp) {
            const float p00 = __expf(sc[2 * jp][0] - mx0);
            const float p01 = __expf(sc[2 * jp][1] - mx0);
            const float p02 = __expf(sc[2 * jp][2] - mx1);
            const float p03 = __expf(sc[2 * jp][3] - mx1);
            const float p10 = __expf(sc[2 * jp + 1][0] - mx0);
            const float p11 = __expf(sc[2 * jp + 1][1] - mx0);
            const float p12 = __expf(sc[2 * jp + 1][2] - mx1);
            const float p13 = __expf(sc[2 * jp + 1][3] - mx1);
            l0 += p00 + p01 + p10 + p11;
            l1 += p02 + p03 + p12 + p13;
            pah[jp][0] = pack_f16(p00, p01);
            pah[jp][1] = pack_f16(p02, p03);
            pah[jp][2] = pack_f16(p10, p11);
            pah[jp][3] = pack_f16(p12, p13);
        }

        // ---- O += P V (fp16: P*(Vh+Vl)) ----
#pragma unroll
        for (int jph = 0; jph < 2; ++jph) {
#pragma unroll
            for (int ntd = 0; ntd < 13; ++ntd) {
                const int vrow = ntd * 8 + (lane & 7);
                const int vchn = 4 * jph + (lane >> 3);
                const uint32_t addr = st + AT_V + vrow * 128 + ((vchn ^ (vrow & 7)) << 4);
                uint32_t vh4[4], vl4[4];
                ldmatrix_x4(vh4, addr);
                ldmatrix_x4(vl4, addr + (AT_VL - AT_V));
                mma_f16(oc[ntd], pah[2 * jph], &vh4[0]);
                mma_f16(oc[ntd], pah[2 * jph], &vl4[0]);
                mma_f16(oc[ntd], pah[2 * jph + 1], &vh4[2]);
                mma_f16(oc[ntd], pah[2 * jph + 1], &vl4[2]);
            }
        }
    }

    // ---- epilogue: normalize, split hi/lo, write proj-GEMM inputs ----
    l0 += __shfl_xor_sync(0xffffffffu, l0, 1);
    l0 += __shfl_xor_sync(0xffffffffu, l0, 2);
    l1 += __shfl_xor_sync(0xffffffffu, l1, 1);
    l1 += __shfl_xor_sync(0xffffffffu, l1, 2);
    const float inv0 = 1.0f / l0, inv1 = 1.0f / l1;
    const int row0 = qt * 128 + wid * 16 + (lane >> 2);
    const size_t tok0 = (size_t)b * NN + row0;
    const int colbase = h * DD + 2 * (lane & 3);
#pragma unroll
    for (int ntd = 0; ntd < 13; ++ntd) {
        const int col = colbase + ntd * 8;
        uint32_t hi, lo;
        pack_hilo(oc[ntd][0] * inv0, oc[ntd][1] * inv0, hi, lo);
        *reinterpret_cast<uint32_t*>(Oh + tok0 * CC + col) = hi;
        *reinterpret_cast<uint32_t*>(Ol + tok0 * CC + col) = lo;
        pack_hilo(oc[ntd][2] * inv1, oc[ntd][3] * inv1, hi, lo);
        *reinterpret_cast<uint32_t*>(Oh + (tok0 + 8) * CC + col) = hi;
        *reinterpret_cast<uint32_t*>(Ol + (tok0 + 8) * CC + col) = lo;
    }
}

// ---------------------------------------------------------------------------
// Launch
// ---------------------------------------------------------------------------
extern "C" void kernel_launch(void* const* d_in, const int* in_sizes, int n_in,
                              void* d_out, int out_size) {
    const float* x = nullptr;
    const int*   coords = nullptr;
    const float* qkv_w = nullptr;
    const float* qkv_b = nullptr;
    const float* proj_w = nullptr;
    const float* proj_b = nullptr;
    for (int i = 0; i < n_in; ++i) {
        switch (in_sizes[i]) {
            case TOKENS * CC:      x      = (const float*)d_in[i]; break;
            case TOKENS * 3:       coords = (const int*)d_in[i];   break;
            case CC * C3:          qkv_w  = (const float*)d_in[i]; break;
            case C3:               qkv_b  = (const float*)d_in[i]; break;
            case CC * CC:          proj_w = (const float*)d_in[i]; break;
            case CC:               proj_b = (const float*)d_in[i]; break;
            default: break;
        }
    }
    float* out = (float*)d_out;

    float* qkv;
    __nv_bfloat16 *xh, *xl, *ah, *al, *wqh, *wql, *wph, *wpl;
    __nv_bfloat16 *qh, *ql, *kh, *kl;
    __half *vth, *vtl;
    cudaGetSymbolAddress((void**)&qkv, g_qkv);
    cudaGetSymbolAddress((void**)&xh,  g_xh);
    cudaGetSymbolAddress((void**)&xl,  g_xl);
    cudaGetSymbolAddress((void**)&ah,  g_ah);
    cudaGetSymbolAddress((void**)&al,  g_al);
    cudaGetSymbolAddress((void**)&wqh, g_wqh);
    cudaGetSymbolAddress((void**)&wql, g_wql);
    cudaGetSymbolAddress((void**)&wph, g_wph);
    cudaGetSymbolAddress((void**)&wpl, g_wpl);
    cudaGetSymbolAddress((void**)&qh,  g_qh);
    cudaGetSymbolAddress((void**)&ql,  g_ql);
    cudaGetSymbolAddress((void**)&kh,  g_kh);
    cudaGetSymbolAddress((void**)&kl,  g_kl);
    cudaGetSymbolAddress((void**)&vth, g_vth);
    cudaGetSymbolAddress((void**)&vtl, g_vtl);

    const int gemm_smem = 4 * STAGE_BYTES;   // 131072
    cudaFuncSetAttribute(mma_gemm_kernel, cudaFuncAttributeMaxDynamicSharedMemorySize, gemm_smem);
    const int attn_smem = 3 * AT_STAGE;      // 178176
    cudaFuncSetAttribute(attn_mma_kernel, cudaFuncAttributeMaxDynamicSharedMemorySize, attn_smem);

    // 1) split x
    convert_split_kernel<<<4096, 256>>>(x, xh, xl, TOKENS * CC);

    // 2) transpose+split qkv_w
    {
        dim3 grid(C3 / 32, CC / 32);
        transpose_split_kernel<<<grid, dim3(32, 8)>>>(qkv_w, wqh, wql, CC, C3);
    }

    // 3) QKV GEMM
    {
        dim3 grid(C3 / 128, TOKENS / 128);
        mma_gemm_kernel<<<grid, 256, gemm_smem>>>(xh, xl, wqh, wql, qkv_b, qkv,
                                                  TOKENS, C3, CC);
    }

    // 4) RoPE + scale + split q/k; transpose+split v (fp16)
    qk_prep_kernel<<<TOKENS, 128>>>(coords, qkv, qh, ql, kh, kl);
    {
        dim3 grid(NN / 32, (DD + 31) / 32, BB * HH);
        vt_prep_kernel<<<grid, dim3(32, 8)>>>(qkv, vth, vtl);
    }

    // 5) Flash attention on tensor cores -> writes proj inputs (ah/al)
    {
        dim3 grid(NN / 128, HH, BB);
        attn_mma_kernel<<<grid, 256, attn_smem>>>(qh, ql, kh, kl, vth, vtl, ah, al);
    }

    // 6) transpose+split proj_w
    {
        dim3 grid(CC / 32, CC / 32);
        transpose_split_kernel<<<grid, dim3(32, 8)>>>(proj_w, wph, wpl, CC, CC);
    }

    // 7) Projection GEMM
    {
        dim3 grid(CC / 128, TOKENS / 128);
        mma_gemm_kernel<<<grid, 256, gemm_smem>>>(ah, al, wph, wpl, proj_b, out,
                                                  TOKENS, CC, CC);
    }
}

// round 8
// speedup vs baseline: 1.1061x; 1.1061x over previous
#include <cuda_runtime.h>
#include <cuda_bf16.h>
#include <cuda_fp16.h>
#include <math.h>
#include <stdint.h>

// Problem constants
#define BB 2
#define NN 2048
#define CC 1664
#define HH 16
#define DD 104
#define C3 (3 * CC)          // 4992
#define TOKENS (BB * NN)     // 4096

// ---------------------------------------------------------------------------
// Scratch (no allocations allowed)
// ---------------------------------------------------------------------------
__device__ __align__(256) float g_qkv[(size_t)TOKENS * C3];
__device__ __align__(256) __nv_bfloat16 g_xh[(size_t)TOKENS * CC];
__device__ __align__(256) __nv_bfloat16 g_xl[(size_t)TOKENS * CC];
__device__ __align__(256) __nv_bfloat16 g_ah[(size_t)TOKENS * CC];
__device__ __align__(256) __nv_bfloat16 g_al[(size_t)TOKENS * CC];
__device__ __align__(256) __nv_bfloat16 g_wqh[(size_t)C3 * CC];
__device__ __align__(256) __nv_bfloat16 g_wql[(size_t)C3 * CC];
__device__ __align__(256) __nv_bfloat16 g_wph[(size_t)CC * CC];
__device__ __align__(256) __nv_bfloat16 g_wpl[(size_t)CC * CC];
// attention operands: Q single fp16 (scaled), K fp16 hi/lo, rows of 104 halves;
// V transposed [d][n] single fp16
__device__ __align__(256) __half g_qh[(size_t)BB * HH * NN * DD];
__device__ __align__(256) __half g_kh[(size_t)BB * HH * NN * DD];
__device__ __align__(256) __half g_kl[(size_t)BB * HH * NN * DD];
__device__ __align__(256) __half g_vth[(size_t)BB * HH * DD * NN];

// ---------------------------------------------------------------------------
// Helpers
// ---------------------------------------------------------------------------
__device__ __forceinline__ uint32_t smem_u32(const void* p) {
    uint32_t a;
    asm("{ .reg .u64 t; cvta.to.shared.u64 t, %1; cvt.u32.u64 %0, t; }" : "=r"(a) : "l"(p));
    return a;
}
__device__ __forceinline__ void cp_async16(uint32_t dst, const void* src) {
    asm volatile("cp.async.cg.shared.global [%0], [%1], 16;" :: "r"(dst), "l"(src));
}
__device__ __forceinline__ void cp_commit() {
    asm volatile("cp.async.commit_group;");
}
__device__ __forceinline__ void ldmatrix_x4(uint32_t* r, uint32_t addr) {
    asm volatile("ldmatrix.sync.aligned.m8n8.x4.shared.b16 {%0,%1,%2,%3}, [%4];"
                 : "=r"(r[0]), "=r"(r[1]), "=r"(r[2]), "=r"(r[3]) : "r"(addr));
}
__device__ __forceinline__ void ldmatrix_x2(uint32_t* r, uint32_t addr) {
    asm volatile("ldmatrix.sync.aligned.m8n8.x2.shared.b16 {%0,%1}, [%2];"
                 : "=r"(r[0]), "=r"(r[1]) : "r"(addr));
}
__device__ __forceinline__ void ldmatrix_x1(uint32_t& r, uint32_t addr) {
    asm volatile("ldmatrix.sync.aligned.m8n8.x1.shared.b16 {%0}, [%1];"
                 : "=r"(r) : "r"(addr));
}
__device__ __forceinline__ void mma_bf16(float* c, const uint32_t* a, const uint32_t* b) {
    asm volatile("mma.sync.aligned.m16n8k16.row.col.f32.bf16.bf16.f32 "
                 "{%0,%1,%2,%3}, {%4,%5,%6,%7}, {%8,%9}, {%0,%1,%2,%3};"
                 : "+f"(c[0]), "+f"(c[1]), "+f"(c[2]), "+f"(c[3])
                 : "r"(a[0]), "r"(a[1]), "r"(a[2]), "r"(a[3]), "r"(b[0]), "r"(b[1]));
}
__device__ __forceinline__ void mma_f16(float* c, const uint32_t* a, const uint32_t* b) {
    asm volatile("mma.sync.aligned.m16n8k16.row.col.f32.f16.f16.f32 "
                 "{%0,%1,%2,%3}, {%4,%5,%6,%7}, {%8,%9}, {%0,%1,%2,%3};"
                 : "+f"(c[0]), "+f"(c[1]), "+f"(c[2]), "+f"(c[3])
                 : "r"(a[0]), "r"(a[1]), "r"(a[2]), "r"(a[3]), "r"(b[0]), "r"(b[1]));
}
__device__ __forceinline__ void mma_f16_k8(float* c, const uint32_t* a, uint32_t b) {
    asm volatile("mma.sync.aligned.m16n8k8.row.col.f32.f16.f16.f32 "
                 "{%0,%1,%2,%3}, {%4,%5}, {%6}, {%0,%1,%2,%3};"
                 : "+f"(c[0]), "+f"(c[1]), "+f"(c[2]), "+f"(c[3])
                 : "r"(a[0]), "r"(a[1]), "r"(b));
}
__device__ __forceinline__ void pack_hilo(float a, float b, uint32_t& hi, uint32_t& lo) {
    const __nv_bfloat16 ha = __float2bfloat16(a);
    const __nv_bfloat16 hb = __float2bfloat16(b);
    const __nv_bfloat16 la = __float2bfloat16(a - __bfloat162float(ha));
    const __nv_bfloat16 lb = __float2bfloat16(b - __bfloat162float(hb));
    hi = (uint32_t)*reinterpret_cast<const uint16_t*>(&ha) |
         ((uint32_t)*reinterpret_cast<const uint16_t*>(&hb) << 16);
    lo = (uint32_t)*reinterpret_cast<const uint16_t*>(&la) |
         ((uint32_t)*reinterpret_cast<const uint16_t*>(&lb) << 16);
}
__device__ __forceinline__ uint32_t pack_f16(float a, float b) {
    __half2 h = __floats2half2_rn(a, b);
    return *reinterpret_cast<uint32_t*>(&h);
}

// ---------------------------------------------------------------------------
// fp32 -> bf16 hi/lo split
// ---------------------------------------------------------------------------
__global__ void convert_split_kernel(const float* __restrict__ src,
                                     __nv_bfloat16* __restrict__ hi,
                                     __nv_bfloat16* __restrict__ lo, int n) {
    for (int i = blockIdx.x * blockDim.x + threadIdx.x; i < n; i += gridDim.x * blockDim.x) {
        const float v = src[i];
        const __nv_bfloat16 h = __float2bfloat16(v);
        hi[i] = h;
        lo[i] = __float2bfloat16(v - __bfloat162float(h));
    }
}

// ---------------------------------------------------------------------------
// W[Kr][Nc] row-major  ->  T[Nc][Kr] bf16 hi/lo
// ---------------------------------------------------------------------------
__global__ void transpose_split_kernel(const float* __restrict__ W,
                                       __nv_bfloat16* __restrict__ Th,
                                       __nv_bfloat16* __restrict__ Tl,
                                       int Kr, int Nc) {
    __shared__ float t[32][33];
    const int x = blockIdx.x * 32 + threadIdx.x;
    const int y0 = blockIdx.y * 32;
    for (int j = threadIdx.y; j < 32; j += 8)
        t[j][threadIdx.x] = W[(size_t)(y0 + j) * Nc + x];
    __syncthreads();
    const int ox = y0 + threadIdx.x;
    const int oy0 = blockIdx.x * 32;
    for (int j = threadIdx.y; j < 32; j += 8) {
        const float v = t[threadIdx.x][j];
        const __nv_bfloat16 h = __float2bfloat16(v);
        Th[(size_t)(oy0 + j) * Kr + ox] = h;
        Tl[(size_t)(oy0 + j) * Kr + ox] = __float2bfloat16(v - __bfloat162float(h));
    }
}

// ---------------------------------------------------------------------------
// mma.sync GEMM: 4-stage cp.async pipeline (unchanged from R7)
// ---------------------------------------------------------------------------
#define TILE_BYTES 8192
#define STAGE_BYTES 32768

__global__ __launch_bounds__(256, 1)
void mma_gemm_kernel(const __nv_bfloat16* __restrict__ Ah,
                     const __nv_bfloat16* __restrict__ Al,
                     const __nv_bfloat16* __restrict__ Bh,
                     const __nv_bfloat16* __restrict__ Bl,
                     const float* __restrict__ bias,
                     float* __restrict__ Cout,
                     int M, int N, int K) {
    extern __shared__ char smem[];
    const uint32_t sbase = smem_u32(smem);
    const int tid  = threadIdx.x;
    const int lane = tid & 31;
    const int wid  = tid >> 5;
    const int wm   = wid & 1;
    const int wn   = wid >> 1;
    const int crow = blockIdx.y * 128;
    const int ccol = blockIdx.x * 128;

    const __nv_bfloat16* gsrc[4];
    gsrc[0] = Ah + (size_t)crow * K;
    gsrc[1] = Al + (size_t)crow * K;
    gsrc[2] = Bh + (size_t)ccol * K;
    gsrc[3] = Bl + (size_t)ccol * K;

    const int lc  = tid & 3;
    const int lr0 = tid >> 2;
    const int lr1 = lr0 + 64;
    const uint32_t sw0 = (uint32_t)((lc ^ ((lr0 >> 1) & 3)) << 4);
    const uint32_t sw1 = (uint32_t)((lc ^ ((lr1 >> 1) & 3)) << 4);

    float acc[4][4][4];
#pragma unroll
    for (int mt = 0; mt < 4; ++mt)
#pragma unroll
        for (int nt = 0; nt < 4; ++nt)
#pragma unroll
            for (int j = 0; j < 4; ++j) acc[mt][nt][j] = 0.0f;

    const int nch = K / 32;

    auto load_stage = [&](int stage, int k0) {
        const uint32_t sb = sbase + (uint32_t)stage * STAGE_BYTES;
#pragma unroll
        for (int t = 0; t < 4; ++t) {
            const __nv_bfloat16* g = gsrc[t];
            cp_async16(sb + t * TILE_BYTES + lr0 * 64 + sw0,
                       g + (size_t)lr0 * K + k0 + lc * 8);
            cp_async16(sb + t * TILE_BYTES + lr1 * 64 + sw1,
                       g + (size_t)lr1 * K + k0 + lc * 8);
        }
        cp_commit();
    };

    load_stage(0, 0);
    load_stage(1, 32);
    load_stage(2, 64);

    const int a_lrow   = (lane & 7) + ((lane >> 3) & 1) * 8;
    const int a_lchunk = lane >> 4;
    const int b_lrow   = lane & 7;
    const int b_lchunk = (lane >> 3) & 1;

    for (int ch = 0; ch < nch; ++ch) {
        if (ch + 3 <= nch) {
            asm volatile("cp.async.wait_group 2;");
        } else if (ch + 2 <= nch) {
            asm volatile("cp.async.wait_group 1;");
        } else {
            asm volatile("cp.async.wait_group 0;");
        }
        __syncthreads();
        if (ch + 3 < nch) load_stage((ch + 3) & 3, (ch + 3) * 32);

        const uint32_t sb = sbase + (uint32_t)(ch & 3) * STAGE_BYTES;

#pragma unroll
        for (int ks = 0; ks < 2; ++ks) {
            uint32_t afh[4][4], afl[4][4], bfh[4][2], bfl[4][2];
#pragma unroll
            for (int mt = 0; mt < 4; ++mt) {
                const int row = wm * 64 + mt * 16 + a_lrow;
                const int chn = 2 * ks + a_lchunk;
                const uint32_t addr = sb + (uint32_t)(row * 64)
                                    + (uint32_t)((chn ^ ((row >> 1) & 3)) << 4);
                ldmatrix_x4(afh[mt], addr);
                ldmatrix_x4(afl[mt], addr + TILE_BYTES);
            }
#pragma unroll
            for (int nt = 0; nt < 4; ++nt) {
                const int row = wn * 32 + nt * 8 + b_lrow;
                const int chn = 2 * ks + b_lchunk;
                const uint32_t addr = sb + 2 * TILE_BYTES + (uint32_t)(row * 64)
                                    + (uint32_t)((chn ^ ((row >> 1) & 3)) << 4);
                ldmatrix_x2(bfh[nt], addr);
                ldmatrix_x2(bfl[nt], addr + TILE_BYTES);
            }
#pragma unroll
            for (int mt = 0; mt < 4; ++mt)
#pragma unroll
                for (int nt = 0; nt < 4; ++nt) {
                    mma_bf16(acc[mt][nt], afh[mt], bfh[nt]);
                    mma_bf16(acc[mt][nt], afh[mt], bfl[nt]);
                    mma_bf16(acc[mt][nt], afl[mt], bfh[nt]);
                }
        }
    }

    const int erow = lane >> 2;
    const int ecol = (lane & 3) * 2;
#pragma unroll
    for (int mt = 0; mt < 4; ++mt) {
#pragma unroll
        for (int nt = 0; nt < 4; ++nt) {
            const int col = ccol + wn * 32 + nt * 8 + ecol;
            const float b0 = bias[col], b1 = bias[col + 1];
            const int r0 = crow + wm * 64 + mt * 16 + erow;
            float2* p0 = reinterpret_cast<float2*>(Cout + (size_t)r0 * N + col);
            *p0 = make_float2(acc[mt][nt][0] + b0, acc[mt][nt][1] + b1);
            float2* p1 = reinterpret_cast<float2*>(Cout + (size_t)(r0 + 8) * N + col);
            *p1 = make_float2(acc[mt][nt][2] + b0, acc[mt][nt][3] + b1);
        }
    }
}

// ---------------------------------------------------------------------------
// qk_prep: fused RoPE + scale (q) -> Q single fp16 [bh][n][104];
//          K fp16 hi/lo [bh][n][104]
// ---------------------------------------------------------------------------
__global__ void qk_prep_kernel(const int* __restrict__ coords,
                               const float* __restrict__ qkv,
                               __half* __restrict__ Qh,
                               __half* __restrict__ Kh, __half* __restrict__ Kl) {
    const int token = blockIdx.x;
    const int tid = threadIdx.x;   // 128
    __shared__ float cs[DD], sn[DD];

    const int c0 = coords[token * 3 + 0];
    const int c1 = coords[token * 3 + 1];
    const int c2 = coords[token * 3 + 2];
    if (tid < DD) {
        const int j = tid;
        int jj, dd, coord;
        if (j < 34)      { const int u = j;      jj = (u < 17) ? u : u - 17; dd = 34; coord = c0; }
        else if (j < 68) { const int u = j - 34; jj = (u < 17) ? u : u - 17; dd = 34; coord = c1; }
        else             { const int u = j - 68; jj = (u < 18) ? u : u - 18; dd = 36; coord = c2; }
        const float inv = powf(10000.0f, -(2.0f * (float)jj) / (float)dd);
        const float ang = (float)coord * inv;
        cs[j] = cosf(ang);
        sn[j] = sinf(ang);
    }
    __syncthreads();

    if (tid >= DD) return;
    const int b = token >> 11, n = token & (NN - 1);
    const float scale = rsqrtf((float)DD);
    const float* base = qkv + (size_t)token * C3;
    const int j = tid;

    for (int h = 0; h < HH; ++h) {
        const size_t o = ((size_t)(b * HH + h) * NN + n) * DD + j;
        const float qa = base[h * DD + j];
        const float qrot = (j < 52) ? -base[h * DD + j + 52] : base[h * DD + j - 52];
        const float qv = (qa * cs[j] + qrot * sn[j]) * scale;
        Qh[o] = __float2half_rn(qv);

        const float ka = base[CC + h * DD + j];
        const float krot = (j < 52) ? -base[CC + h * DD + j + 52] : base[CC + h * DD + j - 52];
        const float kv = ka * cs[j] + krot * sn[j];
        const __half khv = __float2half_rn(kv);
        Kh[o] = khv;
        Kl[o] = __float2half_rn(kv - __half2float(khv));
    }
}

// ---------------------------------------------------------------------------
// vt_prep: V [token][h][d] fp32 -> Vt [bh][d][n] fp16 single (transpose)
// ---------------------------------------------------------------------------
__global__ void vt_prep_kernel(const float* __restrict__ qkv,
                               __half* __restrict__ Vth) {
    __shared__ float t[32][33];
    const int bh = blockIdx.z;
    const int b = bh >> 4, h = bh & 15;
    const int n0 = blockIdx.x * 32;
    const int d0 = blockIdx.y * 32;
    const int tx = threadIdx.x, ty = threadIdx.y;
#pragma unroll
    for (int j = 0; j < 4; ++j) {
        const int d = d0 + tx, n = n0 + ty + 8 * j;
        if (d < DD)
            t[ty + 8 * j][tx] = qkv[(size_t)(b * NN + n) * C3 + 2 * CC + h * DD + d];
    }
    __syncthreads();
#pragma unroll
    for (int j = 0; j < 4; ++j) {
        const int d = d0 + ty + 8 * j, n = n0 + tx;
        if (d < DD)
            Vth[((size_t)bh * DD + d) * NN + n] = __float2half_rn(t[tx][ty + 8 * j]);
    }
}

// ---------------------------------------------------------------------------
// Flash attention, fp16: S = Q*(Kh+Kl) (Q single fp16, scale folded),
// O += P*Vh (P fp16, V single fp16). 6 k16-steps + 1 k8-step (104 dims exact).
// 3-stage cp.async pipeline. Q/K smem rows 256B (13 data chunks), V rows 128B.
// ---------------------------------------------------------------------------
#define AT_KL 16384
#define AT_V  32768
#define AT_STAGE 46080

__global__ __launch_bounds__(256, 1)
void attn_mma_kernel(const __half* __restrict__ Qh,
                     const __half* __restrict__ Kh, const __half* __restrict__ Kl,
                     const __half* __restrict__ Vth,
                     __nv_bfloat16* __restrict__ Oh, __nv_bfloat16* __restrict__ Ol) {
    extern __shared__ char smem[];
    const uint32_t sb = smem_u32(smem);
    const int tid = threadIdx.x, lane = tid & 31, wid = tid >> 5;
    const int qt = blockIdx.x, h = blockIdx.y, b = blockIdx.z;
    const int bh = b * HH + h;

    const __half* qh_p = Qh + ((size_t)bh * NN + qt * 128) * DD;
    const __half* kh_p = Kh + (size_t)bh * NN * DD;
    const __half* kl_p = Kl + (size_t)bh * NN * DD;
    const __half* vh_p = Vth + (size_t)bh * DD * NN;

    // ---- stage Q (13 chunks of 8 halves per 256B smem row), extract a-frags ----
    for (int i = tid; i < 128 * 13; i += 256) {
        const int row = i / 13, c = i % 13;
        const uint32_t off = row * 256 + ((c ^ (row & 7)) << 4);
        cp_async16(sb + off, qh_p + (size_t)row * DD + c * 8);
    }
    cp_commit();
    asm volatile("cp.async.wait_group 0;");
    __syncthreads();

    uint32_t qah[6][4], qa8[2];
    {
        const int arow = wid * 16 + (lane & 7) + ((lane >> 3) & 1) * 8;
#pragma unroll
        for (int j = 0; j < 6; ++j) {
            const int chn = 2 * j + (lane >> 4);
            ldmatrix_x4(qah[j], sb + arow * 256 + ((chn ^ (arow & 7)) << 4));
        }
        ldmatrix_x2(qa8, sb + arow * 256 + ((12 ^ (arow & 7)) << 4));
    }
    __syncthreads();

    float oc[13][4];
#pragma unroll
    for (int i = 0; i < 13; ++i) { oc[i][0] = oc[i][1] = oc[i][2] = oc[i][3] = 0.0f; }
    float m0 = -1e30f, m1 = -1e30f, l0 = 0.0f, l1 = 0.0f;

    auto load_stage = [&](int s, int kt) {
        const uint32_t st = sb + (uint32_t)s * AT_STAGE;
        const __half* kh_t = kh_p + (size_t)kt * 64 * DD;
        const __half* kl_t = kl_p + (size_t)kt * 64 * DD;
        for (int i = tid; i < 64 * 13; i += 256) {
            const int row = i / 13, c = i % 13;
            const uint32_t off = row * 256 + ((c ^ (row & 7)) << 4);
            cp_async16(st + off, kh_t + (size_t)row * DD + c * 8);
            cp_async16(st + AT_KL + off, kl_t + (size_t)row * DD + c * 8);
        }
        const __half* vh_t = vh_p + kt * 64;
        for (int i = tid; i < 832; i += 256) {
            const int row = i >> 3, c = i & 7;
            const uint32_t off = row * 128 + ((c ^ (row & 7)) << 4);
            cp_async16(st + AT_V + off, vh_t + (size_t)row * NN + c * 8);
        }
        cp_commit();
    };

    const int nkt = NN / 64;
    load_stage(0, 0);
    load_stage(1, 1);

    for (int kt = 0; kt < nkt; ++kt) {
        if (kt + 2 <= nkt) {
            asm volatile("cp.async.wait_group 1;");
        } else {
            asm volatile("cp.async.wait_group 0;");
        }
        __syncthreads();
        if (kt + 2 < nkt) load_stage((kt + 2) % 3, kt + 2);

        const uint32_t st = sb + (uint32_t)(kt % 3) * AT_STAGE;

        // ---- S = Q (Kh + Kl), fp16 ----
        float sc[8][4];
#pragma unroll
        for (int nt = 0; nt < 8; ++nt) { sc[nt][0] = sc[nt][1] = sc[nt][2] = sc[nt][3] = 0.0f; }

#pragma unroll
        for (int jp = 0; jp < 3; ++jp) {
#pragma unroll
            for (int nt = 0; nt < 8; ++nt) {
                const int brow = nt * 8 + (lane & 7);
                const int bchn = 4 * jp + (lane >> 3);
                const uint32_t addr = st + brow * 256 + ((bchn ^ (brow & 7)) << 4);
                uint32_t bh4[4], bl4[4];
                ldmatrix_x4(bh4, addr);
                ldmatrix_x4(bl4, addr + AT_KL);
                mma_f16(sc[nt], qah[2 * jp], &bh4[0]);
                mma_f16(sc[nt], qah[2 * jp], &bl4[0]);
                mma_f16(sc[nt], qah[2 * jp + 1], &bh4[2]);
                mma_f16(sc[nt], qah[2 * jp + 1], &bl4[2]);
            }
        }
#pragma unroll
        for (int nt = 0; nt < 8; ++nt) {   // k8 step: dims 96..103 (chunk 12)
            const int brow = nt * 8 + (lane & 7);
            const uint32_t addr = st + brow * 256 + ((12 ^ (brow & 7)) << 4);
            uint32_t bh1, bl1;
            ldmatrix_x1(bh1, addr);
            ldmatrix_x1(bl1, addr + AT_KL);
            mma_f16_k8(sc[nt], qa8, bh1);
            mma_f16_k8(sc[nt], qa8, bl1);
        }

        // ---- online softmax ----
        float mx0 = m0, mx1 = m1;
#pragma unroll
        for (int nt = 0; nt < 8; ++nt) {
            mx0 = fmaxf(mx0, fmaxf(sc[nt][0], sc[nt][1]));
            mx1 = fmaxf(mx1, fmaxf(sc[nt][2], sc[nt][3]));
        }
        mx0 = fmaxf(mx0, __shfl_xor_sync(0xffffffffu, mx0, 1));
        mx0 = fmaxf(mx0, __shfl_xor_sync(0xffffffffu, mx0, 2));
        mx1 = fmaxf(mx1, __shfl_xor_sync(0xffffffffu, mx1, 1));
        mx1 = fmaxf(mx1, __shfl_xor_sync(0xffffffffu, mx1, 2));
        const float a0 = __expf(m0 - mx0), a1 = __expf(m1 - mx1);
        m0 = mx0; m1 = mx1;
        l0 *= a0; l1 *= a1;
#pragma unroll
        for (int i = 0; i < 13; ++i) {
            oc[i][0] *= a0; oc[i][1] *= a0; oc[i][2] *= a1; oc[i][3] *= a1;
        }

        uint32_t pah[4][4];
#pragma unroll
        for (int jp = 0; jp < 4; ++jp) {
            const float p00 = __expf(sc[2 * jp][0] - mx0);
            const float p01 = __expf(sc[2 * jp][1] - mx0);
            const float p02 = __expf(sc[2 * jp][2] - mx1);
            const float p03 = __expf(sc[2 * jp][3] - mx1);
            const float p10 = __expf(sc[2 * jp + 1][0] - mx0);
            const float p11 = __expf(sc[2 * jp + 1][1] - mx0);
            const float p12 = __expf(sc[2 * jp + 1][2] - mx1);
            const float p13 = __expf(sc[2 * jp + 1][3] - mx1);
            l0 += p00 + p01 + p10 + p11;
            l1 += p02 + p03 + p12 + p13;
            pah[jp][0] = pack_f16(p00, p01);
            pah[jp][1] = pack_f16(p02, p03);
            pah[jp][2] = pack_f16(p10, p11);
            pah[jp][3] = pack_f16(p12, p13);
        }

        // ---- O += P Vh (fp16 single-term) ----
#pragma unroll
        for (int jph = 0; jph < 2; ++jph) {
#pragma unroll
            for (int ntd = 0; ntd < 13; ++ntd) {
                const int vrow = ntd * 8 + (lane & 7);
                const int vchn = 4 * jph + (lane >> 3);
                const uint32_t addr = st + AT_V + vrow * 128 + ((vchn ^ (vrow & 7)) << 4);
                uint32_t vh4[4];
                ldmatrix_x4(vh4, addr);
                mma_f16(oc[ntd], pah[2 * jph], &vh4[0]);
                mma_f16(oc[ntd], pah[2 * jph + 1], &vh4[2]);
            }
        }
    }

    // ---- epilogue: normalize, split hi/lo, write proj-GEMM inputs ----
    l0 += __shfl_xor_sync(0xffffffffu, l0, 1);
    l0 += __shfl_xor_sync(0xffffffffu, l0, 2);
    l1 += __shfl_xor_sync(0xffffffffu, l1, 1);
    l1 += __shfl_xor_sync(0xffffffffu, l1, 2);
    const float inv0 = 1.0f / l0, inv1 = 1.0f / l1;
    const int row0 = qt * 128 + wid * 16 + (lane >> 2);
    const size_t tok0 = (size_t)b * NN + row0;
    const int colbase = h * DD + 2 * (lane & 3);
#pragma unroll
    for (int ntd = 0; ntd < 13; ++ntd) {
        const int col = colbase + ntd * 8;
        uint32_t hi, lo;
        pack_hilo(oc[ntd][0] * inv0, oc[ntd][1] * inv0, hi, lo);
        *reinterpret_cast<uint32_t*>(Oh + tok0 * CC + col) = hi;
        *reinterpret_cast<uint32_t*>(Ol + tok0 * CC + col) = lo;
        pack_hilo(oc[ntd][2] * inv1, oc[ntd][3] * inv1, hi, lo);
        *reinterpret_cast<uint32_t*>(Oh + (tok0 + 8) * CC + col) = hi;
        *reinterpret_cast<uint32_t*>(Ol + (tok0 + 8) * CC + col) = lo;
    }
}

// ---------------------------------------------------------------------------
// Launch
// ---------------------------------------------------------------------------
extern "C" void kernel_launch(void* const* d_in, const int* in_sizes, int n_in,
                              void* d_out, int out_size) {
    const float* x = nullptr;
    const int*   coords = nullptr;
    const float* qkv_w = nullptr;
    const float* qkv_b = nullptr;
    const float* proj_w = nullptr;
    const float* proj_b = nullptr;
    for (int i = 0; i < n_in; ++i) {
        switch (in_sizes[i]) {
            case TOKENS * CC:      x      = (const float*)d_in[i]; break;
            case TOKENS * 3:       coords = (const int*)d_in[i];   break;
            case CC * C3:          qkv_w  = (const float*)d_in[i]; break;
            case C3:               qkv_b  = (const float*)d_in[i]; break;
            case CC * CC:          proj_w = (const float*)d_in[i]; break;
            case CC:               proj_b = (const float*)d_in[i]; break;
            default: break;
        }
    }
    float* out = (float*)d_out;

    float* qkv;
    __nv_bfloat16 *xh, *xl, *ah, *al, *wqh, *wql, *wph, *wpl;
    __half *qh, *kh, *kl, *vth;
    cudaGetSymbolAddress((void**)&qkv, g_qkv);
    cudaGetSymbolAddress((void**)&xh,  g_xh);
    cudaGetSymbolAddress((void**)&xl,  g_xl);
    cudaGetSymbolAddress((void**)&ah,  g_ah);
    cudaGetSymbolAddress((void**)&al,  g_al);
    cudaGetSymbolAddress((void**)&wqh, g_wqh);
    cudaGetSymbolAddress((void**)&wql, g_wql);
    cudaGetSymbolAddress((void**)&wph, g_wph);
    cudaGetSymbolAddress((void**)&wpl, g_wpl);
    cudaGetSymbolAddress((void**)&qh,  g_qh);
    cudaGetSymbolAddress((void**)&kh,  g_kh);
    cudaGetSymbolAddress((void**)&kl,  g_kl);
    cudaGetSymbolAddress((void**)&vth, g_vth);

    const int gemm_smem = 4 * STAGE_BYTES;   // 131072
    cudaFuncSetAttribute(mma_gemm_kernel, cudaFuncAttributeMaxDynamicSharedMemorySize, gemm_smem);
    const int attn_smem = 3 * AT_STAGE;      // 138240
    cudaFuncSetAttribute(attn_mma_kernel, cudaFuncAttributeMaxDynamicSharedMemorySize, attn_smem);

    // 1) split x
    convert_split_kernel<<<4096, 256>>>(x, xh, xl, TOKENS * CC);

    // 2) transpose+split qkv_w
    {
        dim3 grid(C3 / 32, CC / 32);
        transpose_split_kernel<<<grid, dim3(32, 8)>>>(qkv_w, wqh, wql, CC, C3);
    }

    // 3) QKV GEMM
    {
        dim3 grid(C3 / 128, TOKENS / 128);
        mma_gemm_kernel<<<grid, 256, gemm_smem>>>(xh, xl, wqh, wql, qkv_b, qkv,
                                                  TOKENS, C3, CC);
    }

    // 4) RoPE + scale -> Q fp16, K fp16 hi/lo; transpose V -> fp16
    qk_prep_kernel<<<TOKENS, 128>>>(coords, qkv, qh, kh, kl);
    {
        dim3 grid(NN / 32, (DD + 31) / 32, BB * HH);
        vt_prep_kernel<<<grid, dim3(32, 8)>>>(qkv, vth);
    }

    // 5) Flash attention on tensor cores -> writes proj inputs (ah/al)
    {
        dim3 grid(NN / 128, HH, BB);
        attn_mma_kernel<<<grid, 256, attn_smem>>>(qh, kh, kl, vth, ah, al);
    }

    // 6) transpose+split proj_w
    {
        dim3 grid(CC / 32, CC / 32);
        transpose_split_kernel<<<grid, dim3(32, 8)>>>(proj_w, wph, wpl, CC, CC);
    }

    // 7) Projection GEMM
    {
        dim3 grid(CC / 128, TOKENS / 128);
        mma_gemm_kernel<<<grid, 256, gemm_smem>>>(ah, al, wph, wpl, proj_b, out,
                                                  TOKENS, CC, CC);
    }
}

// round 9
// speedup vs baseline: 1.3693x; 1.2380x over previous
#include <cuda_runtime.h>
#include <cuda_bf16.h>
#include <cuda_fp16.h>
#include <math.h>
#include <stdint.h>

// Problem constants
#define BB 2
#define NN 2048
#define CC 1664
#define HH 16
#define DD 104
#define C3 (3 * CC)          // 4992
#define TOKENS (BB * NN)     // 4096

// ---------------------------------------------------------------------------
// Scratch (no allocations allowed)
// ---------------------------------------------------------------------------
__device__ __align__(256) float g_qkv[(size_t)TOKENS * C3];
// GEMM operands, fp16: activations hi/lo, weights single
__device__ __align__(256) __half g_xh[(size_t)TOKENS * CC];
__device__ __align__(256) __half g_xl[(size_t)TOKENS * CC];
__device__ __align__(256) __half g_ah[(size_t)TOKENS * CC];
__device__ __align__(256) __half g_al[(size_t)TOKENS * CC];
__device__ __align__(256) __half g_wq[(size_t)C3 * CC];      // qkv_w^T [4992][1664]
__device__ __align__(256) __half g_wp[(size_t)CC * CC];      // proj_w^T [1664][1664]
// attention operands: Q single fp16 (scaled), K fp16 hi/lo, rows of 104 halves;
// V transposed [d][n] single fp16
__device__ __align__(256) __half g_qh[(size_t)BB * HH * NN * DD];
__device__ __align__(256) __half g_kh[(size_t)BB * HH * NN * DD];
__device__ __align__(256) __half g_kl[(size_t)BB * HH * NN * DD];
__device__ __align__(256) __half g_vth[(size_t)BB * HH * DD * NN];

// ---------------------------------------------------------------------------
// Helpers
// ---------------------------------------------------------------------------
__device__ __forceinline__ uint32_t smem_u32(const void* p) {
    uint32_t a;
    asm("{ .reg .u64 t; cvta.to.shared.u64 t, %1; cvt.u32.u64 %0, t; }" : "=r"(a) : "l"(p));
    return a;
}
__device__ __forceinline__ void cp_async16(uint32_t dst, const void* src) {
    asm volatile("cp.async.cg.shared.global [%0], [%1], 16;" :: "r"(dst), "l"(src));
}
__device__ __forceinline__ void cp_commit() {
    asm volatile("cp.async.commit_group;");
}
__device__ __forceinline__ void ldmatrix_x4(uint32_t* r, uint32_t addr) {
    asm volatile("ldmatrix.sync.aligned.m8n8.x4.shared.b16 {%0,%1,%2,%3}, [%4];"
                 : "=r"(r[0]), "=r"(r[1]), "=r"(r[2]), "=r"(r[3]) : "r"(addr));
}
__device__ __forceinline__ void ldmatrix_x2(uint32_t* r, uint32_t addr) {
    asm volatile("ldmatrix.sync.aligned.m8n8.x2.shared.b16 {%0,%1}, [%2];"
                 : "=r"(r[0]), "=r"(r[1]) : "r"(addr));
}
__device__ __forceinline__ void ldmatrix_x1(uint32_t& r, uint32_t addr) {
    asm volatile("ldmatrix.sync.aligned.m8n8.x1.shared.b16 {%0}, [%1];"
                 : "=r"(r) : "r"(addr));
}
__device__ __forceinline__ void mma_f16(float* c, const uint32_t* a, const uint32_t* b) {
    asm volatile("mma.sync.aligned.m16n8k16.row.col.f32.f16.f16.f32 "
                 "{%0,%1,%2,%3}, {%4,%5,%6,%7}, {%8,%9}, {%0,%1,%2,%3};"
                 : "+f"(c[0]), "+f"(c[1]), "+f"(c[2]), "+f"(c[3])
                 : "r"(a[0]), "r"(a[1]), "r"(a[2]), "r"(a[3]), "r"(b[0]), "r"(b[1]));
}
__device__ __forceinline__ void mma_f16_k8(float* c, const uint32_t* a, uint32_t b) {
    asm volatile("mma.sync.aligned.m16n8k8.row.col.f32.f16.f16.f32 "
                 "{%0,%1,%2,%3}, {%4,%5}, {%6}, {%0,%1,%2,%3};"
                 : "+f"(c[0]), "+f"(c[1]), "+f"(c[2]), "+f"(c[3])
                 : "r"(a[0]), "r"(a[1]), "r"(b));
}
__device__ __forceinline__ uint32_t pack_f16(float a, float b) {
    __half2 h = __floats2half2_rn(a, b);
    return *reinterpret_cast<uint32_t*>(&h);
}
__device__ __forceinline__ void pack_hilo_f16(float a, float b, uint32_t& hi, uint32_t& lo) {
    const __half ha = __float2half_rn(a);
    const __half hb = __float2half_rn(b);
    const __half la = __float2half_rn(a - __half2float(ha));
    const __half lb = __float2half_rn(b - __half2float(hb));
    hi = (uint32_t)*reinterpret_cast<const uint16_t*>(&ha) |
         ((uint32_t)*reinterpret_cast<const uint16_t*>(&hb) << 16);
    lo = (uint32_t)*reinterpret_cast<const uint16_t*>(&la) |
         ((uint32_t)*reinterpret_cast<const uint16_t*>(&lb) << 16);
}

// ---------------------------------------------------------------------------
// fp32 -> fp16 hi/lo split
// ---------------------------------------------------------------------------
__global__ void convert_split_f16_kernel(const float* __restrict__ src,
                                         __half* __restrict__ hi,
                                         __half* __restrict__ lo, int n) {
    for (int i = blockIdx.x * blockDim.x + threadIdx.x; i < n; i += gridDim.x * blockDim.x) {
        const float v = src[i];
        const __half h = __float2half_rn(v);
        hi[i] = h;
        lo[i] = __float2half_rn(v - __half2float(h));
    }
}

// ---------------------------------------------------------------------------
// W[Kr][Nc] row-major  ->  T[Nc][Kr] single fp16
// ---------------------------------------------------------------------------
__global__ void transpose_f16_kernel(const float* __restrict__ W,
                                     __half* __restrict__ T,
                                     int Kr, int Nc) {
    __shared__ float t[32][33];
    const int x = blockIdx.x * 32 + threadIdx.x;
    const int y0 = blockIdx.y * 32;
    for (int j = threadIdx.y; j < 32; j += 8)
        t[j][threadIdx.x] = W[(size_t)(y0 + j) * Nc + x];
    __syncthreads();
    const int ox = y0 + threadIdx.x;
    const int oy0 = blockIdx.x * 32;
    for (int j = threadIdx.y; j < 32; j += 8)
        T[(size_t)(oy0 + j) * Kr + ox] = __float2half_rn(t[threadIdx.x][j]);
}

// ---------------------------------------------------------------------------
// mma.sync GEMM, fp16 2-term: C = (Ah+Al)[M,K] @ B[N,K]^T + bias[N].
// 4-stage cp.async pipeline, 3 tiles per stage (Ah, Al, B).
// ---------------------------------------------------------------------------
#define TILE_BYTES 8192
#define STAGE_BYTES 24576

__global__ __launch_bounds__(256, 1)
void mma_gemm_kernel(const __half* __restrict__ Ah,
                     const __half* __restrict__ Al,
                     const __half* __restrict__ B,
                     const float* __restrict__ bias,
                     float* __restrict__ Cout,
                     int M, int N, int K) {
    extern __shared__ char smem[];
    const uint32_t sbase = smem_u32(smem);
    const int tid  = threadIdx.x;
    const int lane = tid & 31;
    const int wid  = tid >> 5;
    const int wm   = wid & 1;
    const int wn   = wid >> 1;
    const int crow = blockIdx.y * 128;
    const int ccol = blockIdx.x * 128;

    const __half* gsrc[3];
    gsrc[0] = Ah + (size_t)crow * K;
    gsrc[1] = Al + (size_t)crow * K;
    gsrc[2] = B  + (size_t)ccol * K;

    const int lc  = tid & 3;
    const int lr0 = tid >> 2;
    const int lr1 = lr0 + 64;
    const uint32_t sw0 = (uint32_t)((lc ^ ((lr0 >> 1) & 3)) << 4);
    const uint32_t sw1 = (uint32_t)((lc ^ ((lr1 >> 1) & 3)) << 4);

    float acc[4][4][4];
#pragma unroll
    for (int mt = 0; mt < 4; ++mt)
#pragma unroll
        for (int nt = 0; nt < 4; ++nt)
#pragma unroll
            for (int j = 0; j < 4; ++j) acc[mt][nt][j] = 0.0f;

    const int nch = K / 32;

    auto load_stage = [&](int stage, int k0) {
        const uint32_t sb = sbase + (uint32_t)stage * STAGE_BYTES;
#pragma unroll
        for (int t = 0; t < 3; ++t) {
            const __half* g = gsrc[t];
            cp_async16(sb + t * TILE_BYTES + lr0 * 64 + sw0,
                       g + (size_t)lr0 * K + k0 + lc * 8);
            cp_async16(sb + t * TILE_BYTES + lr1 * 64 + sw1,
                       g + (size_t)lr1 * K + k0 + lc * 8);
        }
        cp_commit();
    };

    load_stage(0, 0);
    load_stage(1, 32);
    load_stage(2, 64);

    const int a_lrow   = (lane & 7) + ((lane >> 3) & 1) * 8;
    const int a_lchunk = lane >> 4;
    const int b_lrow   = lane & 7;
    const int b_lchunk = (lane >> 3) & 1;

    for (int ch = 0; ch < nch; ++ch) {
        if (ch + 3 <= nch) {
            asm volatile("cp.async.wait_group 2;");
        } else if (ch + 2 <= nch) {
            asm volatile("cp.async.wait_group 1;");
        } else {
            asm volatile("cp.async.wait_group 0;");
        }
        __syncthreads();
        if (ch + 3 < nch) load_stage((ch + 3) & 3, (ch + 3) * 32);

        const uint32_t sb = sbase + (uint32_t)(ch & 3) * STAGE_BYTES;

#pragma unroll
        for (int ks = 0; ks < 2; ++ks) {
            uint32_t afh[4][4], afl[4][4], bf[4][2];
#pragma unroll
            for (int mt = 0; mt < 4; ++mt) {
                const int row = wm * 64 + mt * 16 + a_lrow;
                const int chn = 2 * ks + a_lchunk;
                const uint32_t addr = sb + (uint32_t)(row * 64)
                                    + (uint32_t)((chn ^ ((row >> 1) & 3)) << 4);
                ldmatrix_x4(afh[mt], addr);
                ldmatrix_x4(afl[mt], addr + TILE_BYTES);
            }
#pragma unroll
            for (int nt = 0; nt < 4; ++nt) {
                const int row = wn * 32 + nt * 8 + b_lrow;
                const int chn = 2 * ks + b_lchunk;
                const uint32_t addr = sb + 2 * TILE_BYTES + (uint32_t)(row * 64)
                                    + (uint32_t)((chn ^ ((row >> 1) & 3)) << 4);
                ldmatrix_x2(bf[nt], addr);
            }
#pragma unroll
            for (int mt = 0; mt < 4; ++mt)
#pragma unroll
                for (int nt = 0; nt < 4; ++nt) {
                    mma_f16(acc[mt][nt], afh[mt], bf[nt]);
                    mma_f16(acc[mt][nt], afl[mt], bf[nt]);
                }
        }
    }

    const int erow = lane >> 2;
    const int ecol = (lane & 3) * 2;
#pragma unroll
    for (int mt = 0; mt < 4; ++mt) {
#pragma unroll
        for (int nt = 0; nt < 4; ++nt) {
            const int col = ccol + wn * 32 + nt * 8 + ecol;
            const float b0 = bias[col], b1 = bias[col + 1];
            const int r0 = crow + wm * 64 + mt * 16 + erow;
            float2* p0 = reinterpret_cast<float2*>(Cout + (size_t)r0 * N + col);
            *p0 = make_float2(acc[mt][nt][0] + b0, acc[mt][nt][1] + b1);
            float2* p1 = reinterpret_cast<float2*>(Cout + (size_t)(r0 + 8) * N + col);
            *p1 = make_float2(acc[mt][nt][2] + b0, acc[mt][nt][3] + b1);
        }
    }
}

// ---------------------------------------------------------------------------
// qk_prep: fused RoPE + scale (q) -> Q single fp16 [bh][n][104];
//          K fp16 hi/lo [bh][n][104]
// ---------------------------------------------------------------------------
__global__ void qk_prep_kernel(const int* __restrict__ coords,
                               const float* __restrict__ qkv,
                               __half* __restrict__ Qh,
                               __half* __restrict__ Kh, __half* __restrict__ Kl) {
    const int token = blockIdx.x;
    const int tid = threadIdx.x;   // 128
    __shared__ float cs[DD], sn[DD];

    const int c0 = coords[token * 3 + 0];
    const int c1 = coords[token * 3 + 1];
    const int c2 = coords[token * 3 + 2];
    if (tid < DD) {
        const int j = tid;
        int jj, dd, coord;
        if (j < 34)      { const int u = j;      jj = (u < 17) ? u : u - 17; dd = 34; coord = c0; }
        else if (j < 68) { const int u = j - 34; jj = (u < 17) ? u : u - 17; dd = 34; coord = c1; }
        else             { const int u = j - 68; jj = (u < 18) ? u : u - 18; dd = 36; coord = c2; }
        const float inv = powf(10000.0f, -(2.0f * (float)jj) / (float)dd);
        const float ang = (float)coord * inv;
        cs[j] = cosf(ang);
        sn[j] = sinf(ang);
    }
    __syncthreads();

    if (tid >= DD) return;
    const int b = token >> 11, n = token & (NN - 1);
    const float scale = rsqrtf((float)DD);
    const float* base = qkv + (size_t)token * C3;
    const int j = tid;

    for (int h = 0; h < HH; ++h) {
        const size_t o = ((size_t)(b * HH + h) * NN + n) * DD + j;
        const float qa = base[h * DD + j];
        const float qrot = (j < 52) ? -base[h * DD + j + 52] : base[h * DD + j - 52];
        const float qv = (qa * cs[j] + qrot * sn[j]) * scale;
        Qh[o] = __float2half_rn(qv);

        const float ka = base[CC + h * DD + j];
        const float krot = (j < 52) ? -base[CC + h * DD + j + 52] : base[CC + h * DD + j - 52];
        const float kv = ka * cs[j] + krot * sn[j];
        const __half khv = __float2half_rn(kv);
        Kh[o] = khv;
        Kl[o] = __float2half_rn(kv - __half2float(khv));
    }
}

// ---------------------------------------------------------------------------
// vt_prep: V [token][h][d] fp32 -> Vt [bh][d][n] fp16 single (transpose)
// ---------------------------------------------------------------------------
__global__ void vt_prep_kernel(const float* __restrict__ qkv,
                               __half* __restrict__ Vth) {
    __shared__ float t[32][33];
    const int bh = blockIdx.z;
    const int b = bh >> 4, h = bh & 15;
    const int n0 = blockIdx.x * 32;
    const int d0 = blockIdx.y * 32;
    const int tx = threadIdx.x, ty = threadIdx.y;
#pragma unroll
    for (int j = 0; j < 4; ++j) {
        const int d = d0 + tx, n = n0 + ty + 8 * j;
        if (d < DD)
            t[ty + 8 * j][tx] = qkv[(size_t)(b * NN + n) * C3 + 2 * CC + h * DD + d];
    }
    __syncthreads();
#pragma unroll
    for (int j = 0; j < 4; ++j) {
        const int d = d0 + ty + 8 * j, n = n0 + tx;
        if (d < DD)
            Vth[((size_t)bh * DD + d) * NN + n] = __float2half_rn(t[tx][ty + 8 * j]);
    }
}

// ---------------------------------------------------------------------------
// Flash attention, fp16: S = Q*(Kh+Kl), O += P*Vh. 6 k16 + 1 k8 steps.
// 3-stage cp.async pipeline. Epilogue writes fp16 hi/lo proj inputs.
// ---------------------------------------------------------------------------
#define AT_KL 16384
#define AT_V  32768
#define AT_STAGE 46080

__global__ __launch_bounds__(256, 1)
void attn_mma_kernel(const __half* __restrict__ Qh,
                     const __half* __restrict__ Kh, const __half* __restrict__ Kl,
                     const __half* __restrict__ Vth,
                     __half* __restrict__ Oh, __half* __restrict__ Ol) {
    extern __shared__ char smem[];
    const uint32_t sb = smem_u32(smem);
    const int tid = threadIdx.x, lane = tid & 31, wid = tid >> 5;
    const int qt = blockIdx.x, h = blockIdx.y, b = blockIdx.z;
    const int bh = b * HH + h;

    const __half* qh_p = Qh + ((size_t)bh * NN + qt * 128) * DD;
    const __half* kh_p = Kh + (size_t)bh * NN * DD;
    const __half* kl_p = Kl + (size_t)bh * NN * DD;
    const __half* vh_p = Vth + (size_t)bh * DD * NN;

    // ---- stage Q (13 chunks of 8 halves per 256B smem row), extract a-frags ----
    for (int i = tid; i < 128 * 13; i += 256) {
        const int row = i / 13, c = i % 13;
        const uint32_t off = row * 256 + ((c ^ (row & 7)) << 4);
        cp_async16(sb + off, qh_p + (size_t)row * DD + c * 8);
    }
    cp_commit();
    asm volatile("cp.async.wait_group 0;");
    __syncthreads();

    uint32_t qah[6][4], qa8[2];
    {
        const int arow = wid * 16 + (lane & 7) + ((lane >> 3) & 1) * 8;
#pragma unroll
        for (int j = 0; j < 6; ++j) {
            const int chn = 2 * j + (lane >> 4);
            ldmatrix_x4(qah[j], sb + arow * 256 + ((chn ^ (arow & 7)) << 4));
        }
        ldmatrix_x2(qa8, sb + arow * 256 + ((12 ^ (arow & 7)) << 4));
    }
    __syncthreads();

    float oc[13][4];
#pragma unroll
    for (int i = 0; i < 13; ++i) { oc[i][0] = oc[i][1] = oc[i][2] = oc[i][3] = 0.0f; }
    float m0 = -1e30f, m1 = -1e30f, l0 = 0.0f, l1 = 0.0f;

    auto load_stage = [&](int s, int kt) {
        const uint32_t st = sb + (uint32_t)s * AT_STAGE;
        const __half* kh_t = kh_p + (size_t)kt * 64 * DD;
        const __half* kl_t = kl_p + (size_t)kt * 64 * DD;
        for (int i = tid; i < 64 * 13; i += 256) {
            const int row = i / 13, c = i % 13;
            const uint32_t off = row * 256 + ((c ^ (row & 7)) << 4);
            cp_async16(st + off, kh_t + (size_t)row * DD + c * 8);
            cp_async16(st + AT_KL + off, kl_t + (size_t)row * DD + c * 8);
        }
        const __half* vh_t = vh_p + kt * 64;
        for (int i = tid; i < 832; i += 256) {
            const int row = i >> 3, c = i & 7;
            const uint32_t off = row * 128 + ((c ^ (row & 7)) << 4);
            cp_async16(st + AT_V + off, vh_t + (size_t)row * NN + c * 8);
        }
        cp_commit();
    };

    const int nkt = NN / 64;
    load_stage(0, 0);
    load_stage(1, 1);

    for (int kt = 0; kt < nkt; ++kt) {
        if (kt + 2 <= nkt) {
            asm volatile("cp.async.wait_group 1;");
        } else {
            asm volatile("cp.async.wait_group 0;");
        }
        __syncthreads();
        if (kt + 2 < nkt) load_stage((kt + 2) % 3, kt + 2);

        const uint32_t st = sb + (uint32_t)(kt % 3) * AT_STAGE;

        // ---- S = Q (Kh + Kl), fp16 ----
        float sc[8][4];
#pragma unroll
        for (int nt = 0; nt < 8; ++nt) { sc[nt][0] = sc[nt][1] = sc[nt][2] = sc[nt][3] = 0.0f; }

#pragma unroll
        for (int jp = 0; jp < 3; ++jp) {
#pragma unroll
            for (int nt = 0; nt < 8; ++nt) {
                const int brow = nt * 8 + (lane & 7);
                const int bchn = 4 * jp + (lane >> 3);
                const uint32_t addr = st + brow * 256 + ((bchn ^ (brow & 7)) << 4);
                uint32_t bh4[4], bl4[4];
                ldmatrix_x4(bh4, addr);
                ldmatrix_x4(bl4, addr + AT_KL);
                mma_f16(sc[nt], qah[2 * jp], &bh4[0]);
                mma_f16(sc[nt], qah[2 * jp], &bl4[0]);
                mma_f16(sc[nt], qah[2 * jp + 1], &bh4[2]);
                mma_f16(sc[nt], qah[2 * jp + 1], &bl4[2]);
            }
        }
#pragma unroll
        for (int nt = 0; nt < 8; ++nt) {   // k8 step: dims 96..103 (chunk 12)
            const int brow = nt * 8 + (lane & 7);
            const uint32_t addr = st + brow * 256 + ((12 ^ (brow & 7)) << 4);
            uint32_t bh1, bl1;
            ldmatrix_x1(bh1, addr);
            ldmatrix_x1(bl1, addr + AT_KL);
            mma_f16_k8(sc[nt], qa8, bh1);
            mma_f16_k8(sc[nt], qa8, bl1);
        }

        // ---- online softmax ----
        float mx0 = m0, mx1 = m1;
#pragma unroll
        for (int nt = 0; nt < 8; ++nt) {
            mx0 = fmaxf(mx0, fmaxf(sc[nt][0], sc[nt][1]));
            mx1 = fmaxf(mx1, fmaxf(sc[nt][2], sc[nt][3]));
        }
        mx0 = fmaxf(mx0, __shfl_xor_sync(0xffffffffu, mx0, 1));
        mx0 = fmaxf(mx0, __shfl_xor_sync(0xffffffffu, mx0, 2));
        mx1 = fmaxf(mx1, __shfl_xor_sync(0xffffffffu, mx1, 1));
        mx1 = fmaxf(mx1, __shfl_xor_sync(0xffffffffu, mx1, 2));
        const float a0 = __expf(m0 - mx0), a1 = __expf(m1 - mx1);
        m0 = mx0; m1 = mx1;
        l0 *= a0; l1 *= a1;
#pragma unroll
        for (int i = 0; i < 13; ++i) {
            oc[i][0] *= a0; oc[i][1] *= a0; oc[i][2] *= a1; oc[i][3] *= a1;
        }

        uint32_t pah[4][4];
#pragma unroll
        for (int jp = 0; jp < 4; ++jp) {
            const float p00 = __expf(sc[2 * jp][0] - mx0);
            const float p01 = __expf(sc[2 * jp][1] - mx0);
            const float p02 = __expf(sc[2 * jp][2] - mx1);
            const float p03 = __expf(sc[2 * jp][3] - mx1);
            const float p10 = __expf(sc[2 * jp + 1][0] - mx0);
            const float p11 = __expf(sc[2 * jp + 1][1] - mx0);
            const float p12 = __expf(sc[2 * jp + 1][2] - mx1);
            const float p13 = __expf(sc[2 * jp + 1][3] - mx1);
            l0 += p00 + p01 + p10 + p11;
            l1 += p02 + p03 + p12 + p13;
            pah[jp][0] = pack_f16(p00, p01);
            pah[jp][1] = pack_f16(p02, p03);
            pah[jp][2] = pack_f16(p10, p11);
            pah[jp][3] = pack_f16(p12, p13);
        }

        // ---- O += P Vh (fp16 single-term) ----
#pragma unroll
        for (int jph = 0; jph < 2; ++jph) {
#pragma unroll
            for (int ntd = 0; ntd < 13; ++ntd) {
                const int vrow = ntd * 8 + (lane & 7);
                const int vchn = 4 * jph + (lane >> 3);
                const uint32_t addr = st + AT_V + vrow * 128 + ((vchn ^ (vrow & 7)) << 4);
                uint32_t vh4[4];
                ldmatrix_x4(vh4, addr);
                mma_f16(oc[ntd], pah[2 * jph], &vh4[0]);
                mma_f16(oc[ntd], pah[2 * jph + 1], &vh4[2]);
            }
        }
    }

    // ---- epilogue: normalize, split fp16 hi/lo, write proj-GEMM inputs ----
    l0 += __shfl_xor_sync(0xffffffffu, l0, 1);
    l0 += __shfl_xor_sync(0xffffffffu, l0, 2);
    l1 += __shfl_xor_sync(0xffffffffu, l1, 1);
    l1 += __shfl_xor_sync(0xffffffffu, l1, 2);
    const float inv0 = 1.0f / l0, inv1 = 1.0f / l1;
    const int row0 = qt * 128 + wid * 16 + (lane >> 2);
    const size_t tok0 = (size_t)b * NN + row0;
    const int colbase = h * DD + 2 * (lane & 3);
#pragma unroll
    for (int ntd = 0; ntd < 13; ++ntd) {
        const int col = colbase + ntd * 8;
        uint32_t hi, lo;
        pack_hilo_f16(oc[ntd][0] * inv0, oc[ntd][1] * inv0, hi, lo);
        *reinterpret_cast<uint32_t*>(Oh + tok0 * CC + col) = hi;
        *reinterpret_cast<uint32_t*>(Ol + tok0 * CC + col) = lo;
        pack_hilo_f16(oc[ntd][2] * inv1, oc[ntd][3] * inv1, hi, lo);
        *reinterpret_cast<uint32_t*>(Oh + (tok0 + 8) * CC + col) = hi;
        *reinterpret_cast<uint32_t*>(Ol + (tok0 + 8) * CC + col) = lo;
    }
}

// ---------------------------------------------------------------------------
// Launch
// ---------------------------------------------------------------------------
extern "C" void kernel_launch(void* const* d_in, const int* in_sizes, int n_in,
                              void* d_out, int out_size) {
    const float* x = nullptr;
    const int*   coords = nullptr;
    const float* qkv_w = nullptr;
    const float* qkv_b = nullptr;
    const float* proj_w = nullptr;
    const float* proj_b = nullptr;
    for (int i = 0; i < n_in; ++i) {
        switch (in_sizes[i]) {
            case TOKENS * CC:      x      = (const float*)d_in[i]; break;
            case TOKENS * 3:       coords = (const int*)d_in[i];   break;
            case CC * C3:          qkv_w  = (const float*)d_in[i]; break;
            case C3:               qkv_b  = (const float*)d_in[i]; break;
            case CC * CC:          proj_w = (const float*)d_in[i]; break;
            case CC:               proj_b = (const float*)d_in[i]; break;
            default: break;
        }
    }
    float* out = (float*)d_out;

    float* qkv;
    __half *xh, *xl, *ah, *al, *wq, *wp;
    __half *qh, *kh, *kl, *vth;
    cudaGetSymbolAddress((void**)&qkv, g_qkv);
    cudaGetSymbolAddress((void**)&xh,  g_xh);
    cudaGetSymbolAddress((void**)&xl,  g_xl);
    cudaGetSymbolAddress((void**)&ah,  g_ah);
    cudaGetSymbolAddress((void**)&al,  g_al);
    cudaGetSymbolAddress((void**)&wq,  g_wq);
    cudaGetSymbolAddress((void**)&wp,  g_wp);
    cudaGetSymbolAddress((void**)&qh,  g_qh);
    cudaGetSymbolAddress((void**)&kh,  g_kh);
    cudaGetSymbolAddress((void**)&kl,  g_kl);
    cudaGetSymbolAddress((void**)&vth, g_vth);

    const int gemm_smem = 4 * STAGE_BYTES;   // 98304
    cudaFuncSetAttribute(mma_gemm_kernel, cudaFuncAttributeMaxDynamicSharedMemorySize, gemm_smem);
    const int attn_smem = 3 * AT_STAGE;      // 138240
    cudaFuncSetAttribute(attn_mma_kernel, cudaFuncAttributeMaxDynamicSharedMemorySize, attn_smem);

    // 1) split x -> fp16 hi/lo
    convert_split_f16_kernel<<<4096, 256>>>(x, xh, xl, TOKENS * CC);

    // 2) transpose qkv_w -> single fp16
    {
        dim3 grid(C3 / 32, CC / 32);
        transpose_f16_kernel<<<grid, dim3(32, 8)>>>(qkv_w, wq, CC, C3);
    }

    // 3) QKV GEMM (fp16, 2-term)
    {
        dim3 grid(C3 / 128, TOKENS / 128);
        mma_gemm_kernel<<<grid, 256, gemm_smem>>>(xh, xl, wq, qkv_b, qkv,
                                                  TOKENS, C3, CC);
    }

    // 4) RoPE + scale -> Q fp16, K fp16 hi/lo; transpose V -> fp16
    qk_prep_kernel<<<TOKENS, 128>>>(coords, qkv, qh, kh, kl);
    {
        dim3 grid(NN / 32, (DD + 31) / 32, BB * HH);
        vt_prep_kernel<<<grid, dim3(32, 8)>>>(qkv, vth);
    }

    // 5) Flash attention -> writes proj inputs (ah/al, fp16 hi/lo)
    {
        dim3 grid(NN / 128, HH, BB);
        attn_mma_kernel<<<grid, 256, attn_smem>>>(qh, kh, kl, vth, ah, al);
    }

    // 6) transpose proj_w -> single fp16
    {
        dim3 grid(CC / 32, CC / 32);
        transpose_f16_kernel<<<grid, dim3(32, 8)>>>(proj_w, wp, CC, CC);
    }

    // 7) Projection GEMM (fp16, 2-term)
    {
        dim3 grid(CC / 128, TOKENS / 128);
        mma_gemm_kernel<<<grid, 256, gemm_smem>>>(ah, al, wp, proj_b, out,
                                                  TOKENS, CC, CC);
    }
}

// round 10
// speedup vs baseline: 1.9550x; 1.4277x over previous
#include <cuda_runtime.h>
#include <cuda_bf16.h>
#include <cuda_fp16.h>
#include <math.h>
#include <stdint.h>

// Problem constants
#define BB 2
#define NN 2048
#define CC 1664
#define HH 16
#define DD 104
#define C3 (3 * CC)          // 4992
#define TOKENS (BB * NN)     // 4096

// ---------------------------------------------------------------------------
// Scratch (no allocations allowed)
// ---------------------------------------------------------------------------
__device__ __align__(256) float g_qkv[(size_t)TOKENS * C3];
// GEMM operands, single fp16
__device__ __align__(256) __half g_xh[(size_t)TOKENS * CC];
__device__ __align__(256) __half g_ah[(size_t)TOKENS * CC];
__device__ __align__(256) __half g_wq[(size_t)C3 * CC];      // qkv_w^T [4992][1664]
__device__ __align__(256) __half g_wp[(size_t)CC * CC];      // proj_w^T [1664][1664]
// attention operands: Q, K single fp16 (scale folded into Q), rows of 104 halves;
// V transposed [d][n] single fp16
__device__ __align__(256) __half g_qh[(size_t)BB * HH * NN * DD];
__device__ __align__(256) __half g_kh[(size_t)BB * HH * NN * DD];
__device__ __align__(256) __half g_vth[(size_t)BB * HH * DD * NN];

// ---------------------------------------------------------------------------
// Helpers
// ---------------------------------------------------------------------------
__device__ __forceinline__ uint32_t smem_u32(const void* p) {
    uint32_t a;
    asm("{ .reg .u64 t; cvta.to.shared.u64 t, %1; cvt.u32.u64 %0, t; }" : "=r"(a) : "l"(p));
    return a;
}
__device__ __forceinline__ void cp_async16(uint32_t dst, const void* src) {
    asm volatile("cp.async.cg.shared.global [%0], [%1], 16;" :: "r"(dst), "l"(src));
}
__device__ __forceinline__ void cp_commit() {
    asm volatile("cp.async.commit_group;");
}
__device__ __forceinline__ void ldmatrix_x4(uint32_t* r, uint32_t addr) {
    asm volatile("ldmatrix.sync.aligned.m8n8.x4.shared.b16 {%0,%1,%2,%3}, [%4];"
                 : "=r"(r[0]), "=r"(r[1]), "=r"(r[2]), "=r"(r[3]) : "r"(addr));
}
__device__ __forceinline__ void ldmatrix_x2(uint32_t* r, uint32_t addr) {
    asm volatile("ldmatrix.sync.aligned.m8n8.x2.shared.b16 {%0,%1}, [%2];"
                 : "=r"(r[0]), "=r"(r[1]) : "r"(addr));
}
__device__ __forceinline__ void ldmatrix_x1(uint32_t& r, uint32_t addr) {
    asm volatile("ldmatrix.sync.aligned.m8n8.x1.shared.b16 {%0}, [%1];"
                 : "=r"(r) : "r"(addr));
}
__device__ __forceinline__ void mma_f16(float* c, const uint32_t* a, const uint32_t* b) {
    asm volatile("mma.sync.aligned.m16n8k16.row.col.f32.f16.f16.f32 "
                 "{%0,%1,%2,%3}, {%4,%5,%6,%7}, {%8,%9}, {%0,%1,%2,%3};"
                 : "+f"(c[0]), "+f"(c[1]), "+f"(c[2]), "+f"(c[3])
                 : "r"(a[0]), "r"(a[1]), "r"(a[2]), "r"(a[3]), "r"(b[0]), "r"(b[1]));
}
__device__ __forceinline__ void mma_f16_k8(float* c, const uint32_t* a, uint32_t b) {
    asm volatile("mma.sync.aligned.m16n8k8.row.col.f32.f16.f16.f32 "
                 "{%0,%1,%2,%3}, {%4,%5}, {%6}, {%0,%1,%2,%3};"
                 : "+f"(c[0]), "+f"(c[1]), "+f"(c[2]), "+f"(c[3])
                 : "r"(a[0]), "r"(a[1]), "r"(b));
}
__device__ __forceinline__ uint32_t pack_f16(float a, float b) {
    __half2 h = __floats2half2_rn(a, b);
    return *reinterpret_cast<uint32_t*>(&h);
}

// ---------------------------------------------------------------------------
// fp32 -> single fp16 convert
// ---------------------------------------------------------------------------
__global__ void convert_f16_kernel(const float* __restrict__ src,
                                   __half* __restrict__ dst, int n) {
    for (int i = blockIdx.x * blockDim.x + threadIdx.x; i < n; i += gridDim.x * blockDim.x)
        dst[i] = __float2half_rn(src[i]);
}

// ---------------------------------------------------------------------------
// W[Kr][Nc] row-major  ->  T[Nc][Kr] single fp16
// ---------------------------------------------------------------------------
__global__ void transpose_f16_kernel(const float* __restrict__ W,
                                     __half* __restrict__ T,
                                     int Kr, int Nc) {
    __shared__ float t[32][33];
    const int x = blockIdx.x * 32 + threadIdx.x;
    const int y0 = blockIdx.y * 32;
    for (int j = threadIdx.y; j < 32; j += 8)
        t[j][threadIdx.x] = W[(size_t)(y0 + j) * Nc + x];
    __syncthreads();
    const int ox = y0 + threadIdx.x;
    const int oy0 = blockIdx.x * 32;
    for (int j = threadIdx.y; j < 32; j += 8)
        T[(size_t)(oy0 + j) * Kr + ox] = __float2half_rn(t[threadIdx.x][j]);
}

// ---------------------------------------------------------------------------
// mma.sync GEMM, single fp16: C = A[M,K] @ B[N,K]^T + bias[N], fp32 accum.
// 4-stage cp.async pipeline, 2 tiles per stage (A, B).
// ---------------------------------------------------------------------------
#define TILE_BYTES 8192
#define STAGE_BYTES 16384

__global__ __launch_bounds__(256, 1)
void mma_gemm_kernel(const __half* __restrict__ A,
                     const __half* __restrict__ B,
                     const float* __restrict__ bias,
                     float* __restrict__ Cout,
                     int M, int N, int K) {
    extern __shared__ char smem[];
    const uint32_t sbase = smem_u32(smem);
    const int tid  = threadIdx.x;
    const int lane = tid & 31;
    const int wid  = tid >> 5;
    const int wm   = wid & 1;
    const int wn   = wid >> 1;
    const int crow = blockIdx.y * 128;
    const int ccol = blockIdx.x * 128;

    const __half* gsrc[2];
    gsrc[0] = A + (size_t)crow * K;
    gsrc[1] = B + (size_t)ccol * K;

    const int lc  = tid & 3;
    const int lr0 = tid >> 2;
    const int lr1 = lr0 + 64;
    const uint32_t sw0 = (uint32_t)((lc ^ ((lr0 >> 1) & 3)) << 4);
    const uint32_t sw1 = (uint32_t)((lc ^ ((lr1 >> 1) & 3)) << 4);

    float acc[4][4][4];
#pragma unroll
    for (int mt = 0; mt < 4; ++mt)
#pragma unroll
        for (int nt = 0; nt < 4; ++nt)
#pragma unroll
            for (int j = 0; j < 4; ++j) acc[mt][nt][j] = 0.0f;

    const int nch = K / 32;

    auto load_stage = [&](int stage, int k0) {
        const uint32_t sb = sbase + (uint32_t)stage * STAGE_BYTES;
#pragma unroll
        for (int t = 0; t < 2; ++t) {
            const __half* g = gsrc[t];
            cp_async16(sb + t * TILE_BYTES + lr0 * 64 + sw0,
                       g + (size_t)lr0 * K + k0 + lc * 8);
            cp_async16(sb + t * TILE_BYTES + lr1 * 64 + sw1,
                       g + (size_t)lr1 * K + k0 + lc * 8);
        }
        cp_commit();
    };

    load_stage(0, 0);
    load_stage(1, 32);
    load_stage(2, 64);

    const int a_lrow   = (lane & 7) + ((lane >> 3) & 1) * 8;
    const int a_lchunk = lane >> 4;
    const int b_lrow   = lane & 7;
    const int b_lchunk = (lane >> 3) & 1;

    for (int ch = 0; ch < nch; ++ch) {
        if (ch + 3 <= nch) {
            asm volatile("cp.async.wait_group 2;");
        } else if (ch + 2 <= nch) {
            asm volatile("cp.async.wait_group 1;");
        } else {
            asm volatile("cp.async.wait_group 0;");
        }
        __syncthreads();
        if (ch + 3 < nch) load_stage((ch + 3) & 3, (ch + 3) * 32);

        const uint32_t sb = sbase + (uint32_t)(ch & 3) * STAGE_BYTES;

#pragma unroll
        for (int ks = 0; ks < 2; ++ks) {
            uint32_t af[4][4], bf[4][2];
#pragma unroll
            for (int mt = 0; mt < 4; ++mt) {
                const int row = wm * 64 + mt * 16 + a_lrow;
                const int chn = 2 * ks + a_lchunk;
                const uint32_t addr = sbase + (uint32_t)(ch & 3) * STAGE_BYTES
                                    + (uint32_t)(row * 64)
                                    + (uint32_t)((chn ^ ((row >> 1) & 3)) << 4);
                ldmatrix_x4(af[mt], addr);
            }
#pragma unroll
            for (int nt = 0; nt < 4; ++nt) {
                const int row = wn * 32 + nt * 8 + b_lrow;
                const int chn = 2 * ks + b_lchunk;
                const uint32_t addr = sb + TILE_BYTES + (uint32_t)(row * 64)
                                    + (uint32_t)((chn ^ ((row >> 1) & 3)) << 4);
                ldmatrix_x2(bf[nt], addr);
            }
#pragma unroll
            for (int mt = 0; mt < 4; ++mt)
#pragma unroll
                for (int nt = 0; nt < 4; ++nt)
                    mma_f16(acc[mt][nt], af[mt], bf[nt]);
        }
    }

    const int erow = lane >> 2;
    const int ecol = (lane & 3) * 2;
#pragma unroll
    for (int mt = 0; mt < 4; ++mt) {
#pragma unroll
        for (int nt = 0; nt < 4; ++nt) {
            const int col = ccol + wn * 32 + nt * 8 + ecol;
            const float b0 = bias[col], b1 = bias[col + 1];
            const int r0 = crow + wm * 64 + mt * 16 + erow;
            float2* p0 = reinterpret_cast<float2*>(Cout + (size_t)r0 * N + col);
            *p0 = make_float2(acc[mt][nt][0] + b0, acc[mt][nt][1] + b1);
            float2* p1 = reinterpret_cast<float2*>(Cout + (size_t)(r0 + 8) * N + col);
            *p1 = make_float2(acc[mt][nt][2] + b0, acc[mt][nt][3] + b1);
        }
    }
}

// ---------------------------------------------------------------------------
// qk_prep: fused RoPE + scale (q) -> Q, K single fp16 [bh][n][104]
// ---------------------------------------------------------------------------
__global__ void qk_prep_kernel(const int* __restrict__ coords,
                               const float* __restrict__ qkv,
                               __half* __restrict__ Qh,
                               __half* __restrict__ Kh) {
    const int token = blockIdx.x;
    const int tid = threadIdx.x;   // 128
    __shared__ float cs[DD], sn[DD];

    const int c0 = coords[token * 3 + 0];
    const int c1 = coords[token * 3 + 1];
    const int c2 = coords[token * 3 + 2];
    if (tid < DD) {
        const int j = tid;
        int jj, dd, coord;
        if (j < 34)      { const int u = j;      jj = (u < 17) ? u : u - 17; dd = 34; coord = c0; }
        else if (j < 68) { const int u = j - 34; jj = (u < 17) ? u : u - 17; dd = 34; coord = c1; }
        else             { const int u = j - 68; jj = (u < 18) ? u : u - 18; dd = 36; coord = c2; }
        const float inv = powf(10000.0f, -(2.0f * (float)jj) / (float)dd);
        const float ang = (float)coord * inv;
        cs[j] = cosf(ang);
        sn[j] = sinf(ang);
    }
    __syncthreads();

    if (tid >= DD) return;
    const int b = token >> 11, n = token & (NN - 1);
    const float scale = rsqrtf((float)DD);
    const float* base = qkv + (size_t)token * C3;
    const int j = tid;

    for (int h = 0; h < HH; ++h) {
        const size_t o = ((size_t)(b * HH + h) * NN + n) * DD + j;
        const float qa = base[h * DD + j];
        const float qrot = (j < 52) ? -base[h * DD + j + 52] : base[h * DD + j - 52];
        Qh[o] = __float2half_rn((qa * cs[j] + qrot * sn[j]) * scale);

        const float ka = base[CC + h * DD + j];
        const float krot = (j < 52) ? -base[CC + h * DD + j + 52] : base[CC + h * DD + j - 52];
        Kh[o] = __float2half_rn(ka * cs[j] + krot * sn[j]);
    }
}

// ---------------------------------------------------------------------------
// vt_prep: V [token][h][d] fp32 -> Vt [bh][d][n] fp16 single (transpose)
// ---------------------------------------------------------------------------
__global__ void vt_prep_kernel(const float* __restrict__ qkv,
                               __half* __restrict__ Vth) {
    __shared__ float t[32][33];
    const int bh = blockIdx.z;
    const int b = bh >> 4, h = bh & 15;
    const int n0 = blockIdx.x * 32;
    const int d0 = blockIdx.y * 32;
    const int tx = threadIdx.x, ty = threadIdx.y;
#pragma unroll
    for (int j = 0; j < 4; ++j) {
        const int d = d0 + tx, n = n0 + ty + 8 * j;
        if (d < DD)
            t[ty + 8 * j][tx] = qkv[(size_t)(b * NN + n) * C3 + 2 * CC + h * DD + d];
    }
    __syncthreads();
#pragma unroll
    for (int j = 0; j < 4; ++j) {
        const int d = d0 + ty + 8 * j, n = n0 + tx;
        if (d < DD)
            Vth[((size_t)bh * DD + d) * NN + n] = __float2half_rn(t[tx][ty + 8 * j]);
    }
}

// ---------------------------------------------------------------------------
// Flash attention, single fp16: S = Q*K, O += P*V. 6 k16 + 1 k8 steps.
// 3-stage cp.async pipeline. Epilogue writes single-fp16 proj input.
// K tile: 64 rows x 256B (13 data chunks). V tile at +16384: 104 rows x 128B.
// ---------------------------------------------------------------------------
#define AT_V  16384
#define AT_STAGE 29696

__global__ __launch_bounds__(256, 1)
void attn_mma_kernel(const __half* __restrict__ Qh,
                     const __half* __restrict__ Kh,
                     const __half* __restrict__ Vth,
                     __half* __restrict__ Oh) {
    extern __shared__ char smem[];
    const uint32_t sb = smem_u32(smem);
    const int tid = threadIdx.x, lane = tid & 31, wid = tid >> 5;
    const int qt = blockIdx.x, h = blockIdx.y, b = blockIdx.z;
    const int bh = b * HH + h;

    const __half* qh_p = Qh + ((size_t)bh * NN + qt * 128) * DD;
    const __half* kh_p = Kh + (size_t)bh * NN * DD;
    const __half* vh_p = Vth + (size_t)bh * DD * NN;

    // ---- stage Q (13 chunks of 8 halves per 256B smem row), extract a-frags ----
    for (int i = tid; i < 128 * 13; i += 256) {
        const int row = i / 13, c = i % 13;
        const uint32_t off = row * 256 + ((c ^ (row & 7)) << 4);
        cp_async16(sb + off, qh_p + (size_t)row * DD + c * 8);
    }
    cp_commit();
    asm volatile("cp.async.wait_group 0;");
    __syncthreads();

    uint32_t qah[6][4], qa8[2];
    {
        const int arow = wid * 16 + (lane & 7) + ((lane >> 3) & 1) * 8;
#pragma unroll
        for (int j = 0; j < 6; ++j) {
            const int chn = 2 * j + (lane >> 4);
            ldmatrix_x4(qah[j], sb + arow * 256 + ((chn ^ (arow & 7)) << 4));
        }
        ldmatrix_x2(qa8, sb + arow * 256 + ((12 ^ (arow & 7)) << 4));
    }
    __syncthreads();

    float oc[13][4];
#pragma unroll
    for (int i = 0; i < 13; ++i) { oc[i][0] = oc[i][1] = oc[i][2] = oc[i][3] = 0.0f; }
    float m0 = -1e30f, m1 = -1e30f, l0 = 0.0f, l1 = 0.0f;

    auto load_stage = [&](int s, int kt) {
        const uint32_t st = sb + (uint32_t)s * AT_STAGE;
        const __half* kh_t = kh_p + (size_t)kt * 64 * DD;
        for (int i = tid; i < 64 * 13; i += 256) {
            const int row = i / 13, c = i % 13;
            const uint32_t off = row * 256 + ((c ^ (row & 7)) << 4);
            cp_async16(st + off, kh_t + (size_t)row * DD + c * 8);
        }
        const __half* vh_t = vh_p + kt * 64;
        for (int i = tid; i < 832; i += 256) {
            const int row = i >> 3, c = i & 7;
            const uint32_t off = row * 128 + ((c ^ (row & 7)) << 4);
            cp_async16(st + AT_V + off, vh_t + (size_t)row * NN + c * 8);
        }
        cp_commit();
    };

    const int nkt = NN / 64;
    load_stage(0, 0);
    load_stage(1, 1);

    for (int kt = 0; kt < nkt; ++kt) {
        if (kt + 2 <= nkt) {
            asm volatile("cp.async.wait_group 1;");
        } else {
            asm volatile("cp.async.wait_group 0;");
        }
        __syncthreads();
        if (kt + 2 < nkt) load_stage((kt + 2) % 3, kt + 2);

        const uint32_t st = sb + (uint32_t)(kt % 3) * AT_STAGE;

        // ---- S = Q K, fp16 single-term ----
        float sc[8][4];
#pragma unroll
        for (int nt = 0; nt < 8; ++nt) { sc[nt][0] = sc[nt][1] = sc[nt][2] = sc[nt][3] = 0.0f; }

#pragma unroll
        for (int jp = 0; jp < 3; ++jp) {
#pragma unroll
            for (int nt = 0; nt < 8; ++nt) {
                const int brow = nt * 8 + (lane & 7);
                const int bchn = 4 * jp + (lane >> 3);
                const uint32_t addr = st + brow * 256 + ((bchn ^ (brow & 7)) << 4);
                uint32_t bh4[4];
                ldmatrix_x4(bh4, addr);
                mma_f16(sc[nt], qah[2 * jp], &bh4[0]);
                mma_f16(sc[nt], qah[2 * jp + 1], &bh4[2]);
            }
        }
#pragma unroll
        for (int nt = 0; nt < 8; ++nt) {   // k8 step: dims 96..103 (chunk 12)
            const int brow = nt * 8 + (lane & 7);
            const uint32_t addr = st + brow * 256 + ((12 ^ (brow & 7)) << 4);
            uint32_t bh1;
            ldmatrix_x1(bh1, addr);
            mma_f16_k8(sc[nt], qa8, bh1);
        }

        // ---- online softmax ----
        float mx0 = m0, mx1 = m1;
#pragma unroll
        for (int nt = 0; nt < 8; ++nt) {
            mx0 = fmaxf(mx0, fmaxf(sc[nt][0], sc[nt][1]));
            mx1 = fmaxf(mx1, fmaxf(sc[nt][2], sc[nt][3]));
        }
        mx0 = fmaxf(mx0, __shfl_xor_sync(0xffffffffu, mx0, 1));
        mx0 = fmaxf(mx0, __shfl_xor_sync(0xffffffffu, mx0, 2));
        mx1 = fmaxf(mx1, __shfl_xor_sync(0xffffffffu, mx1, 1));
        mx1 = fmaxf(mx1, __shfl_xor_sync(0xffffffffu, mx1, 2));
        const float a0 = __expf(m0 - mx0), a1 = __expf(m1 - mx1);
        m0 = mx0; m1 = mx1;
        l0 *= a0; l1 *= a1;
#pragma unroll
        for (int i = 0; i < 13; ++i) {
            oc[i][0] *= a0; oc[i][1] *= a0; oc[i][2] *= a1; oc[i][3] *= a1;
        }

        uint32_t pah[4][4];
#pragma unroll
        for (int jp = 0; jp < 4; ++jp) {
            const float p00 = __expf(sc[2 * jp][0] - mx0);
            const float p01 = __expf(sc[2 * jp][1] - mx0);
            const float p02 = __expf(sc[2 * jp][2] - mx1);
            const float p03 = __expf(sc[2 * jp][3] - mx1);
            const float p10 = __expf(sc[2 * jp + 1][0] - mx0);
            const float p11 = __expf(sc[2 * jp + 1][1] - mx0);
            const float p12 = __expf(sc[2 * jp + 1][2] - mx1);
            const float p13 = __expf(sc[2 * jp + 1][3] - mx1);
            l0 += p00 + p01 + p10 + p11;
            l1 += p02 + p03 + p12 + p13;
            pah[jp][0] = pack_f16(p00, p01);
            pah[jp][1] = pack_f16(p02, p03);
            pah[jp][2] = pack_f16(p10, p11);
            pah[jp][3] = pack_f16(p12, p13);
        }

        // ---- O += P V (fp16 single-term) ----
#pragma unroll
        for (int jph = 0; jph < 2; ++jph) {
#pragma unroll
            for (int ntd = 0; ntd < 13; ++ntd) {
                const int vrow = ntd * 8 + (lane & 7);
                const int vchn = 4 * jph + (lane >> 3);
                const uint32_t addr = st + AT_V + vrow * 128 + ((vchn ^ (vrow & 7)) << 4);
                uint32_t vh4[4];
                ldmatrix_x4(vh4, addr);
                mma_f16(oc[ntd], pah[2 * jph], &vh4[0]);
                mma_f16(oc[ntd], pah[2 * jph + 1], &vh4[2]);
            }
        }
    }

    // ---- epilogue: normalize, write single-fp16 proj input ----
    l0 += __shfl_xor_sync(0xffffffffu, l0, 1);
    l0 += __shfl_xor_sync(0xffffffffu, l0, 2);
    l1 += __shfl_xor_sync(0xffffffffu, l1, 1);
    l1 += __shfl_xor_sync(0xffffffffu, l1, 2);
    const float inv0 = 1.0f / l0, inv1 = 1.0f / l1;
    const int row0 = qt * 128 + wid * 16 + (lane >> 2);
    const size_t tok0 = (size_t)b * NN + row0;
    const int colbase = h * DD + 2 * (lane & 3);
#pragma unroll
    for (int ntd = 0; ntd < 13; ++ntd) {
        const int col = colbase + ntd * 8;
        *reinterpret_cast<uint32_t*>(Oh + tok0 * CC + col) =
            pack_f16(oc[ntd][0] * inv0, oc[ntd][1] * inv0);
        *reinterpret_cast<uint32_t*>(Oh + (tok0 + 8) * CC + col) =
            pack_f16(oc[ntd][2] * inv1, oc[ntd][3] * inv1);
    }
}

// ---------------------------------------------------------------------------
// Launch
// ---------------------------------------------------------------------------
extern "C" void kernel_launch(void* const* d_in, const int* in_sizes, int n_in,
                              void* d_out, int out_size) {
    const float* x = nullptr;
    const int*   coords = nullptr;
    const float* qkv_w = nullptr;
    const float* qkv_b = nullptr;
    const float* proj_w = nullptr;
    const float* proj_b = nullptr;
    for (int i = 0; i < n_in; ++i) {
        switch (in_sizes[i]) {
            case TOKENS * CC:      x      = (const float*)d_in[i]; break;
            case TOKENS * 3:       coords = (const int*)d_in[i];   break;
            case CC * C3:          qkv_w  = (const float*)d_in[i]; break;
            case C3:               qkv_b  = (const float*)d_in[i]; break;
            case CC * CC:          proj_w = (const float*)d_in[i]; break;
            case CC:               proj_b = (const float*)d_in[i]; break;
            default: break;
        }
    }
    float* out = (float*)d_out;

    float* qkv;
    __half *xh, *ah, *wq, *wp, *qh, *kh, *vth;
    cudaGetSymbolAddress((void**)&qkv, g_qkv);
    cudaGetSymbolAddress((void**)&xh,  g_xh);
    cudaGetSymbolAddress((void**)&ah,  g_ah);
    cudaGetSymbolAddress((void**)&wq,  g_wq);
    cudaGetSymbolAddress((void**)&wp,  g_wp);
    cudaGetSymbolAddress((void**)&qh,  g_qh);
    cudaGetSymbolAddress((void**)&kh,  g_kh);
    cudaGetSymbolAddress((void**)&vth, g_vth);

    const int gemm_smem = 4 * STAGE_BYTES;   // 65536
    cudaFuncSetAttribute(mma_gemm_kernel, cudaFuncAttributeMaxDynamicSharedMemorySize, gemm_smem);
    const int attn_smem = 3 * AT_STAGE;      // 89088
    cudaFuncSetAttribute(attn_mma_kernel, cudaFuncAttributeMaxDynamicSharedMemorySize, attn_smem);

    // 1) convert x -> single fp16
    convert_f16_kernel<<<4096, 256>>>(x, xh, TOKENS * CC);

    // 2) transpose qkv_w -> single fp16
    {
        dim3 grid(C3 / 32, CC / 32);
        transpose_f16_kernel<<<grid, dim3(32, 8)>>>(qkv_w, wq, CC, C3);
    }

    // 3) QKV GEMM (fp16 single-term)
    {
        dim3 grid(C3 / 128, TOKENS / 128);
        mma_gemm_kernel<<<grid, 256, gemm_smem>>>(xh, wq, qkv_b, qkv,
                                                  TOKENS, C3, CC);
    }

    // 4) RoPE + scale -> Q, K fp16; transpose V -> fp16
    qk_prep_kernel<<<TOKENS, 128>>>(coords, qkv, qh, kh);
    {
        dim3 grid(NN / 32, (DD + 31) / 32, BB * HH);
        vt_prep_kernel<<<grid, dim3(32, 8)>>>(qkv, vth);
    }

    // 5) Flash attention -> writes proj input (ah, single fp16)
    {
        dim3 grid(NN / 128, HH, BB);
        attn_mma_kernel<<<grid, 256, attn_smem>>>(qh, kh, vth, ah);
    }

    // 6) transpose proj_w -> single fp16
    {
        dim3 grid(CC / 32, CC / 32);
        transpose_f16_kernel<<<grid, dim3(32, 8)>>>(proj_w, wp, CC, CC);
    }

    // 7) Projection GEMM (fp16 single-term)
    {
        dim3 grid(CC / 128, TOKENS / 128);
        mma_gemm_kernel<<<grid, 256, gemm_smem>>>(ah, wp, proj_b, out,
                                                  TOKENS, CC, CC);
    }
}

// round 11
// speedup vs baseline: 2.0089x; 1.0276x over previous
#include <cuda_runtime.h>
#include <cuda_bf16.h>
#include <cuda_fp16.h>
#include <math.h>
#include <stdint.h>

// Problem constants
#define BB 2
#define NN 2048
#define CC 1664
#define HH 16
#define DD 104
#define C3 (3 * CC)          // 4992
#define TOKENS (BB * NN)     // 4096

// ---------------------------------------------------------------------------
// Scratch (no allocations allowed)
// ---------------------------------------------------------------------------
__device__ __align__(256) __half g_qkv[(size_t)TOKENS * C3];   // fp16 qkv intermediate
__device__ __align__(256) __half g_xh[(size_t)TOKENS * CC];
__device__ __align__(256) __half g_ah[(size_t)TOKENS * CC];
__device__ __align__(256) __half g_wq[(size_t)C3 * CC];        // qkv_w^T [4992][1664]
__device__ __align__(256) __half g_wp[(size_t)CC * CC];        // proj_w^T [1664][1664]
// attention operands: Q, K single fp16 (scale folded into Q), rows of 104 halves;
// V transposed [d][n] single fp16
__device__ __align__(256) __half g_qh[(size_t)BB * HH * NN * DD];
__device__ __align__(256) __half g_kh[(size_t)BB * HH * NN * DD];
__device__ __align__(256) __half g_vth[(size_t)BB * HH * DD * NN];

// ---------------------------------------------------------------------------
// Helpers
// ---------------------------------------------------------------------------
__device__ __forceinline__ uint32_t smem_u32(const void* p) {
    uint32_t a;
    asm("{ .reg .u64 t; cvta.to.shared.u64 t, %1; cvt.u32.u64 %0, t; }" : "=r"(a) : "l"(p));
    return a;
}
__device__ __forceinline__ void cp_async16(uint32_t dst, const void* src) {
    asm volatile("cp.async.cg.shared.global [%0], [%1], 16;" :: "r"(dst), "l"(src));
}
__device__ __forceinline__ void cp_commit() {
    asm volatile("cp.async.commit_group;");
}
__device__ __forceinline__ void ldmatrix_x4(uint32_t* r, uint32_t addr) {
    asm volatile("ldmatrix.sync.aligned.m8n8.x4.shared.b16 {%0,%1,%2,%3}, [%4];"
                 : "=r"(r[0]), "=r"(r[1]), "=r"(r[2]), "=r"(r[3]) : "r"(addr));
}
__device__ __forceinline__ void ldmatrix_x2(uint32_t* r, uint32_t addr) {
    asm volatile("ldmatrix.sync.aligned.m8n8.x2.shared.b16 {%0,%1}, [%2];"
                 : "=r"(r[0]), "=r"(r[1]) : "r"(addr));
}
__device__ __forceinline__ void ldmatrix_x1(uint32_t& r, uint32_t addr) {
    asm volatile("ldmatrix.sync.aligned.m8n8.x1.shared.b16 {%0}, [%1];"
                 : "=r"(r) : "r"(addr));
}
__device__ __forceinline__ void mma_f16(float* c, const uint32_t* a, const uint32_t* b) {
    asm volatile("mma.sync.aligned.m16n8k16.row.col.f32.f16.f16.f32 "
                 "{%0,%1,%2,%3}, {%4,%5,%6,%7}, {%8,%9}, {%0,%1,%2,%3};"
                 : "+f"(c[0]), "+f"(c[1]), "+f"(c[2]), "+f"(c[3])
                 : "r"(a[0]), "r"(a[1]), "r"(a[2]), "r"(a[3]), "r"(b[0]), "r"(b[1]));
}
__device__ __forceinline__ void mma_f16_k8(float* c, const uint32_t* a, uint32_t b) {
    asm volatile("mma.sync.aligned.m16n8k8.row.col.f32.f16.f16.f32 "
                 "{%0,%1,%2,%3}, {%4,%5}, {%6}, {%0,%1,%2,%3};"
                 : "+f"(c[0]), "+f"(c[1]), "+f"(c[2]), "+f"(c[3])
                 : "r"(a[0]), "r"(a[1]), "r"(b));
}
__device__ __forceinline__ uint32_t pack_f16(float a, float b) {
    __half2 h = __floats2half2_rn(a, b);
    return *reinterpret_cast<uint32_t*>(&h);
}

// ---------------------------------------------------------------------------
// fp32 -> single fp16 convert
// ---------------------------------------------------------------------------
__global__ void convert_f16_kernel(const float* __restrict__ src,
                                   __half* __restrict__ dst, int n) {
    for (int i = blockIdx.x * blockDim.x + threadIdx.x; i < n; i += gridDim.x * blockDim.x)
        dst[i] = __float2half_rn(src[i]);
}

// ---------------------------------------------------------------------------
// W[Kr][Nc] row-major  ->  T[Nc][Kr] single fp16
// ---------------------------------------------------------------------------
__global__ void transpose_f16_kernel(const float* __restrict__ W,
                                     __half* __restrict__ T,
                                     int Kr, int Nc) {
    __shared__ float t[32][33];
    const int x = blockIdx.x * 32 + threadIdx.x;
    const int y0 = blockIdx.y * 32;
    for (int j = threadIdx.y; j < 32; j += 8)
        t[j][threadIdx.x] = W[(size_t)(y0 + j) * Nc + x];
    __syncthreads();
    const int ox = y0 + threadIdx.x;
    const int oy0 = blockIdx.x * 32;
    for (int j = threadIdx.y; j < 32; j += 8)
        T[(size_t)(oy0 + j) * Kr + ox] = __float2half_rn(t[threadIdx.x][j]);
}

// ---------------------------------------------------------------------------
// mma.sync GEMM, single fp16: C = A[M,K] @ B[N,K]^T + bias[N], fp32 accum.
// CTA tile 256x128 (warps 4m x 2n, warp tile 64x64). 4-stage cp.async.
// Templated output: __half (qkv intermediate) or float (final out).
// ---------------------------------------------------------------------------
#define GM_TILE_A 16384   // 256 rows * 64B
#define GM_TILE_B 8192    // 128 rows * 64B
#define GM_STAGE  24576

template <typename OutT>
__global__ __launch_bounds__(256, 1)
void mma_gemm_kernel(const __half* __restrict__ A,
                     const __half* __restrict__ B,
                     const float* __restrict__ bias,
                     OutT* __restrict__ Cout,
                     int M, int N, int K) {
    extern __shared__ char smem[];
    const uint32_t sbase = smem_u32(smem);
    const int tid  = threadIdx.x;
    const int lane = tid & 31;
    const int wid  = tid >> 5;
    const int wm   = wid & 3;        // 0..3  (m, 64 rows each)
    const int wn   = wid >> 2;       // 0..1  (n, 64 cols each)
    const int crow = blockIdx.y * 256;
    const int ccol = blockIdx.x * 128;

    const __half* Abase = A + (size_t)crow * K;
    const __half* Bbase = B + (size_t)ccol * K;

    const int lc  = tid & 3;         // chunk
    const int lr  = tid >> 2;        // 0..63

    float acc[4][8][4];
#pragma unroll
    for (int mt = 0; mt < 4; ++mt)
#pragma unroll
        for (int nt = 0; nt < 8; ++nt)
#pragma unroll
            for (int j = 0; j < 4; ++j) acc[mt][nt][j] = 0.0f;

    const int nch = K / 32;

    auto load_stage = [&](int stage, int k0) {
        const uint32_t sb = sbase + (uint32_t)stage * GM_STAGE;
#pragma unroll
        for (int rr = 0; rr < 4; ++rr) {
            const int row = lr + rr * 64;
            const uint32_t sw = (uint32_t)((lc ^ ((row >> 1) & 3)) << 4);
            cp_async16(sb + row * 64 + sw, Abase + (size_t)row * K + k0 + lc * 8);
        }
#pragma unroll
        for (int rr = 0; rr < 2; ++rr) {
            const int row = lr + rr * 64;
            const uint32_t sw = (uint32_t)((lc ^ ((row >> 1) & 3)) << 4);
            cp_async16(sb + GM_TILE_A + row * 64 + sw, Bbase + (size_t)row * K + k0 + lc * 8);
        }
        cp_commit();
    };

    load_stage(0, 0);
    load_stage(1, 32);
    load_stage(2, 64);

    const int a_lrow   = (lane & 7) + ((lane >> 3) & 1) * 8;
    const int a_lchunk = lane >> 4;
    const int b_lrow   = lane & 7;
    const int b_lchunk = (lane >> 3) & 1;

    for (int ch = 0; ch < nch; ++ch) {
        if (ch + 3 <= nch) {
            asm volatile("cp.async.wait_group 2;");
        } else if (ch + 2 <= nch) {
            asm volatile("cp.async.wait_group 1;");
        } else {
            asm volatile("cp.async.wait_group 0;");
        }
        __syncthreads();
        if (ch + 3 < nch) load_stage((ch + 3) & 3, (ch + 3) * 32);

        const uint32_t sb = sbase + (uint32_t)(ch & 3) * GM_STAGE;

#pragma unroll
        for (int ks = 0; ks < 2; ++ks) {
            uint32_t af[4][4], bf[8][2];
#pragma unroll
            for (int mt = 0; mt < 4; ++mt) {
                const int row = wm * 64 + mt * 16 + a_lrow;
                const int chn = 2 * ks + a_lchunk;
                const uint32_t addr = sb + (uint32_t)(row * 64)
                                    + (uint32_t)((chn ^ ((row >> 1) & 3)) << 4);
                ldmatrix_x4(af[mt], addr);
            }
#pragma unroll
            for (int nt = 0; nt < 8; ++nt) {
                const int row = wn * 64 + nt * 8 + b_lrow;
                const int chn = 2 * ks + b_lchunk;
                const uint32_t addr = sb + GM_TILE_A + (uint32_t)(row * 64)
                                    + (uint32_t)((chn ^ ((row >> 1) & 3)) << 4);
                ldmatrix_x2(bf[nt], addr);
            }
#pragma unroll
            for (int mt = 0; mt < 4; ++mt)
#pragma unroll
                for (int nt = 0; nt < 8; ++nt)
                    mma_f16(acc[mt][nt], af[mt], bf[nt]);
        }
    }

    const int erow = lane >> 2;
    const int ecol = (lane & 3) * 2;
#pragma unroll
    for (int mt = 0; mt < 4; ++mt) {
#pragma unroll
        for (int nt = 0; nt < 8; ++nt) {
            const int col = ccol + wn * 64 + nt * 8 + ecol;
            const float b0 = bias[col], b1 = bias[col + 1];
            const int r0 = crow + wm * 64 + mt * 16 + erow;
            if constexpr (sizeof(OutT) == 4) {
                float2* p0 = reinterpret_cast<float2*>((float*)Cout + (size_t)r0 * N + col);
                *p0 = make_float2(acc[mt][nt][0] + b0, acc[mt][nt][1] + b1);
                float2* p1 = reinterpret_cast<float2*>((float*)Cout + (size_t)(r0 + 8) * N + col);
                *p1 = make_float2(acc[mt][nt][2] + b0, acc[mt][nt][3] + b1);
            } else {
                *reinterpret_cast<uint32_t*>((__half*)Cout + (size_t)r0 * N + col) =
                    pack_f16(acc[mt][nt][0] + b0, acc[mt][nt][1] + b1);
                *reinterpret_cast<uint32_t*>((__half*)Cout + (size_t)(r0 + 8) * N + col) =
                    pack_f16(acc[mt][nt][2] + b0, acc[mt][nt][3] + b1);
            }
        }
    }
}

// ---------------------------------------------------------------------------
// qk_prep: fused RoPE + scale (q) -> Q, K single fp16 [bh][n][104]
// (reads fp16 qkv intermediate)
// ---------------------------------------------------------------------------
__global__ void qk_prep_kernel(const int* __restrict__ coords,
                               const __half* __restrict__ qkv,
                               __half* __restrict__ Qh,
                               __half* __restrict__ Kh) {
    const int token = blockIdx.x;
    const int tid = threadIdx.x;   // 128
    __shared__ float cs[DD], sn[DD];

    const int c0 = coords[token * 3 + 0];
    const int c1 = coords[token * 3 + 1];
    const int c2 = coords[token * 3 + 2];
    if (tid < DD) {
        const int j = tid;
        int jj, dd, coord;
        if (j < 34)      { const int u = j;      jj = (u < 17) ? u : u - 17; dd = 34; coord = c0; }
        else if (j < 68) { const int u = j - 34; jj = (u < 17) ? u : u - 17; dd = 34; coord = c1; }
        else             { const int u = j - 68; jj = (u < 18) ? u : u - 18; dd = 36; coord = c2; }
        const float inv = powf(10000.0f, -(2.0f * (float)jj) / (float)dd);
        const float ang = (float)coord * inv;
        cs[j] = cosf(ang);
        sn[j] = sinf(ang);
    }
    __syncthreads();

    if (tid >= DD) return;
    const int b = token >> 11, n = token & (NN - 1);
    const float scale = rsqrtf((float)DD);
    const __half* base = qkv + (size_t)token * C3;
    const int j = tid;

    for (int h = 0; h < HH; ++h) {
        const size_t o = ((size_t)(b * HH + h) * NN + n) * DD + j;
        const float qa = __half2float(base[h * DD + j]);
        const float qrot = (j < 52) ? -__half2float(base[h * DD + j + 52])
                                    :  __half2float(base[h * DD + j - 52]);
        Qh[o] = __float2half_rn((qa * cs[j] + qrot * sn[j]) * scale);

        const float ka = __half2float(base[CC + h * DD + j]);
        const float krot = (j < 52) ? -__half2float(base[CC + h * DD + j + 52])
                                    :  __half2float(base[CC + h * DD + j - 52]);
        Kh[o] = __float2half_rn(ka * cs[j] + krot * sn[j]);
    }
}

// ---------------------------------------------------------------------------
// vt_prep: V [token][h][d] fp16 -> Vt [bh][d][n] fp16 (transpose)
// ---------------------------------------------------------------------------
__global__ void vt_prep_kernel(const __half* __restrict__ qkv,
                               __half* __restrict__ Vth) {
    __shared__ float t[32][33];
    const int bh = blockIdx.z;
    const int b = bh >> 4, h = bh & 15;
    const int n0 = blockIdx.x * 32;
    const int d0 = blockIdx.y * 32;
    const int tx = threadIdx.x, ty = threadIdx.y;
#pragma unroll
    for (int j = 0; j < 4; ++j) {
        const int d = d0 + tx, n = n0 + ty + 8 * j;
        if (d < DD)
            t[ty + 8 * j][tx] = __half2float(qkv[(size_t)(b * NN + n) * C3 + 2 * CC + h * DD + d]);
    }
    __syncthreads();
#pragma unroll
    for (int j = 0; j < 4; ++j) {
        const int d = d0 + ty + 8 * j, n = n0 + tx;
        if (d < DD)
            Vth[((size_t)bh * DD + d) * NN + n] = __float2half_rn(t[tx][ty + 8 * j]);
    }
}

// ---------------------------------------------------------------------------
// Flash attention, single fp16: S = Q*K, O += P*V. 6 k16 + 1 k8 steps.
// 3-stage cp.async pipeline. Epilogue writes single-fp16 proj input.
// ---------------------------------------------------------------------------
#define AT_V  16384
#define AT_STAGE 29696

__global__ __launch_bounds__(256, 1)
void attn_mma_kernel(const __half* __restrict__ Qh,
                     const __half* __restrict__ Kh,
                     const __half* __restrict__ Vth,
                     __half* __restrict__ Oh) {
    extern __shared__ char smem[];
    const uint32_t sb = smem_u32(smem);
    const int tid = threadIdx.x, lane = tid & 31, wid = tid >> 5;
    const int qt = blockIdx.x, h = blockIdx.y, b = blockIdx.z;
    const int bh = b * HH + h;

    const __half* qh_p = Qh + ((size_t)bh * NN + qt * 128) * DD;
    const __half* kh_p = Kh + (size_t)bh * NN * DD;
    const __half* vh_p = Vth + (size_t)bh * DD * NN;

    // ---- stage Q (13 chunks of 8 halves per 256B smem row), extract a-frags ----
    for (int i = tid; i < 128 * 13; i += 256) {
        const int row = i / 13, c = i % 13;
        const uint32_t off = row * 256 + ((c ^ (row & 7)) << 4);
        cp_async16(sb + off, qh_p + (size_t)row * DD + c * 8);
    }
    cp_commit();
    asm volatile("cp.async.wait_group 0;");
    __syncthreads();

    uint32_t qah[6][4], qa8[2];
    {
        const int arow = wid * 16 + (lane & 7) + ((lane >> 3) & 1) * 8;
#pragma unroll
        for (int j = 0; j < 6; ++j) {
            const int chn = 2 * j + (lane >> 4);
            ldmatrix_x4(qah[j], sb + arow * 256 + ((chn ^ (arow & 7)) << 4));
        }
        ldmatrix_x2(qa8, sb + arow * 256 + ((12 ^ (arow & 7)) << 4));
    }
    __syncthreads();

    float oc[13][4];
#pragma unroll
    for (int i = 0; i < 13; ++i) { oc[i][0] = oc[i][1] = oc[i][2] = oc[i][3] = 0.0f; }
    float m0 = -1e30f, m1 = -1e30f, l0 = 0.0f, l1 = 0.0f;

    auto load_stage = [&](int s, int kt) {
        const uint32_t st = sb + (uint32_t)s * AT_STAGE;
        const __half* kh_t = kh_p + (size_t)kt * 64 * DD;
        for (int i = tid; i < 64 * 13; i += 256) {
            const int row = i / 13, c = i % 13;
            const uint32_t off = row * 256 + ((c ^ (row & 7)) << 4);
            cp_async16(st + off, kh_t + (size_t)row * DD + c * 8);
        }
        const __half* vh_t = vh_p + kt * 64;
        for (int i = tid; i < 832; i += 256) {
            const int row = i >> 3, c = i & 7;
            const uint32_t off = row * 128 + ((c ^ (row & 7)) << 4);
            cp_async16(st + AT_V + off, vh_t + (size_t)row * NN + c * 8);
        }
        cp_commit();
    };

    const int nkt = NN / 64;
    load_stage(0, 0);
    load_stage(1, 1);

    for (int kt = 0; kt < nkt; ++kt) {
        if (kt + 2 <= nkt) {
            asm volatile("cp.async.wait_group 1;");
        } else {
            asm volatile("cp.async.wait_group 0;");
        }
        __syncthreads();
        if (kt + 2 < nkt) load_stage((kt + 2) % 3, kt + 2);

        const uint32_t st = sb + (uint32_t)(kt % 3) * AT_STAGE;

        // ---- S = Q K, fp16 single-term ----
        float sc[8][4];
#pragma unroll
        for (int nt = 0; nt < 8; ++nt) { sc[nt][0] = sc[nt][1] = sc[nt][2] = sc[nt][3] = 0.0f; }

#pragma unroll
        for (int jp = 0; jp < 3; ++jp) {
#pragma unroll
            for (int nt = 0; nt < 8; ++nt) {
                const int brow = nt * 8 + (lane & 7);
                const int bchn = 4 * jp + (lane >> 3);
                const uint32_t addr = st + brow * 256 + ((bchn ^ (brow & 7)) << 4);
                uint32_t bh4[4];
                ldmatrix_x4(bh4, addr);
                mma_f16(sc[nt], qah[2 * jp], &bh4[0]);
                mma_f16(sc[nt], qah[2 * jp + 1], &bh4[2]);
            }
        }
#pragma unroll
        for (int nt = 0; nt < 8; ++nt) {   // k8 step: dims 96..103 (chunk 12)
            const int brow = nt * 8 + (lane & 7);
            const uint32_t addr = st + brow * 256 + ((12 ^ (brow & 7)) << 4);
            uint32_t bh1;
            ldmatrix_x1(bh1, addr);
            mma_f16_k8(sc[nt], qa8, bh1);
        }

        // ---- online softmax ----
        float mx0 = m0, mx1 = m1;
#pragma unroll
        for (int nt = 0; nt < 8; ++nt) {
            mx0 = fmaxf(mx0, fmaxf(sc[nt][0], sc[nt][1]));
            mx1 = fmaxf(mx1, fmaxf(sc[nt][2], sc[nt][3]));
        }
        mx0 = fmaxf(mx0, __shfl_xor_sync(0xffffffffu, mx0, 1));
        mx0 = fmaxf(mx0, __shfl_xor_sync(0xffffffffu, mx0, 2));
        mx1 = fmaxf(mx1, __shfl_xor_sync(0xffffffffu, mx1, 1));
        mx1 = fmaxf(mx1, __shfl_xor_sync(0xffffffffu, mx1, 2));
        const float a0 = __expf(m0 - mx0), a1 = __expf(m1 - mx1);
        m0 = mx0; m1 = mx1;
        l0 *= a0; l1 *= a1;
#pragma unroll
        for (int i = 0; i < 13; ++i) {
            oc[i][0] *= a0; oc[i][1] *= a0; oc[i][2] *= a1; oc[i][3] *= a1;
        }

        uint32_t pah[4][4];
#pragma unroll
        for (int jp = 0; jp < 4; ++jp) {
            const float p00 = __expf(sc[2 * jp][0] - mx0);
            const float p01 = __expf(sc[2 * jp][1] - mx0);
            const float p02 = __expf(sc[2 * jp][2] - mx1);
            const float p03 = __expf(sc[2 * jp][3] - mx1);
            const float p10 = __expf(sc[2 * jp + 1][0] - mx0);
            const float p11 = __expf(sc[2 * jp + 1][1] - mx0);
            const float p12 = __expf(sc[2 * jp + 1][2] - mx1);
            const float p13 = __expf(sc[2 * jp + 1][3] - mx1);
            l0 += p00 + p01 + p10 + p11;
            l1 += p02 + p03 + p12 + p13;
            pah[jp][0] = pack_f16(p00, p01);
            pah[jp][1] = pack_f16(p02, p03);
            pah[jp][2] = pack_f16(p10, p11);
            pah[jp][3] = pack_f16(p12, p13);
        }

        // ---- O += P V (fp16 single-term) ----
#pragma unroll
        for (int jph = 0; jph < 2; ++jph) {
#pragma unroll
            for (int ntd = 0; ntd < 13; ++ntd) {
                const int vrow = ntd * 8 + (lane & 7);
                const int vchn = 4 * jph + (lane >> 3);
                const uint32_t addr = st + AT_V + vrow * 128 + ((vchn ^ (vrow & 7)) << 4);
                uint32_t vh4[4];
                ldmatrix_x4(vh4, addr);
                mma_f16(oc[ntd], pah[2 * jph], &vh4[0]);
                mma_f16(oc[ntd], pah[2 * jph + 1], &vh4[2]);
            }
        }
    }

    // ---- epilogue: normalize, write single-fp16 proj input ----
    l0 += __shfl_xor_sync(0xffffffffu, l0, 1);
    l0 += __shfl_xor_sync(0xffffffffu, l0, 2);
    l1 += __shfl_xor_sync(0xffffffffu, l1, 1);
    l1 += __shfl_xor_sync(0xffffffffu, l1, 2);
    const float inv0 = 1.0f / l0, inv1 = 1.0f / l1;
    const int row0 = qt * 128 + wid * 16 + (lane >> 2);
    const size_t tok0 = (size_t)b * NN + row0;
    const int colbase = h * DD + 2 * (lane & 3);
#pragma unroll
    for (int ntd = 0; ntd < 13; ++ntd) {
        const int col = colbase + ntd * 8;
        *reinterpret_cast<uint32_t*>(Oh + tok0 * CC + col) =
            pack_f16(oc[ntd][0] * inv0, oc[ntd][1] * inv0);
        *reinterpret_cast<uint32_t*>(Oh + (tok0 + 8) * CC + col) =
            pack_f16(oc[ntd][2] * inv1, oc[ntd][3] * inv1);
    }
}

// ---------------------------------------------------------------------------
// Launch
// ---------------------------------------------------------------------------
extern "C" void kernel_launch(void* const* d_in, const int* in_sizes, int n_in,
                              void* d_out, int out_size) {
    const float* x = nullptr;
    const int*   coords = nullptr;
    const float* qkv_w = nullptr;
    const float* qkv_b = nullptr;
    const float* proj_w = nullptr;
    const float* proj_b = nullptr;
    for (int i = 0; i < n_in; ++i) {
        switch (in_sizes[i]) {
            case TOKENS * CC:      x      = (const float*)d_in[i]; break;
            case TOKENS * 3:       coords = (const int*)d_in[i];   break;
            case CC * C3:          qkv_w  = (const float*)d_in[i]; break;
            case C3:               qkv_b  = (const float*)d_in[i]; break;
            case CC * CC:          proj_w = (const float*)d_in[i]; break;
            case CC:               proj_b = (const float*)d_in[i]; break;
            default: break;
        }
    }
    float* out = (float*)d_out;

    __half *qkv, *xh, *ah, *wq, *wp, *qh, *kh, *vth;
    cudaGetSymbolAddress((void**)&qkv, g_qkv);
    cudaGetSymbolAddress((void**)&xh,  g_xh);
    cudaGetSymbolAddress((void**)&ah,  g_ah);
    cudaGetSymbolAddress((void**)&wq,  g_wq);
    cudaGetSymbolAddress((void**)&wp,  g_wp);
    cudaGetSymbolAddress((void**)&qh,  g_qh);
    cudaGetSymbolAddress((void**)&kh,  g_kh);
    cudaGetSymbolAddress((void**)&vth, g_vth);

    const int gemm_smem = 4 * GM_STAGE;      // 98304
    cudaFuncSetAttribute(mma_gemm_kernel<__half>, cudaFuncAttributeMaxDynamicSharedMemorySize, gemm_smem);
    cudaFuncSetAttribute(mma_gemm_kernel<float>,  cudaFuncAttributeMaxDynamicSharedMemorySize, gemm_smem);
    const int attn_smem = 3 * AT_STAGE;      // 89088
    cudaFuncSetAttribute(attn_mma_kernel, cudaFuncAttributeMaxDynamicSharedMemorySize, attn_smem);

    // 1) convert x -> single fp16
    convert_f16_kernel<<<4096, 256>>>(x, xh, TOKENS * CC);

    // 2) transpose qkv_w -> single fp16
    {
        dim3 grid(C3 / 32, CC / 32);
        transpose_f16_kernel<<<grid, dim3(32, 8)>>>(qkv_w, wq, CC, C3);
    }

    // 3) QKV GEMM (fp16, writes fp16 intermediate)
    {
        dim3 grid(C3 / 128, TOKENS / 256);
        mma_gemm_kernel<__half><<<grid, 256, gemm_smem>>>(xh, wq, qkv_b, qkv,
                                                          TOKENS, C3, CC);
    }

    // 4) RoPE + scale -> Q, K fp16; transpose V -> fp16
    qk_prep_kernel<<<TOKENS, 128>>>(coords, qkv, qh, kh);
    {
        dim3 grid(NN / 32, (DD + 31) / 32, BB * HH);
        vt_prep_kernel<<<grid, dim3(32, 8)>>>(qkv, vth);
    }

    // 5) Flash attention -> writes proj input (ah, single fp16)
    {
        dim3 grid(NN / 128, HH, BB);
        attn_mma_kernel<<<grid, 256, attn_smem>>>(qh, kh, vth, ah);
    }

    // 6) transpose proj_w -> single fp16
    {
        dim3 grid(CC / 32, CC / 32);
        transpose_f16_kernel<<<grid, dim3(32, 8)>>>(proj_w, wp, CC, CC);
    }

    // 7) Projection GEMM (fp16, writes fp32 output)
    {
        dim3 grid(CC / 128, TOKENS / 256);
        mma_gemm_kernel<float><<<grid, 256, gemm_smem>>>(ah, wp, proj_b, out,
                                                         TOKENS, CC, CC);
    }
}

// round 12
// speedup vs baseline: 2.2808x; 1.1353x over previous
#include <cuda_runtime.h>
#include <cuda_bf16.h>
#include <cuda_fp16.h>
#include <math.h>
#include <stdint.h>

// Problem constants
#define BB 2
#define NN 2048
#define CC 1664
#define HH 16
#define DD 104
#define C3 (3 * CC)          // 4992
#define TOKENS (BB * NN)     // 4096

// ---------------------------------------------------------------------------
// Scratch (no allocations allowed)
// ---------------------------------------------------------------------------
__device__ __align__(256) __half g_qkv[(size_t)TOKENS * C3];   // fp16 qkv intermediate
__device__ __align__(256) __half g_xh[(size_t)TOKENS * CC];
__device__ __align__(256) __half g_ah[(size_t)TOKENS * CC];
__device__ __align__(256) __half g_wq[(size_t)C3 * CC];        // qkv_w^T [4992][1664]
__device__ __align__(256) __half g_wp[(size_t)CC * CC];        // proj_w^T [1664][1664]
// attention operands: Q, K single fp16 (scale folded into Q), rows of 104 halves;
// V transposed [d][n] single fp16
__device__ __align__(256) __half g_qh[(size_t)BB * HH * NN * DD];
__device__ __align__(256) __half g_kh[(size_t)BB * HH * NN * DD];
__device__ __align__(256) __half g_vth[(size_t)BB * HH * DD * NN];

// ---------------------------------------------------------------------------
// Helpers
// ---------------------------------------------------------------------------
__device__ __forceinline__ uint32_t smem_u32(const void* p) {
    uint32_t a;
    asm("{ .reg .u64 t; cvta.to.shared.u64 t, %1; cvt.u32.u64 %0, t; }" : "=r"(a) : "l"(p));
    return a;
}
__device__ __forceinline__ void cp_async16(uint32_t dst, const void* src) {
    asm volatile("cp.async.cg.shared.global [%0], [%1], 16;" :: "r"(dst), "l"(src));
}
__device__ __forceinline__ void cp_commit() {
    asm volatile("cp.async.commit_group;");
}
__device__ __forceinline__ void ldmatrix_x4(uint32_t* r, uint32_t addr) {
    asm volatile("ldmatrix.sync.aligned.m8n8.x4.shared.b16 {%0,%1,%2,%3}, [%4];"
                 : "=r"(r[0]), "=r"(r[1]), "=r"(r[2]), "=r"(r[3]) : "r"(addr));
}
__device__ __forceinline__ void ldmatrix_x2(uint32_t* r, uint32_t addr) {
    asm volatile("ldmatrix.sync.aligned.m8n8.x2.shared.b16 {%0,%1}, [%2];"
                 : "=r"(r[0]), "=r"(r[1]) : "r"(addr));
}
__device__ __forceinline__ void ldmatrix_x1(uint32_t& r, uint32_t addr) {
    asm volatile("ldmatrix.sync.aligned.m8n8.x1.shared.b16 {%0}, [%1];"
                 : "=r"(r) : "r"(addr));
}
__device__ __forceinline__ void mma_f16(float* c, const uint32_t* a, const uint32_t* b) {
    asm volatile("mma.sync.aligned.m16n8k16.row.col.f32.f16.f16.f32 "
                 "{%0,%1,%2,%3}, {%4,%5,%6,%7}, {%8,%9}, {%0,%1,%2,%3};"
                 : "+f"(c[0]), "+f"(c[1]), "+f"(c[2]), "+f"(c[3])
                 : "r"(a[0]), "r"(a[1]), "r"(a[2]), "r"(a[3]), "r"(b[0]), "r"(b[1]));
}
__device__ __forceinline__ void mma_f16_k8(float* c, const uint32_t* a, uint32_t b) {
    asm volatile("mma.sync.aligned.m16n8k8.row.col.f32.f16.f16.f32 "
                 "{%0,%1,%2,%3}, {%4,%5}, {%6}, {%0,%1,%2,%3};"
                 : "+f"(c[0]), "+f"(c[1]), "+f"(c[2]), "+f"(c[3])
                 : "r"(a[0]), "r"(a[1]), "r"(b));
}
__device__ __forceinline__ uint32_t pack_f16(float a, float b) {
    __half2 h = __floats2half2_rn(a, b);
    return *reinterpret_cast<uint32_t*>(&h);
}

// ---------------------------------------------------------------------------
// fp32 -> single fp16 convert
// ---------------------------------------------------------------------------
__global__ void convert_f16_kernel(const float* __restrict__ src,
                                   __half* __restrict__ dst, int n) {
    for (int i = blockIdx.x * blockDim.x + threadIdx.x; i < n; i += gridDim.x * blockDim.x)
        dst[i] = __float2half_rn(src[i]);
}

// ---------------------------------------------------------------------------
// W[Kr][Nc] row-major  ->  T[Nc][Kr] single fp16
// ---------------------------------------------------------------------------
__global__ void transpose_f16_kernel(const float* __restrict__ W,
                                     __half* __restrict__ T,
                                     int Kr, int Nc) {
    __shared__ float t[32][33];
    const int x = blockIdx.x * 32 + threadIdx.x;
    const int y0 = blockIdx.y * 32;
    for (int j = threadIdx.y; j < 32; j += 8)
        t[j][threadIdx.x] = W[(size_t)(y0 + j) * Nc + x];
    __syncthreads();
    const int ox = y0 + threadIdx.x;
    const int oy0 = blockIdx.x * 32;
    for (int j = threadIdx.y; j < 32; j += 8)
        T[(size_t)(oy0 + j) * Kr + ox] = __float2half_rn(t[threadIdx.x][j]);
}

// ---------------------------------------------------------------------------
// mma.sync GEMM, single fp16: C = A[M,K] @ B[N,K]^T + bias[N], fp32 accum.
// CTA tile 128x128, 3-stage cp.async, 2 CTAs/SM (bubble overlap across CTAs).
// ---------------------------------------------------------------------------
#define TILE_BYTES 8192
#define STAGE_BYTES 16384

template <typename OutT>
__global__ __launch_bounds__(256, 2)
void mma_gemm_kernel(const __half* __restrict__ A,
                     const __half* __restrict__ B,
                     const float* __restrict__ bias,
                     OutT* __restrict__ Cout,
                     int M, int N, int K) {
    extern __shared__ char smem[];
    const uint32_t sbase = smem_u32(smem);
    const int tid  = threadIdx.x;
    const int lane = tid & 31;
    const int wid  = tid >> 5;
    const int wm   = wid & 1;
    const int wn   = wid >> 1;
    const int crow = blockIdx.y * 128;
    const int ccol = blockIdx.x * 128;

    const __half* gsrc[2];
    gsrc[0] = A + (size_t)crow * K;
    gsrc[1] = B + (size_t)ccol * K;

    const int lc  = tid & 3;
    const int lr0 = tid >> 2;
    const int lr1 = lr0 + 64;
    const uint32_t sw0 = (uint32_t)((lc ^ ((lr0 >> 1) & 3)) << 4);
    const uint32_t sw1 = (uint32_t)((lc ^ ((lr1 >> 1) & 3)) << 4);

    float acc[4][4][4];
#pragma unroll
    for (int mt = 0; mt < 4; ++mt)
#pragma unroll
        for (int nt = 0; nt < 4; ++nt)
#pragma unroll
            for (int j = 0; j < 4; ++j) acc[mt][nt][j] = 0.0f;

    const int nch = K / 32;

    auto load_stage = [&](int stage, int k0) {
        const uint32_t sb = sbase + (uint32_t)stage * STAGE_BYTES;
#pragma unroll
        for (int t = 0; t < 2; ++t) {
            const __half* g = gsrc[t];
            cp_async16(sb + t * TILE_BYTES + lr0 * 64 + sw0,
                       g + (size_t)lr0 * K + k0 + lc * 8);
            cp_async16(sb + t * TILE_BYTES + lr1 * 64 + sw1,
                       g + (size_t)lr1 * K + k0 + lc * 8);
        }
        cp_commit();
    };

    load_stage(0, 0);
    load_stage(1, 32);

    const int a_lrow   = (lane & 7) + ((lane >> 3) & 1) * 8;
    const int a_lchunk = lane >> 4;
    const int b_lrow   = lane & 7;
    const int b_lchunk = (lane >> 3) & 1;

    for (int ch = 0; ch < nch; ++ch) {
        if (ch + 2 <= nch) {
            asm volatile("cp.async.wait_group 1;");
        } else {
            asm volatile("cp.async.wait_group 0;");
        }
        __syncthreads();
        if (ch + 2 < nch) load_stage((ch + 2) % 3, (ch + 2) * 32);

        const uint32_t sb = sbase + (uint32_t)(ch % 3) * STAGE_BYTES;

#pragma unroll
        for (int ks = 0; ks < 2; ++ks) {
            uint32_t af[4][4], bf[4][2];
#pragma unroll
            for (int mt = 0; mt < 4; ++mt) {
                const int row = wm * 64 + mt * 16 + a_lrow;
                const int chn = 2 * ks + a_lchunk;
                const uint32_t addr = sb + (uint32_t)(row * 64)
                                    + (uint32_t)((chn ^ ((row >> 1) & 3)) << 4);
                ldmatrix_x4(af[mt], addr);
            }
#pragma unroll
            for (int nt = 0; nt < 4; ++nt) {
                const int row = wn * 32 + nt * 8 + b_lrow;
                const int chn = 2 * ks + b_lchunk;
                const uint32_t addr = sb + TILE_BYTES + (uint32_t)(row * 64)
                                    + (uint32_t)((chn ^ ((row >> 1) & 3)) << 4);
                ldmatrix_x2(bf[nt], addr);
            }
#pragma unroll
            for (int mt = 0; mt < 4; ++mt)
#pragma unroll
                for (int nt = 0; nt < 4; ++nt)
                    mma_f16(acc[mt][nt], af[mt], bf[nt]);
        }
    }

    const int erow = lane >> 2;
    const int ecol = (lane & 3) * 2;
#pragma unroll
    for (int mt = 0; mt < 4; ++mt) {
#pragma unroll
        for (int nt = 0; nt < 4; ++nt) {
            const int col = ccol + wn * 32 + nt * 8 + ecol;
            const float b0 = bias[col], b1 = bias[col + 1];
            const int r0 = crow + wm * 64 + mt * 16 + erow;
            if constexpr (sizeof(OutT) == 4) {
                float2* p0 = reinterpret_cast<float2*>((float*)Cout + (size_t)r0 * N + col);
                *p0 = make_float2(acc[mt][nt][0] + b0, acc[mt][nt][1] + b1);
                float2* p1 = reinterpret_cast<float2*>((float*)Cout + (size_t)(r0 + 8) * N + col);
                *p1 = make_float2(acc[mt][nt][2] + b0, acc[mt][nt][3] + b1);
            } else {
                *reinterpret_cast<uint32_t*>((__half*)Cout + (size_t)r0 * N + col) =
                    pack_f16(acc[mt][nt][0] + b0, acc[mt][nt][1] + b1);
                *reinterpret_cast<uint32_t*>((__half*)Cout + (size_t)(r0 + 8) * N + col) =
                    pack_f16(acc[mt][nt][2] + b0, acc[mt][nt][3] + b1);
            }
        }
    }
}

// ---------------------------------------------------------------------------
// qk_prep: fused RoPE + scale (q) -> Q, K single fp16 [bh][n][104]
// ---------------------------------------------------------------------------
__global__ void qk_prep_kernel(const int* __restrict__ coords,
                               const __half* __restrict__ qkv,
                               __half* __restrict__ Qh,
                               __half* __restrict__ Kh) {
    const int token = blockIdx.x;
    const int tid = threadIdx.x;   // 128
    __shared__ float cs[DD], sn[DD];

    const int c0 = coords[token * 3 + 0];
    const int c1 = coords[token * 3 + 1];
    const int c2 = coords[token * 3 + 2];
    if (tid < DD) {
        const int j = tid;
        int jj, dd, coord;
        if (j < 34)      { const int u = j;      jj = (u < 17) ? u : u - 17; dd = 34; coord = c0; }
        else if (j < 68) { const int u = j - 34; jj = (u < 17) ? u : u - 17; dd = 34; coord = c1; }
        else             { const int u = j - 68; jj = (u < 18) ? u : u - 18; dd = 36; coord = c2; }
        const float inv = powf(10000.0f, -(2.0f * (float)jj) / (float)dd);
        const float ang = (float)coord * inv;
        cs[j] = cosf(ang);
        sn[j] = sinf(ang);
    }
    __syncthreads();

    if (tid >= DD) return;
    const int b = token >> 11, n = token & (NN - 1);
    const float scale = rsqrtf((float)DD);
    const __half* base = qkv + (size_t)token * C3;
    const int j = tid;

    for (int h = 0; h < HH; ++h) {
        const size_t o = ((size_t)(b * HH + h) * NN + n) * DD + j;
        const float qa = __half2float(base[h * DD + j]);
        const float qrot = (j < 52) ? -__half2float(base[h * DD + j + 52])
                                    :  __half2float(base[h * DD + j - 52]);
        Qh[o] = __float2half_rn((qa * cs[j] + qrot * sn[j]) * scale);

        const float ka = __half2float(base[CC + h * DD + j]);
        const float krot = (j < 52) ? -__half2float(base[CC + h * DD + j + 52])
                                    :  __half2float(base[CC + h * DD + j - 52]);
        Kh[o] = __float2half_rn(ka * cs[j] + krot * sn[j]);
    }
}

// ---------------------------------------------------------------------------
// vt_prep: V [token][h][d] fp16 -> Vt [bh][d][n] fp16 (transpose)
// ---------------------------------------------------------------------------
__global__ void vt_prep_kernel(const __half* __restrict__ qkv,
                               __half* __restrict__ Vth) {
    __shared__ float t[32][33];
    const int bh = blockIdx.z;
    const int b = bh >> 4, h = bh & 15;
    const int n0 = blockIdx.x * 32;
    const int d0 = blockIdx.y * 32;
    const int tx = threadIdx.x, ty = threadIdx.y;
#pragma unroll
    for (int j = 0; j < 4; ++j) {
        const int d = d0 + tx, n = n0 + ty + 8 * j;
        if (d < DD)
            t[ty + 8 * j][tx] = __half2float(qkv[(size_t)(b * NN + n) * C3 + 2 * CC + h * DD + d]);
    }
    __syncthreads();
#pragma unroll
    for (int j = 0; j < 4; ++j) {
        const int d = d0 + ty + 8 * j, n = n0 + tx;
        if (d < DD)
            Vth[((size_t)bh * DD + d) * NN + n] = __float2half_rn(t[tx][ty + 8 * j]);
    }
}

// ---------------------------------------------------------------------------
// Flash attention, single fp16: S = Q*K, O += P*V. 6 k16 + 1 k8 steps.
// 3-stage cp.async pipeline. Epilogue writes single-fp16 proj input.
// ---------------------------------------------------------------------------
#define AT_V  16384
#define AT_STAGE 29696

__global__ __launch_bounds__(256, 1)
void attn_mma_kernel(const __half* __restrict__ Qh,
                     const __half* __restrict__ Kh,
                     const __half* __restrict__ Vth,
                     __half* __restrict__ Oh) {
    extern __shared__ char smem[];
    const uint32_t sb = smem_u32(smem);
    const int tid = threadIdx.x, lane = tid & 31, wid = tid >> 5;
    const int qt = blockIdx.x, h = blockIdx.y, b = blockIdx.z;
    const int bh = b * HH + h;

    const __half* qh_p = Qh + ((size_t)bh * NN + qt * 128) * DD;
    const __half* kh_p = Kh + (size_t)bh * NN * DD;
    const __half* vh_p = Vth + (size_t)bh * DD * NN;

    // ---- stage Q (13 chunks of 8 halves per 256B smem row), extract a-frags ----
    for (int i = tid; i < 128 * 13; i += 256) {
        const int row = i / 13, c = i % 13;
        const uint32_t off = row * 256 + ((c ^ (row & 7)) << 4);
        cp_async16(sb + off, qh_p + (size_t)row * DD + c * 8);
    }
    cp_commit();
    asm volatile("cp.async.wait_group 0;");
    __syncthreads();

    uint32_t qah[6][4], qa8[2];
    {
        const int arow = wid * 16 + (lane & 7) + ((lane >> 3) & 1) * 8;
#pragma unroll
        for (int j = 0; j < 6; ++j) {
            const int chn = 2 * j + (lane >> 4);
            ldmatrix_x4(qah[j], sb + arow * 256 + ((chn ^ (arow & 7)) << 4));
        }
        ldmatrix_x2(qa8, sb + arow * 256 + ((12 ^ (arow & 7)) << 4));
    }
    __syncthreads();

    float oc[13][4];
#pragma unroll
    for (int i = 0; i < 13; ++i) { oc[i][0] = oc[i][1] = oc[i][2] = oc[i][3] = 0.0f; }
    float m0 = -1e30f, m1 = -1e30f, l0 = 0.0f, l1 = 0.0f;

    auto load_stage = [&](int s, int kt) {
        const uint32_t st = sb + (uint32_t)s * AT_STAGE;
        const __half* kh_t = kh_p + (size_t)kt * 64 * DD;
        for (int i = tid; i < 64 * 13; i += 256) {
            const int row = i / 13, c = i % 13;
            const uint32_t off = row * 256 + ((c ^ (row & 7)) << 4);
            cp_async16(st + off, kh_t + (size_t)row * DD + c * 8);
        }
        const __half* vh_t = vh_p + kt * 64;
        for (int i = tid; i < 832; i += 256) {
            const int row = i >> 3, c = i & 7;
            const uint32_t off = row * 128 + ((c ^ (row & 7)) << 4);
            cp_async16(st + AT_V + off, vh_t + (size_t)row * NN + c * 8);
        }
        cp_commit();
    };

    const int nkt = NN / 64;
    load_stage(0, 0);
    load_stage(1, 1);

    for (int kt = 0; kt < nkt; ++kt) {
        if (kt + 2 <= nkt) {
            asm volatile("cp.async.wait_group 1;");
        } else {
            asm volatile("cp.async.wait_group 0;");
        }
        __syncthreads();
        if (kt + 2 < nkt) load_stage((kt + 2) % 3, kt + 2);

        const uint32_t st = sb + (uint32_t)(kt % 3) * AT_STAGE;

        // ---- S = Q K, fp16 single-term ----
        float sc[8][4];
#pragma unroll
        for (int nt = 0; nt < 8; ++nt) { sc[nt][0] = sc[nt][1] = sc[nt][2] = sc[nt][3] = 0.0f; }

#pragma unroll
        for (int jp = 0; jp < 3; ++jp) {
#pragma unroll
            for (int nt = 0; nt < 8; ++nt) {
                const int brow = nt * 8 + (lane & 7);
                const int bchn = 4 * jp + (lane >> 3);
                const uint32_t addr = st + brow * 256 + ((bchn ^ (brow & 7)) << 4);
                uint32_t bh4[4];
                ldmatrix_x4(bh4, addr);
                mma_f16(sc[nt], qah[2 * jp], &bh4[0]);
                mma_f16(sc[nt], qah[2 * jp + 1], &bh4[2]);
            }
        }
#pragma unroll
        for (int nt = 0; nt < 8; ++nt) {   // k8 step: dims 96..103 (chunk 12)
            const int brow = nt * 8 + (lane & 7);
            const uint32_t addr = st + brow * 256 + ((12 ^ (brow & 7)) << 4);
            uint32_t bh1;
            ldmatrix_x1(bh1, addr);
            mma_f16_k8(sc[nt], qa8, bh1);
        }

        // ---- online softmax ----
        float mx0 = m0, mx1 = m1;
#pragma unroll
        for (int nt = 0; nt < 8; ++nt) {
            mx0 = fmaxf(mx0, fmaxf(sc[nt][0], sc[nt][1]));
            mx1 = fmaxf(mx1, fmaxf(sc[nt][2], sc[nt][3]));
        }
        mx0 = fmaxf(mx0, __shfl_xor_sync(0xffffffffu, mx0, 1));
        mx0 = fmaxf(mx0, __shfl_xor_sync(0xffffffffu, mx0, 2));
        mx1 = fmaxf(mx1, __shfl_xor_sync(0xffffffffu, mx1, 1));
        mx1 = fmaxf(mx1, __shfl_xor_sync(0xffffffffu, mx1, 2));
        const float a0 = __expf(m0 - mx0), a1 = __expf(m1 - mx1);
        m0 = mx0; m1 = mx1;
        l0 *= a0; l1 *= a1;
#pragma unroll
        for (int i = 0; i < 13; ++i) {
            oc[i][0] *= a0; oc[i][1] *= a0; oc[i][2] *= a1; oc[i][3] *= a1;
        }

        uint32_t pah[4][4];
#pragma unroll
        for (int jp = 0; jp < 4; ++jp) {
            const float p00 = __expf(sc[2 * jp][0] - mx0);
            const float p01 = __expf(sc[2 * jp][1] - mx0);
            const float p02 = __expf(sc[2 * jp][2] - mx1);
            const float p03 = __expf(sc[2 * jp][3] - mx1);
            const float p10 = __expf(sc[2 * jp + 1][0] - mx0);
            const float p11 = __expf(sc[2 * jp + 1][1] - mx0);
            const float p12 = __expf(sc[2 * jp + 1][2] - mx1);
            const float p13 = __expf(sc[2 * jp + 1][3] - mx1);
            l0 += p00 + p01 + p10 + p11;
            l1 += p02 + p03 + p12 + p13;
            pah[jp][0] = pack_f16(p00, p01);
            pah[jp][1] = pack_f16(p02, p03);
            pah[jp][2] = pack_f16(p10, p11);
            pah[jp][3] = pack_f16(p12, p13);
        }

        // ---- O += P V (fp16 single-term) ----
#pragma unroll
        for (int jph = 0; jph < 2; ++jph) {
#pragma unroll
            for (int ntd = 0; ntd < 13; ++ntd) {
                const int vrow = ntd * 8 + (lane & 7);
                const int vchn = 4 * jph + (lane >> 3);
                const uint32_t addr = st + AT_V + vrow * 128 + ((vchn ^ (vrow & 7)) << 4);
                uint32_t vh4[4];
                ldmatrix_x4(vh4, addr);
                mma_f16(oc[ntd], pah[2 * jph], &vh4[0]);
                mma_f16(oc[ntd], pah[2 * jph + 1], &vh4[2]);
            }
        }
    }

    // ---- epilogue: normalize, write single-fp16 proj input ----
    l0 += __shfl_xor_sync(0xffffffffu, l0, 1);
    l0 += __shfl_xor_sync(0xffffffffu, l0, 2);
    l1 += __shfl_xor_sync(0xffffffffu, l1, 1);
    l1 += __shfl_xor_sync(0xffffffffu, l1, 2);
    const float inv0 = 1.0f / l0, inv1 = 1.0f / l1;
    const int row0 = qt * 128 + wid * 16 + (lane >> 2);
    const size_t tok0 = (size_t)b * NN + row0;
    const int colbase = h * DD + 2 * (lane & 3);
#pragma unroll
    for (int ntd = 0; ntd < 13; ++ntd) {
        const int col = colbase + ntd * 8;
        *reinterpret_cast<uint32_t*>(Oh + tok0 * CC + col) =
            pack_f16(oc[ntd][0] * inv0, oc[ntd][1] * inv0);
        *reinterpret_cast<uint32_t*>(Oh + (tok0 + 8) * CC + col) =
            pack_f16(oc[ntd][2] * inv1, oc[ntd][3] * inv1);
    }
}

// ---------------------------------------------------------------------------
// Launch
// ---------------------------------------------------------------------------
extern "C" void kernel_launch(void* const* d_in, const int* in_sizes, int n_in,
                              void* d_out, int out_size) {
    const float* x = nullptr;
    const int*   coords = nullptr;
    const float* qkv_w = nullptr;
    const float* qkv_b = nullptr;
    const float* proj_w = nullptr;
    const float* proj_b = nullptr;
    for (int i = 0; i < n_in; ++i) {
        switch (in_sizes[i]) {
            case TOKENS * CC:      x      = (const float*)d_in[i]; break;
            case TOKENS * 3:       coords = (const int*)d_in[i];   break;
            case CC * C3:          qkv_w  = (const float*)d_in[i]; break;
            case C3:               qkv_b  = (const float*)d_in[i]; break;
            case CC * CC:          proj_w = (const float*)d_in[i]; break;
            case CC:               proj_b = (const float*)d_in[i]; break;
            default: break;
        }
    }
    float* out = (float*)d_out;

    __half *qkv, *xh, *ah, *wq, *wp, *qh, *kh, *vth;
    cudaGetSymbolAddress((void**)&qkv, g_qkv);
    cudaGetSymbolAddress((void**)&xh,  g_xh);
    cudaGetSymbolAddress((void**)&ah,  g_ah);
    cudaGetSymbolAddress((void**)&wq,  g_wq);
    cudaGetSymbolAddress((void**)&wp,  g_wp);
    cudaGetSymbolAddress((void**)&qh,  g_qh);
    cudaGetSymbolAddress((void**)&kh,  g_kh);
    cudaGetSymbolAddress((void**)&vth, g_vth);

    const int gemm_smem = 3 * STAGE_BYTES;   // 49152 (x2 CTAs/SM = 96 KB)
    cudaFuncSetAttribute(mma_gemm_kernel<__half>, cudaFuncAttributeMaxDynamicSharedMemorySize, gemm_smem);
    cudaFuncSetAttribute(mma_gemm_kernel<float>,  cudaFuncAttributeMaxDynamicSharedMemorySize, gemm_smem);
    const int attn_smem = 3 * AT_STAGE;      // 89088
    cudaFuncSetAttribute(attn_mma_kernel, cudaFuncAttributeMaxDynamicSharedMemorySize, attn_smem);

    // 1) convert x -> single fp16
    convert_f16_kernel<<<4096, 256>>>(x, xh, TOKENS * CC);

    // 2) transpose qkv_w -> single fp16
    {
        dim3 grid(C3 / 32, CC / 32);
        transpose_f16_kernel<<<grid, dim3(32, 8)>>>(qkv_w, wq, CC, C3);
    }

    // 3) transpose proj_w -> single fp16 (moved early so GEMM is launch #4 for ncu)
    {
        dim3 grid(CC / 32, CC / 32);
        transpose_f16_kernel<<<grid, dim3(32, 8)>>>(proj_w, wp, CC, CC);
    }

    // 4) QKV GEMM (fp16, writes fp16 intermediate)
    {
        dim3 grid(C3 / 128, TOKENS / 128);
        mma_gemm_kernel<__half><<<grid, 256, gemm_smem>>>(xh, wq, qkv_b, qkv,
                                                          TOKENS, C3, CC);
    }

    // 5) RoPE + scale -> Q, K fp16; 6) transpose V -> fp16
    qk_prep_kernel<<<TOKENS, 128>>>(coords, qkv, qh, kh);
    {
        dim3 grid(NN / 32, (DD + 31) / 32, BB * HH);
        vt_prep_kernel<<<grid, dim3(32, 8)>>>(qkv, vth);
    }

    // 7) Flash attention -> writes proj input (ah, single fp16)
    {
        dim3 grid(NN / 128, HH, BB);
        attn_mma_kernel<<<grid, 256, attn_smem>>>(qh, kh, vth, ah);
    }

    // 8) Projection GEMM (fp16, writes fp32 output)
    {
        dim3 grid(CC / 128, TOKENS / 128);
        mma_gemm_kernel<float><<<grid, 256, gemm_smem>>>(ah, wp, proj_b, out,
                                                         TOKENS, CC, CC);
    }
}

// round 13
// speedup vs baseline: 2.3144x; 1.0148x over previous
#include <cuda_runtime.h>
#include <cuda_bf16.h>
#include <cuda_fp16.h>
#include <math.h>
#include <stdint.h>

// Problem constants
#define BB 2
#define NN 2048
#define CC 1664
#define HH 16
#define DD 104
#define C3 (3 * CC)          // 4992
#define TOKENS (BB * NN)     // 4096

// ---------------------------------------------------------------------------
// Scratch (no allocations allowed)
// ---------------------------------------------------------------------------
__device__ __align__(256) __half g_qkv[(size_t)TOKENS * C3];   // fp16 qkv intermediate
__device__ __align__(256) __half g_xh[(size_t)TOKENS * CC];
__device__ __align__(256) __half g_ah[(size_t)TOKENS * CC];
__device__ __align__(256) __half g_wq[(size_t)C3 * CC];        // qkv_w^T [4992][1664]
__device__ __align__(256) __half g_wp[(size_t)CC * CC];        // proj_w^T [1664][1664]
__device__ __align__(256) __half g_qh[(size_t)BB * HH * NN * DD];
__device__ __align__(256) __half g_kh[(size_t)BB * HH * NN * DD];
__device__ __align__(256) __half g_vth[(size_t)BB * HH * DD * NN];

// ---------------------------------------------------------------------------
// Helpers
// ---------------------------------------------------------------------------
__device__ __forceinline__ uint32_t smem_u32(const void* p) {
    uint32_t a;
    asm("{ .reg .u64 t; cvta.to.shared.u64 t, %1; cvt.u32.u64 %0, t; }" : "=r"(a) : "l"(p));
    return a;
}
__device__ __forceinline__ void cp_async16(uint32_t dst, const void* src) {
    asm volatile("cp.async.cg.shared.global [%0], [%1], 16;" :: "r"(dst), "l"(src));
}
__device__ __forceinline__ void cp_commit() {
    asm volatile("cp.async.commit_group;");
}
__device__ __forceinline__ void ldmatrix_x4(uint32_t* r, uint32_t addr) {
    asm volatile("ldmatrix.sync.aligned.m8n8.x4.shared.b16 {%0,%1,%2,%3}, [%4];"
                 : "=r"(r[0]), "=r"(r[1]), "=r"(r[2]), "=r"(r[3]) : "r"(addr));
}
__device__ __forceinline__ void ldmatrix_x2(uint32_t* r, uint32_t addr) {
    asm volatile("ldmatrix.sync.aligned.m8n8.x2.shared.b16 {%0,%1}, [%2];"
                 : "=r"(r[0]), "=r"(r[1]) : "r"(addr));
}
__device__ __forceinline__ void ldmatrix_x1(uint32_t& r, uint32_t addr) {
    asm volatile("ldmatrix.sync.aligned.m8n8.x1.shared.b16 {%0}, [%1];"
                 : "=r"(r) : "r"(addr));
}
__device__ __forceinline__ void mma_f16(float* c, const uint32_t* a, const uint32_t* b) {
    asm volatile("mma.sync.aligned.m16n8k16.row.col.f32.f16.f16.f32 "
                 "{%0,%1,%2,%3}, {%4,%5,%6,%7}, {%8,%9}, {%0,%1,%2,%3};"
                 : "+f"(c[0]), "+f"(c[1]), "+f"(c[2]), "+f"(c[3])
                 : "r"(a[0]), "r"(a[1]), "r"(a[2]), "r"(a[3]), "r"(b[0]), "r"(b[1]));
}
__device__ __forceinline__ void mma_f16_k8(float* c, const uint32_t* a, uint32_t b) {
    asm volatile("mma.sync.aligned.m16n8k8.row.col.f32.f16.f16.f32 "
                 "{%0,%1,%2,%3}, {%4,%5}, {%6}, {%0,%1,%2,%3};"
                 : "+f"(c[0]), "+f"(c[1]), "+f"(c[2]), "+f"(c[3])
                 : "r"(a[0]), "r"(a[1]), "r"(b));
}
__device__ __forceinline__ uint32_t pack_f16(float a, float b) {
    __half2 h = __floats2half2_rn(a, b);
    return *reinterpret_cast<uint32_t*>(&h);
}

// ---------------------------------------------------------------------------
// fp32 -> single fp16 convert
// ---------------------------------------------------------------------------
__global__ void convert_f16_kernel(const float* __restrict__ src,
                                   __half* __restrict__ dst, int n) {
    for (int i = blockIdx.x * blockDim.x + threadIdx.x; i < n; i += gridDim.x * blockDim.x)
        dst[i] = __float2half_rn(src[i]);
}

// ---------------------------------------------------------------------------
// W[Kr][Nc] row-major  ->  T[Nc][Kr] single fp16
// ---------------------------------------------------------------------------
__global__ void transpose_f16_kernel(const float* __restrict__ W,
                                     __half* __restrict__ T,
                                     int Kr, int Nc) {
    __shared__ float t[32][33];
    const int x = blockIdx.x * 32 + threadIdx.x;
    const int y0 = blockIdx.y * 32;
    for (int j = threadIdx.y; j < 32; j += 8)
        t[j][threadIdx.x] = W[(size_t)(y0 + j) * Nc + x];
    __syncthreads();
    const int ox = y0 + threadIdx.x;
    const int oy0 = blockIdx.x * 32;
    for (int j = threadIdx.y; j < 32; j += 8)
        T[(size_t)(oy0 + j) * Kr + ox] = __float2half_rn(t[threadIdx.x][j]);
}

// ---------------------------------------------------------------------------
// mma.sync GEMM, single fp16: C = A[M,K] @ B[N,K]^T + bias[N], fp32 accum.
// BK=64 (128B rows, swizzle c^(row&7)), 3-stage cp.async, 2 CTAs/SM.
// MT = m-tiles per warp (4 -> BM=128, 2 -> BM=64). BN=128.
// ---------------------------------------------------------------------------
template <typename OutT, int MT>
__global__ __launch_bounds__(256, 2)
void mma_gemm_kernel(const __half* __restrict__ A,
                     const __half* __restrict__ B,
                     const float* __restrict__ bias,
                     OutT* __restrict__ Cout,
                     int M, int N, int K) {
    constexpr int BM = MT * 32;                 // 128 or 64
    constexpr int A_TILE = BM * 128;            // bytes
    constexpr int B_TILE = 128 * 128;
    constexpr int STG = A_TILE + B_TILE;

    extern __shared__ char smem[];
    const uint32_t sbase = smem_u32(smem);
    const int tid  = threadIdx.x;
    const int lane = tid & 31;
    const int wid  = tid >> 5;
    const int wm   = wid & 1;        // m half
    const int wn   = wid >> 1;       // 0..3, 32 cols each
    const int crow = blockIdx.y * BM;
    const int ccol = blockIdx.x * 128;

    const __half* Abase = A + (size_t)crow * K;
    const __half* Bbase = B + (size_t)ccol * K;

    const int lc = tid & 7;          // chunk 0..7
    const int lr = tid >> 3;         // 0..31

    float acc[MT][4][4];
#pragma unroll
    for (int mt = 0; mt < MT; ++mt)
#pragma unroll
        for (int nt = 0; nt < 4; ++nt)
#pragma unroll
            for (int j = 0; j < 4; ++j) acc[mt][nt][j] = 0.0f;

    const int nch = K / 64;

    auto load_stage = [&](int stage, int k0) {
        const uint32_t sb = sbase + (uint32_t)stage * STG;
#pragma unroll
        for (int rr = 0; rr < BM / 32; ++rr) {
            const int row = lr + rr * 32;
            const uint32_t sw = (uint32_t)((lc ^ (row & 7)) << 4);
            cp_async16(sb + row * 128 + sw, Abase + (size_t)row * K + k0 + lc * 8);
        }
#pragma unroll
        for (int rr = 0; rr < 4; ++rr) {
            const int row = lr + rr * 32;
            const uint32_t sw = (uint32_t)((lc ^ (row & 7)) << 4);
            cp_async16(sb + A_TILE + row * 128 + sw, Bbase + (size_t)row * K + k0 + lc * 8);
        }
        cp_commit();
    };

    load_stage(0, 0);
    load_stage(1, 64);

    const int a_lrow   = (lane & 7) + ((lane >> 3) & 1) * 8;
    const int a_lchunk = lane >> 4;
    const int b_lrow   = lane & 7;
    const int b_lchunk = (lane >> 3) & 1;

    for (int ch = 0; ch < nch; ++ch) {
        if (ch + 2 <= nch) {
            asm volatile("cp.async.wait_group 1;");
        } else {
            asm volatile("cp.async.wait_group 0;");
        }
        __syncthreads();
        if (ch + 2 < nch) load_stage((ch + 2) % 3, (ch + 2) * 64);

        const uint32_t sb = sbase + (uint32_t)(ch % 3) * STG;

#pragma unroll
        for (int ks = 0; ks < 4; ++ks) {
            uint32_t af[MT][4], bf[4][2];
#pragma unroll
            for (int mt = 0; mt < MT; ++mt) {
                const int row = wm * (MT * 16) + mt * 16 + a_lrow;
                const int chn = 2 * ks + a_lchunk;
                const uint32_t addr = sb + (uint32_t)(row * 128)
                                    + (uint32_t)((chn ^ (row & 7)) << 4);
                ldmatrix_x4(af[mt], addr);
            }
#pragma unroll
            for (int nt = 0; nt < 4; ++nt) {
                const int row = wn * 32 + nt * 8 + b_lrow;
                const int chn = 2 * ks + b_lchunk;
                const uint32_t addr = sb + A_TILE + (uint32_t)(row * 128)
                                    + (uint32_t)((chn ^ (row & 7)) << 4);
                ldmatrix_x2(bf[nt], addr);
            }
#pragma unroll
            for (int mt = 0; mt < MT; ++mt)
#pragma unroll
                for (int nt = 0; nt < 4; ++nt)
                    mma_f16(acc[mt][nt], af[mt], bf[nt]);
        }
    }

    const int erow = lane >> 2;
    const int ecol = (lane & 3) * 2;
#pragma unroll
    for (int mt = 0; mt < MT; ++mt) {
#pragma unroll
        for (int nt = 0; nt < 4; ++nt) {
            const int col = ccol + wn * 32 + nt * 8 + ecol;
            const float b0 = bias[col], b1 = bias[col + 1];
            const int r0 = crow + wm * (MT * 16) + mt * 16 + erow;
            if constexpr (sizeof(OutT) == 4) {
                float2* p0 = reinterpret_cast<float2*>((float*)Cout + (size_t)r0 * N + col);
                *p0 = make_float2(acc[mt][nt][0] + b0, acc[mt][nt][1] + b1);
                float2* p1 = reinterpret_cast<float2*>((float*)Cout + (size_t)(r0 + 8) * N + col);
                *p1 = make_float2(acc[mt][nt][2] + b0, acc[mt][nt][3] + b1);
            } else {
                *reinterpret_cast<uint32_t*>((__half*)Cout + (size_t)r0 * N + col) =
                    pack_f16(acc[mt][nt][0] + b0, acc[mt][nt][1] + b1);
                *reinterpret_cast<uint32_t*>((__half*)Cout + (size_t)(r0 + 8) * N + col) =
                    pack_f16(acc[mt][nt][2] + b0, acc[mt][nt][3] + b1);
            }
        }
    }
}

// ---------------------------------------------------------------------------
// qk_prep: fused RoPE + scale (q) -> Q, K single fp16 [bh][n][104]
// ---------------------------------------------------------------------------
__global__ void qk_prep_kernel(const int* __restrict__ coords,
                               const __half* __restrict__ qkv,
                               __half* __restrict__ Qh,
                               __half* __restrict__ Kh) {
    const int token = blockIdx.x;
    const int tid = threadIdx.x;   // 128
    __shared__ float cs[DD], sn[DD];

    const int c0 = coords[token * 3 + 0];
    const int c1 = coords[token * 3 + 1];
    const int c2 = coords[token * 3 + 2];
    if (tid < DD) {
        const int j = tid;
        int jj, dd, coord;
        if (j < 34)      { const int u = j;      jj = (u < 17) ? u : u - 17; dd = 34; coord = c0; }
        else if (j < 68) { const int u = j - 34; jj = (u < 17) ? u : u - 17; dd = 34; coord = c1; }
        else             { const int u = j - 68; jj = (u < 18) ? u : u - 18; dd = 36; coord = c2; }
        const float inv = powf(10000.0f, -(2.0f * (float)jj) / (float)dd);
        const float ang = (float)coord * inv;
        cs[j] = cosf(ang);
        sn[j] = sinf(ang);
    }
    __syncthreads();

    if (tid >= DD) return;
    const int b = token >> 11, n = token & (NN - 1);
    const float scale = rsqrtf((float)DD);
    const __half* base = qkv + (size_t)token * C3;
    const int j = tid;

    for (int h = 0; h < HH; ++h) {
        const size_t o = ((size_t)(b * HH + h) * NN + n) * DD + j;
        const float qa = __half2float(base[h * DD + j]);
        const float qrot = (j < 52) ? -__half2float(base[h * DD + j + 52])
                                    :  __half2float(base[h * DD + j - 52]);
        Qh[o] = __float2half_rn((qa * cs[j] + qrot * sn[j]) * scale);

        const float ka = __half2float(base[CC + h * DD + j]);
        const float krot = (j < 52) ? -__half2float(base[CC + h * DD + j + 52])
                                    :  __half2float(base[CC + h * DD + j - 52]);
        Kh[o] = __float2half_rn(ka * cs[j] + krot * sn[j]);
    }
}

// ---------------------------------------------------------------------------
// vt_prep: V [token][h][d] fp16 -> Vt [bh][d][n] fp16 (transpose)
// ---------------------------------------------------------------------------
__global__ void vt_prep_kernel(const __half* __restrict__ qkv,
                               __half* __restrict__ Vth) {
    __shared__ float t[32][33];
    const int bh = blockIdx.z;
    const int b = bh >> 4, h = bh & 15;
    const int n0 = blockIdx.x * 32;
    const int d0 = blockIdx.y * 32;
    const int tx = threadIdx.x, ty = threadIdx.y;
#pragma unroll
    for (int j = 0; j < 4; ++j) {
        const int d = d0 + tx, n = n0 + ty + 8 * j;
        if (d < DD)
            t[ty + 8 * j][tx] = __half2float(qkv[(size_t)(b * NN + n) * C3 + 2 * CC + h * DD + d]);
    }
    __syncthreads();
#pragma unroll
    for (int j = 0; j < 4; ++j) {
        const int d = d0 + ty + 8 * j, n = n0 + tx;
        if (d < DD)
            Vth[((size_t)bh * DD + d) * NN + n] = __float2half_rn(t[tx][ty + 8 * j]);
    }
}

// ---------------------------------------------------------------------------
// Flash attention, single fp16: S = Q*K, O += P*V. 6 k16 + 1 k8 steps.
// 3-stage cp.async pipeline. Epilogue writes single-fp16 proj input.
// ---------------------------------------------------------------------------
#define AT_V  16384
#define AT_STAGE 29696

__global__ __launch_bounds__(256, 1)
void attn_mma_kernel(const __half* __restrict__ Qh,
                     const __half* __restrict__ Kh,
                     const __half* __restrict__ Vth,
                     __half* __restrict__ Oh) {
    extern __shared__ char smem[];
    const uint32_t sb = smem_u32(smem);
    const int tid = threadIdx.x, lane = tid & 31, wid = tid >> 5;
    const int qt = blockIdx.x, h = blockIdx.y, b = blockIdx.z;
    const int bh = b * HH + h;

    const __half* qh_p = Qh + ((size_t)bh * NN + qt * 128) * DD;
    const __half* kh_p = Kh + (size_t)bh * NN * DD;
    const __half* vh_p = Vth + (size_t)bh * DD * NN;

    for (int i = tid; i < 128 * 13; i += 256) {
        const int row = i / 13, c = i % 13;
        const uint32_t off = row * 256 + ((c ^ (row & 7)) << 4);
        cp_async16(sb + off, qh_p + (size_t)row * DD + c * 8);
    }
    cp_commit();
    asm volatile("cp.async.wait_group 0;");
    __syncthreads();

    uint32_t qah[6][4], qa8[2];
    {
        const int arow = wid * 16 + (lane & 7) + ((lane >> 3) & 1) * 8;
#pragma unroll
        for (int j = 0; j < 6; ++j) {
            const int chn = 2 * j + (lane >> 4);
            ldmatrix_x4(qah[j], sb + arow * 256 + ((chn ^ (arow & 7)) << 4));
        }
        ldmatrix_x2(qa8, sb + arow * 256 + ((12 ^ (arow & 7)) << 4));
    }
    __syncthreads();

    float oc[13][4];
#pragma unroll
    for (int i = 0; i < 13; ++i) { oc[i][0] = oc[i][1] = oc[i][2] = oc[i][3] = 0.0f; }
    float m0 = -1e30f, m1 = -1e30f, l0 = 0.0f, l1 = 0.0f;

    auto load_stage = [&](int s, int kt) {
        const uint32_t st = sb + (uint32_t)s * AT_STAGE;
        const __half* kh_t = kh_p + (size_t)kt * 64 * DD;
        for (int i = tid; i < 64 * 13; i += 256) {
            const int row = i / 13, c = i % 13;
            const uint32_t off = row * 256 + ((c ^ (row & 7)) << 4);
            cp_async16(st + off, kh_t + (size_t)row * DD + c * 8);
        }
        const __half* vh_t = vh_p + kt * 64;
        for (int i = tid; i < 832; i += 256) {
            const int row = i >> 3, c = i & 7;
            const uint32_t off = row * 128 + ((c ^ (row & 7)) << 4);
            cp_async16(st + AT_V + off, vh_t + (size_t)row * NN + c * 8);
        }
        cp_commit();
    };

    const int nkt = NN / 64;
    load_stage(0, 0);
    load_stage(1, 1);

    for (int kt = 0; kt < nkt; ++kt) {
        if (kt + 2 <= nkt) {
            asm volatile("cp.async.wait_group 1;");
        } else {
            asm volatile("cp.async.wait_group 0;");
        }
        __syncthreads();
        if (kt + 2 < nkt) load_stage((kt + 2) % 3, kt + 2);

        const uint32_t st = sb + (uint32_t)(kt % 3) * AT_STAGE;

        float sc[8][4];
#pragma unroll
        for (int nt = 0; nt < 8; ++nt) { sc[nt][0] = sc[nt][1] = sc[nt][2] = sc[nt][3] = 0.0f; }

#pragma unroll
        for (int jp = 0; jp < 3; ++jp) {
#pragma unroll
            for (int nt = 0; nt < 8; ++nt) {
                const int brow = nt * 8 + (lane & 7);
                const int bchn = 4 * jp + (lane >> 3);
                const uint32_t addr = st + brow * 256 + ((bchn ^ (brow & 7)) << 4);
                uint32_t bh4[4];
                ldmatrix_x4(bh4, addr);
                mma_f16(sc[nt], qah[2 * jp], &bh4[0]);
                mma_f16(sc[nt], qah[2 * jp + 1], &bh4[2]);
            }
        }
#pragma unroll
        for (int nt = 0; nt < 8; ++nt) {
            const int brow = nt * 8 + (lane & 7);
            const uint32_t addr = st + brow * 256 + ((12 ^ (brow & 7)) << 4);
            uint32_t bh1;
            ldmatrix_x1(bh1, addr);
            mma_f16_k8(sc[nt], qa8, bh1);
        }

        float mx0 = m0, mx1 = m1;
#pragma unroll
        for (int nt = 0; nt < 8; ++nt) {
            mx0 = fmaxf(mx0, fmaxf(sc[nt][0], sc[nt][1]));
            mx1 = fmaxf(mx1, fmaxf(sc[nt][2], sc[nt][3]));
        }
        mx0 = fmaxf(mx0, __shfl_xor_sync(0xffffffffu, mx0, 1));
        mx0 = fmaxf(mx0, __shfl_xor_sync(0xffffffffu, mx0, 2));
        mx1 = fmaxf(mx1, __shfl_xor_sync(0xffffffffu, mx1, 1));
        mx1 = fmaxf(mx1, __shfl_xor_sync(0xffffffffu, mx1, 2));
        const float a0 = __expf(m0 - mx0), a1 = __expf(m1 - mx1);
        m0 = mx0; m1 = mx1;
        l0 *= a0; l1 *= a1;
#pragma unroll
        for (int i = 0; i < 13; ++i) {
            oc[i][0] *= a0; oc[i][1] *= a0; oc[i][2] *= a1; oc[i][3] *= a1;
        }

        uint32_t pah[4][4];
#pragma unroll
        for (int jp = 0; jp < 4; ++jp) {
            const float p00 = __expf(sc[2 * jp][0] - mx0);
            const float p01 = __expf(sc[2 * jp][1] - mx0);
            const float p02 = __expf(sc[2 * jp][2] - mx1);
            const float p03 = __expf(sc[2 * jp][3] - mx1);
            const float p10 = __expf(sc[2 * jp + 1][0] - mx0);
            const float p11 = __expf(sc[2 * jp + 1][1] - mx0);
            const float p12 = __expf(sc[2 * jp + 1][2] - mx1);
            const float p13 = __expf(sc[2 * jp + 1][3] - mx1);
            l0 += p00 + p01 + p10 + p11;
            l1 += p02 + p03 + p12 + p13;
            pah[jp][0] = pack_f16(p00, p01);
            pah[jp][1] = pack_f16(p02, p03);
            pah[jp][2] = pack_f16(p10, p11);
            pah[jp][3] = pack_f16(p12, p13);
        }

#pragma unroll
        for (int jph = 0; jph < 2; ++jph) {
#pragma unroll
            for (int ntd = 0; ntd < 13; ++ntd) {
                const int vrow = ntd * 8 + (lane & 7);
                const int vchn = 4 * jph + (lane >> 3);
                const uint32_t addr = st + AT_V + vrow * 128 + ((vchn ^ (vrow & 7)) << 4);
                uint32_t vh4[4];
                ldmatrix_x4(vh4, addr);
                mma_f16(oc[ntd], pah[2 * jph], &vh4[0]);
                mma_f16(oc[ntd], pah[2 * jph + 1], &vh4[2]);
            }
        }
    }

    l0 += __shfl_xor_sync(0xffffffffu, l0, 1);
    l0 += __shfl_xor_sync(0xffffffffu, l0, 2);
    l1 += __shfl_xor_sync(0xffffffffu, l1, 1);
    l1 += __shfl_xor_sync(0xffffffffu, l1, 2);
    const float inv0 = 1.0f / l0, inv1 = 1.0f / l1;
    const int row0 = qt * 128 + wid * 16 + (lane >> 2);
    const size_t tok0 = (size_t)b * NN + row0;
    const int colbase = h * DD + 2 * (lane & 3);
#pragma unroll
    for (int ntd = 0; ntd < 13; ++ntd) {
        const int col = colbase + ntd * 8;
        *reinterpret_cast<uint32_t*>(Oh + tok0 * CC + col) =
            pack_f16(oc[ntd][0] * inv0, oc[ntd][1] * inv0);
        *reinterpret_cast<uint32_t*>(Oh + (tok0 + 8) * CC + col) =
            pack_f16(oc[ntd][2] * inv1, oc[ntd][3] * inv1);
    }
}

// ---------------------------------------------------------------------------
// Launch
// ---------------------------------------------------------------------------
extern "C" void kernel_launch(void* const* d_in, const int* in_sizes, int n_in,
                              void* d_out, int out_size) {
    const float* x = nullptr;
    const int*   coords = nullptr;
    const float* qkv_w = nullptr;
    const float* qkv_b = nullptr;
    const float* proj_w = nullptr;
    const float* proj_b = nullptr;
    for (int i = 0; i < n_in; ++i) {
        switch (in_sizes[i]) {
            case TOKENS * CC:      x      = (const float*)d_in[i]; break;
            case TOKENS * 3:       coords = (const int*)d_in[i];   break;
            case CC * C3:          qkv_w  = (const float*)d_in[i]; break;
            case C3:               qkv_b  = (const float*)d_in[i]; break;
            case CC * CC:          proj_w = (const float*)d_in[i]; break;
            case CC:               proj_b = (const float*)d_in[i]; break;
            default: break;
        }
    }
    float* out = (float*)d_out;

    __half *qkv, *xh, *ah, *wq, *wp, *qh, *kh, *vth;
    cudaGetSymbolAddress((void**)&qkv, g_qkv);
    cudaGetSymbolAddress((void**)&xh,  g_xh);
    cudaGetSymbolAddress((void**)&ah,  g_ah);
    cudaGetSymbolAddress((void**)&wq,  g_wq);
    cudaGetSymbolAddress((void**)&wp,  g_wp);
    cudaGetSymbolAddress((void**)&qh,  g_qh);
    cudaGetSymbolAddress((void**)&kh,  g_kh);
    cudaGetSymbolAddress((void**)&vth, g_vth);

    const int gemm_smem_qkv = 3 * (128 * 128 + 128 * 128);   // 98304 (BM=128)
    const int gemm_smem_prj = 3 * (64 * 128 + 128 * 128);    // 73728 (BM=64)
    cudaFuncSetAttribute((void*)mma_gemm_kernel<__half, 4>, cudaFuncAttributeMaxDynamicSharedMemorySize, gemm_smem_qkv);
    cudaFuncSetAttribute((void*)mma_gemm_kernel<float, 2>,  cudaFuncAttributeMaxDynamicSharedMemorySize, gemm_smem_prj);
    const int attn_smem = 3 * AT_STAGE;      // 89088
    cudaFuncSetAttribute(attn_mma_kernel, cudaFuncAttributeMaxDynamicSharedMemorySize, attn_smem);

    // 1) convert x -> single fp16
    convert_f16_kernel<<<4096, 256>>>(x, xh, TOKENS * CC);

    // 2) transpose qkv_w -> single fp16
    {
        dim3 grid(C3 / 32, CC / 32);
        transpose_f16_kernel<<<grid, dim3(32, 8)>>>(qkv_w, wq, CC, C3);
    }

    // 3) transpose proj_w -> single fp16
    {
        dim3 grid(CC / 32, CC / 32);
        transpose_f16_kernel<<<grid, dim3(32, 8)>>>(proj_w, wp, CC, CC);
    }

    // 4) QKV GEMM (BM=128, BK=64)
    {
        dim3 grid(C3 / 128, TOKENS / 128);
        mma_gemm_kernel<__half, 4><<<grid, 256, gemm_smem_qkv>>>(xh, wq, qkv_b, qkv,
                                                                 TOKENS, C3, CC);
    }

    // 5) RoPE + scale -> Q, K fp16; 6) transpose V -> fp16
    qk_prep_kernel<<<TOKENS, 128>>>(coords, qkv, qh, kh);
    {
        dim3 grid(NN / 32, (DD + 31) / 32, BB * HH);
        vt_prep_kernel<<<grid, dim3(32, 8)>>>(qkv, vth);
    }

    // 7) Flash attention -> writes proj input (ah, single fp16)
    {
        dim3 grid(NN / 128, HH, BB);
        attn_mma_kernel<<<grid, 256, attn_smem>>>(qh, kh, vth, ah);
    }

    // 8) Projection GEMM (BM=64 for tail, BK=64, writes fp32 output)
    {
        dim3 grid(CC / 128, TOKENS / 64);
        mma_gemm_kernel<float, 2><<<grid, 256, gemm_smem_prj>>>(ah, wp, proj_b, out,
                                                                TOKENS, CC, CC);
    }
}

// round 14
// speedup vs baseline: 2.3939x; 1.0343x over previous
#include <cuda_runtime.h>
#include <cuda_bf16.h>
#include <cuda_fp16.h>
#include <math.h>
#include <stdint.h>

// Problem constants
#define BB 2
#define NN 2048
#define CC 1664
#define HH 16
#define DD 104
#define C3 (3 * CC)          // 4992
#define TOKENS (BB * NN)     // 4096

// ---------------------------------------------------------------------------
// Scratch (no allocations allowed)
// ---------------------------------------------------------------------------
__device__ __align__(256) __half g_qkv[(size_t)TOKENS * C3];   // fp16 qkv intermediate
__device__ __align__(256) __half g_xh[(size_t)TOKENS * CC];
__device__ __align__(256) __half g_ah[(size_t)TOKENS * CC];
__device__ __align__(256) __half g_wq[(size_t)C3 * CC];        // qkv_w^T [4992][1664]
__device__ __align__(256) __half g_wp[(size_t)CC * CC];        // proj_w^T [1664][1664]
__device__ __align__(256) __half g_qh[(size_t)BB * HH * NN * DD];
__device__ __align__(256) __half g_kh[(size_t)BB * HH * NN * DD];
__device__ __align__(256) __half g_vth[(size_t)BB * HH * DD * NN];

// ---------------------------------------------------------------------------
// Helpers
// ---------------------------------------------------------------------------
__device__ __forceinline__ uint32_t smem_u32(const void* p) {
    uint32_t a;
    asm("{ .reg .u64 t; cvta.to.shared.u64 t, %1; cvt.u32.u64 %0, t; }" : "=r"(a) : "l"(p));
    return a;
}
__device__ __forceinline__ void cp_async16(uint32_t dst, const void* src) {
    asm volatile("cp.async.cg.shared.global [%0], [%1], 16;" :: "r"(dst), "l"(src));
}
__device__ __forceinline__ void cp_commit() {
    asm volatile("cp.async.commit_group;");
}
__device__ __forceinline__ void ldmatrix_x4(uint32_t* r, uint32_t addr) {
    asm volatile("ldmatrix.sync.aligned.m8n8.x4.shared.b16 {%0,%1,%2,%3}, [%4];"
                 : "=r"(r[0]), "=r"(r[1]), "=r"(r[2]), "=r"(r[3]) : "r"(addr));
}
__device__ __forceinline__ void ldmatrix_x2(uint32_t* r, uint32_t addr) {
    asm volatile("ldmatrix.sync.aligned.m8n8.x2.shared.b16 {%0,%1}, [%2];"
                 : "=r"(r[0]), "=r"(r[1]) : "r"(addr));
}
__device__ __forceinline__ void ldmatrix_x1(uint32_t& r, uint32_t addr) {
    asm volatile("ldmatrix.sync.aligned.m8n8.x1.shared.b16 {%0}, [%1];"
                 : "=r"(r) : "r"(addr));
}
__device__ __forceinline__ void mma_f16(float* c, const uint32_t* a, const uint32_t* b) {
    asm volatile("mma.sync.aligned.m16n8k16.row.col.f32.f16.f16.f32 "
                 "{%0,%1,%2,%3}, {%4,%5,%6,%7}, {%8,%9}, {%0,%1,%2,%3};"
                 : "+f"(c[0]), "+f"(c[1]), "+f"(c[2]), "+f"(c[3])
                 : "r"(a[0]), "r"(a[1]), "r"(a[2]), "r"(a[3]), "r"(b[0]), "r"(b[1]));
}
__device__ __forceinline__ void mma_f16_k8(float* c, const uint32_t* a, uint32_t b) {
    asm volatile("mma.sync.aligned.m16n8k8.row.col.f32.f16.f16.f32 "
                 "{%0,%1,%2,%3}, {%4,%5}, {%6}, {%0,%1,%2,%3};"
                 : "+f"(c[0]), "+f"(c[1]), "+f"(c[2]), "+f"(c[3])
                 : "r"(a[0]), "r"(a[1]), "r"(b));
}
__device__ __forceinline__ uint32_t pack_f16(float a, float b) {
    __half2 h = __floats2half2_rn(a, b);
    return *reinterpret_cast<uint32_t*>(&h);
}

// ---------------------------------------------------------------------------
// fp32 -> single fp16 convert
// ---------------------------------------------------------------------------
__global__ void convert_f16_kernel(const float* __restrict__ src,
                                   __half* __restrict__ dst, int n) {
    for (int i = blockIdx.x * blockDim.x + threadIdx.x; i < n; i += gridDim.x * blockDim.x)
        dst[i] = __float2half_rn(src[i]);
}

// ---------------------------------------------------------------------------
// W[Kr][Nc] row-major  ->  T[Nc][Kr] single fp16
// ---------------------------------------------------------------------------
__global__ void transpose_f16_kernel(const float* __restrict__ W,
                                     __half* __restrict__ T,
                                     int Kr, int Nc) {
    __shared__ float t[32][33];
    const int x = blockIdx.x * 32 + threadIdx.x;
    const int y0 = blockIdx.y * 32;
    for (int j = threadIdx.y; j < 32; j += 8)
        t[j][threadIdx.x] = W[(size_t)(y0 + j) * Nc + x];
    __syncthreads();
    const int ox = y0 + threadIdx.x;
    const int oy0 = blockIdx.x * 32;
    for (int j = threadIdx.y; j < 32; j += 8)
        T[(size_t)(oy0 + j) * Kr + ox] = __float2half_rn(t[threadIdx.x][j]);
}

// ---------------------------------------------------------------------------
// mma.sync GEMM (unchanged from R13): BK=64, 3-stage, 2 CTAs/SM.
// ---------------------------------------------------------------------------
template <typename OutT, int MT>
__global__ __launch_bounds__(256, 2)
void mma_gemm_kernel(const __half* __restrict__ A,
                     const __half* __restrict__ B,
                     const float* __restrict__ bias,
                     OutT* __restrict__ Cout,
                     int M, int N, int K) {
    constexpr int BM = MT * 32;
    constexpr int A_TILE = BM * 128;
    constexpr int B_TILE = 128 * 128;
    constexpr int STG = A_TILE + B_TILE;

    extern __shared__ char smem[];
    const uint32_t sbase = smem_u32(smem);
    const int tid  = threadIdx.x;
    const int lane = tid & 31;
    const int wid  = tid >> 5;
    const int wm   = wid & 1;
    const int wn   = wid >> 1;
    const int crow = blockIdx.y * BM;
    const int ccol = blockIdx.x * 128;

    const __half* Abase = A + (size_t)crow * K;
    const __half* Bbase = B + (size_t)ccol * K;

    const int lc = tid & 7;
    const int lr = tid >> 3;

    float acc[MT][4][4];
#pragma unroll
    for (int mt = 0; mt < MT; ++mt)
#pragma unroll
        for (int nt = 0; nt < 4; ++nt)
#pragma unroll
            for (int j = 0; j < 4; ++j) acc[mt][nt][j] = 0.0f;

    const int nch = K / 64;

    auto load_stage = [&](int stage, int k0) {
        const uint32_t sb = sbase + (uint32_t)stage * STG;
#pragma unroll
        for (int rr = 0; rr < BM / 32; ++rr) {
            const int row = lr + rr * 32;
            const uint32_t sw = (uint32_t)((lc ^ (row & 7)) << 4);
            cp_async16(sb + row * 128 + sw, Abase + (size_t)row * K + k0 + lc * 8);
        }
#pragma unroll
        for (int rr = 0; rr < 4; ++rr) {
            const int row = lr + rr * 32;
            const uint32_t sw = (uint32_t)((lc ^ (row & 7)) << 4);
            cp_async16(sb + A_TILE + row * 128 + sw, Bbase + (size_t)row * K + k0 + lc * 8);
        }
        cp_commit();
    };

    load_stage(0, 0);
    load_stage(1, 64);

    const int a_lrow   = (lane & 7) + ((lane >> 3) & 1) * 8;
    const int a_lchunk = lane >> 4;
    const int b_lrow   = lane & 7;
    const int b_lchunk = (lane >> 3) & 1;

    for (int ch = 0; ch < nch; ++ch) {
        if (ch + 2 <= nch) {
            asm volatile("cp.async.wait_group 1;");
        } else {
            asm volatile("cp.async.wait_group 0;");
        }
        __syncthreads();
        if (ch + 2 < nch) load_stage((ch + 2) % 3, (ch + 2) * 64);

        const uint32_t sb = sbase + (uint32_t)(ch % 3) * STG;

#pragma unroll
        for (int ks = 0; ks < 4; ++ks) {
            uint32_t af[MT][4], bf[4][2];
#pragma unroll
            for (int mt = 0; mt < MT; ++mt) {
                const int row = wm * (MT * 16) + mt * 16 + a_lrow;
                const int chn = 2 * ks + a_lchunk;
                const uint32_t addr = sb + (uint32_t)(row * 128)
                                    + (uint32_t)((chn ^ (row & 7)) << 4);
                ldmatrix_x4(af[mt], addr);
            }
#pragma unroll
            for (int nt = 0; nt < 4; ++nt) {
                const int row = wn * 32 + nt * 8 + b_lrow;
                const int chn = 2 * ks + b_lchunk;
                const uint32_t addr = sb + A_TILE + (uint32_t)(row * 128)
                                    + (uint32_t)((chn ^ (row & 7)) << 4);
                ldmatrix_x2(bf[nt], addr);
            }
#pragma unroll
            for (int mt = 0; mt < MT; ++mt)
#pragma unroll
                for (int nt = 0; nt < 4; ++nt)
                    mma_f16(acc[mt][nt], af[mt], bf[nt]);
        }
    }

    const int erow = lane >> 2;
    const int ecol = (lane & 3) * 2;
#pragma unroll
    for (int mt = 0; mt < MT; ++mt) {
#pragma unroll
        for (int nt = 0; nt < 4; ++nt) {
            const int col = ccol + wn * 32 + nt * 8 + ecol;
            const float b0 = bias[col], b1 = bias[col + 1];
            const int r0 = crow + wm * (MT * 16) + mt * 16 + erow;
            if constexpr (sizeof(OutT) == 4) {
                float2* p0 = reinterpret_cast<float2*>((float*)Cout + (size_t)r0 * N + col);
                *p0 = make_float2(acc[mt][nt][0] + b0, acc[mt][nt][1] + b1);
                float2* p1 = reinterpret_cast<float2*>((float*)Cout + (size_t)(r0 + 8) * N + col);
                *p1 = make_float2(acc[mt][nt][2] + b0, acc[mt][nt][3] + b1);
            } else {
                *reinterpret_cast<uint32_t*>((__half*)Cout + (size_t)r0 * N + col) =
                    pack_f16(acc[mt][nt][0] + b0, acc[mt][nt][1] + b1);
                *reinterpret_cast<uint32_t*>((__half*)Cout + (size_t)(r0 + 8) * N + col) =
                    pack_f16(acc[mt][nt][2] + b0, acc[mt][nt][3] + b1);
            }
        }
    }
}

// ---------------------------------------------------------------------------
// qk_prep: fused RoPE + scale (q) -> Q, K single fp16 [bh][n][104]
// ---------------------------------------------------------------------------
__global__ void qk_prep_kernel(const int* __restrict__ coords,
                               const __half* __restrict__ qkv,
                               __half* __restrict__ Qh,
                               __half* __restrict__ Kh) {
    const int token = blockIdx.x;
    const int tid = threadIdx.x;   // 128
    __shared__ float cs[DD], sn[DD];

    const int c0 = coords[token * 3 + 0];
    const int c1 = coords[token * 3 + 1];
    const int c2 = coords[token * 3 + 2];
    if (tid < DD) {
        const int j = tid;
        int jj, dd, coord;
        if (j < 34)      { const int u = j;      jj = (u < 17) ? u : u - 17; dd = 34; coord = c0; }
        else if (j < 68) { const int u = j - 34; jj = (u < 17) ? u : u - 17; dd = 34; coord = c1; }
        else             { const int u = j - 68; jj = (u < 18) ? u : u - 18; dd = 36; coord = c2; }
        const float inv = powf(10000.0f, -(2.0f * (float)jj) / (float)dd);
        const float ang = (float)coord * inv;
        cs[j] = cosf(ang);
        sn[j] = sinf(ang);
    }
    __syncthreads();

    if (tid >= DD) return;
    const int b = token >> 11, n = token & (NN - 1);
    const float scale = rsqrtf((float)DD);
    const __half* base = qkv + (size_t)token * C3;
    const int j = tid;

    for (int h = 0; h < HH; ++h) {
        const size_t o = ((size_t)(b * HH + h) * NN + n) * DD + j;
        const float qa = __half2float(base[h * DD + j]);
        const float qrot = (j < 52) ? -__half2float(base[h * DD + j + 52])
                                    :  __half2float(base[h * DD + j - 52]);
        Qh[o] = __float2half_rn((qa * cs[j] + qrot * sn[j]) * scale);

        const float ka = __half2float(base[CC + h * DD + j]);
        const float krot = (j < 52) ? -__half2float(base[CC + h * DD + j + 52])
                                    :  __half2float(base[CC + h * DD + j - 52]);
        Kh[o] = __float2half_rn(ka * cs[j] + krot * sn[j]);
    }
}

// ---------------------------------------------------------------------------
// vt_prep: V [token][h][d] fp16 -> Vt [bh][d][n] fp16 (transpose)
// ---------------------------------------------------------------------------
__global__ void vt_prep_kernel(const __half* __restrict__ qkv,
                               __half* __restrict__ Vth) {
    __shared__ float t[32][33];
    const int bh = blockIdx.z;
    const int b = bh >> 4, h = bh & 15;
    const int n0 = blockIdx.x * 32;
    const int d0 = blockIdx.y * 32;
    const int tx = threadIdx.x, ty = threadIdx.y;
#pragma unroll
    for (int j = 0; j < 4; ++j) {
        const int d = d0 + tx, n = n0 + ty + 8 * j;
        if (d < DD)
            t[ty + 8 * j][tx] = __half2float(qkv[(size_t)(b * NN + n) * C3 + 2 * CC + h * DD + d]);
    }
    __syncthreads();
#pragma unroll
    for (int j = 0; j < 4; ++j) {
        const int d = d0 + ty + 8 * j, n = n0 + tx;
        if (d < DD)
            Vth[((size_t)bh * DD + d) * NN + n] = __float2half_rn(t[tx][ty + 8 * j]);
    }
}

// ---------------------------------------------------------------------------
// Flash attention, single fp16. 256 queries/CTA, warp tile m32 x n64.
// Q resident in smem (64KB); m0 frags persistent, m1 frags reloaded per jp.
// K/V: 3-stage cp.async ring behind the Q region.
// ---------------------------------------------------------------------------
#define AT_Q     65536
#define AT_V     16384
#define AT_STAGE 29696

__global__ __launch_bounds__(256, 1)
void attn_mma_kernel(const __half* __restrict__ Qh,
                     const __half* __restrict__ Kh,
                     const __half* __restrict__ Vth,
                     __half* __restrict__ Oh) {
    extern __shared__ char smem[];
    const uint32_t sb = smem_u32(smem);
    const int tid = threadIdx.x, lane = tid & 31, wid = tid >> 5;
    const int qt = blockIdx.x, h = blockIdx.y, b = blockIdx.z;
    const int bh = b * HH + h;

    const __half* qh_p = Qh + ((size_t)bh * NN + qt * 256) * DD;
    const __half* kh_p = Kh + (size_t)bh * NN * DD;
    const __half* vh_p = Vth + (size_t)bh * DD * NN;

    // ---- stage Q: 256 rows x 13 chunks into resident region [0, 65536) ----
    for (int i = tid; i < 256 * 13; i += 256) {
        const int row = i / 13, c = i % 13;
        const uint32_t off = row * 256 + ((c ^ (row & 7)) << 4);
        cp_async16(sb + off, qh_p + (size_t)row * DD + c * 8);
    }
    cp_commit();

    auto load_stage = [&](int s, int kt) {
        const uint32_t st = sb + AT_Q + (uint32_t)s * AT_STAGE;
        const __half* kh_t = kh_p + (size_t)kt * 64 * DD;
        for (int i = tid; i < 64 * 13; i += 256) {
            const int row = i / 13, c = i % 13;
            const uint32_t off = row * 256 + ((c ^ (row & 7)) << 4);
            cp_async16(st + off, kh_t + (size_t)row * DD + c * 8);
        }
        const __half* vh_t = vh_p + kt * 64;
        for (int i = tid; i < 832; i += 256) {
            const int row = i >> 3, c = i & 7;
            const uint32_t off = row * 128 + ((c ^ (row & 7)) << 4);
            cp_async16(st + AT_V + off, vh_t + (size_t)row * NN + c * 8);
        }
        cp_commit();
    };

    load_stage(0, 0);
    load_stage(1, 1);
    asm volatile("cp.async.wait_group 2;");   // Q group complete
    __syncthreads();

    const int a_lrow = (lane & 7) + ((lane >> 3) & 1) * 8;
    const int arow0 = wid * 32 + a_lrow;        // m-frag 0 rows
    const int arow1 = arow0 + 16;               // m-frag 1 rows

    // persistent m0 frags + both k8 frags
    uint32_t qah0[6][4], qa80[2], qa81[2];
#pragma unroll
    for (int j = 0; j < 6; ++j) {
        const int chn = 2 * j + (lane >> 4);
        ldmatrix_x4(qah0[j], sb + arow0 * 256 + ((chn ^ (arow0 & 7)) << 4));
    }
    ldmatrix_x2(qa80, sb + arow0 * 256 + ((12 ^ (arow0 & 7)) << 4));
    ldmatrix_x2(qa81, sb + arow1 * 256 + ((12 ^ (arow1 & 7)) << 4));

    float oc0[13][4], oc1[13][4];
#pragma unroll
    for (int i = 0; i < 13; ++i) {
        oc0[i][0] = oc0[i][1] = oc0[i][2] = oc0[i][3] = 0.0f;
        oc1[i][0] = oc1[i][1] = oc1[i][2] = oc1[i][3] = 0.0f;
    }
    float m0 = -1e30f, m1 = -1e30f, m2 = -1e30f, m3 = -1e30f;
    float l0 = 0.0f, l1 = 0.0f, l2 = 0.0f, l3 = 0.0f;

    const int nkt = NN / 64;
    for (int kt = 0; kt < nkt; ++kt) {
        if (kt + 2 <= nkt) {
            asm volatile("cp.async.wait_group 1;");
        } else {
            asm volatile("cp.async.wait_group 0;");
        }
        __syncthreads();
        if (kt + 2 < nkt) load_stage((kt + 2) % 3, kt + 2);

        const uint32_t st = sb + AT_Q + (uint32_t)(kt % 3) * AT_STAGE;

        // ---- S = Q K for both m-frags ----
        float sc0[8][4], sc1[8][4];
#pragma unroll
        for (int nt = 0; nt < 8; ++nt) {
            sc0[nt][0] = sc0[nt][1] = sc0[nt][2] = sc0[nt][3] = 0.0f;
            sc1[nt][0] = sc1[nt][1] = sc1[nt][2] = sc1[nt][3] = 0.0f;
        }

#pragma unroll
        for (int jp = 0; jp < 3; ++jp) {
            uint32_t q1a[4], q1b[4];
            {
                const int c0n = 4 * jp + (lane >> 4);
                ldmatrix_x4(q1a, sb + arow1 * 256 + ((c0n ^ (arow1 & 7)) << 4));
                const int c1n = 4 * jp + 2 + (lane >> 4);
                ldmatrix_x4(q1b, sb + arow1 * 256 + ((c1n ^ (arow1 & 7)) << 4));
            }
#pragma unroll
            for (int nt = 0; nt < 8; ++nt) {
                const int brow = nt * 8 + (lane & 7);
                const int bchn = 4 * jp + (lane >> 3);
                const uint32_t addr = st + brow * 256 + ((bchn ^ (brow & 7)) << 4);
                uint32_t bh4[4];
                ldmatrix_x4(bh4, addr);
                mma_f16(sc0[nt], qah0[2 * jp],     &bh4[0]);
                mma_f16(sc0[nt], qah0[2 * jp + 1], &bh4[2]);
                mma_f16(sc1[nt], q1a, &bh4[0]);
                mma_f16(sc1[nt], q1b, &bh4[2]);
            }
        }
#pragma unroll
        for (int nt = 0; nt < 8; ++nt) {   // k8 step: dims 96..103
            const int brow = nt * 8 + (lane & 7);
            const uint32_t addr = st + brow * 256 + ((12 ^ (brow & 7)) << 4);
            uint32_t bh1;
            ldmatrix_x1(bh1, addr);
            mma_f16_k8(sc0[nt], qa80, bh1);
            mma_f16_k8(sc1[nt], qa81, bh1);
        }

        // ---- online softmax (4 row groups) ----
        float mx0 = m0, mx1 = m1, mx2 = m2, mx3 = m3;
#pragma unroll
        for (int nt = 0; nt < 8; ++nt) {
            mx0 = fmaxf(mx0, fmaxf(sc0[nt][0], sc0[nt][1]));
            mx1 = fmaxf(mx1, fmaxf(sc0[nt][2], sc0[nt][3]));
            mx2 = fmaxf(mx2, fmaxf(sc1[nt][0], sc1[nt][1]));
            mx3 = fmaxf(mx3, fmaxf(sc1[nt][2], sc1[nt][3]));
        }
        mx0 = fmaxf(mx0, __shfl_xor_sync(0xffffffffu, mx0, 1));
        mx0 = fmaxf(mx0, __shfl_xor_sync(0xffffffffu, mx0, 2));
        mx1 = fmaxf(mx1, __shfl_xor_sync(0xffffffffu, mx1, 1));
        mx1 = fmaxf(mx1, __shfl_xor_sync(0xffffffffu, mx1, 2));
        mx2 = fmaxf(mx2, __shfl_xor_sync(0xffffffffu, mx2, 1));
        mx2 = fmaxf(mx2, __shfl_xor_sync(0xffffffffu, mx2, 2));
        mx3 = fmaxf(mx3, __shfl_xor_sync(0xffffffffu, mx3, 1));
        mx3 = fmaxf(mx3, __shfl_xor_sync(0xffffffffu, mx3, 2));
        const float a0 = __expf(m0 - mx0), a1 = __expf(m1 - mx1);
        const float a2 = __expf(m2 - mx2), a3 = __expf(m3 - mx3);
        m0 = mx0; m1 = mx1; m2 = mx2; m3 = mx3;
        l0 *= a0; l1 *= a1; l2 *= a2; l3 *= a3;
#pragma unroll
        for (int i = 0; i < 13; ++i) {
            oc0[i][0] *= a0; oc0[i][1] *= a0; oc0[i][2] *= a1; oc0[i][3] *= a1;
            oc1[i][0] *= a2; oc1[i][1] *= a2; oc1[i][2] *= a3; oc1[i][3] *= a3;
        }

        uint32_t pah0[4][4], pah1[4][4];
#pragma unroll
        for (int jp = 0; jp < 4; ++jp) {
            {
                const float p00 = __expf(sc0[2 * jp][0] - mx0);
                const float p01 = __expf(sc0[2 * jp][1] - mx0);
                const float p02 = __expf(sc0[2 * jp][2] - mx1);
                const float p03 = __expf(sc0[2 * jp][3] - mx1);
                const float p10 = __expf(sc0[2 * jp + 1][0] - mx0);
                const float p11 = __expf(sc0[2 * jp + 1][1] - mx0);
                const float p12 = __expf(sc0[2 * jp + 1][2] - mx1);
                const float p13 = __expf(sc0[2 * jp + 1][3] - mx1);
                l0 += p00 + p01 + p10 + p11;
                l1 += p02 + p03 + p12 + p13;
                pah0[jp][0] = pack_f16(p00, p01);
                pah0[jp][1] = pack_f16(p02, p03);
                pah0[jp][2] = pack_f16(p10, p11);
                pah0[jp][3] = pack_f16(p12, p13);
            }
            {
                const float p00 = __expf(sc1[2 * jp][0] - mx2);
                const float p01 = __expf(sc1[2 * jp][1] - mx2);
                const float p02 = __expf(sc1[2 * jp][2] - mx3);
                const float p03 = __expf(sc1[2 * jp][3] - mx3);
                const float p10 = __expf(sc1[2 * jp + 1][0] - mx2);
                const float p11 = __expf(sc1[2 * jp + 1][1] - mx2);
                const float p12 = __expf(sc1[2 * jp + 1][2] - mx3);
                const float p13 = __expf(sc1[2 * jp + 1][3] - mx3);
                l2 += p00 + p01 + p10 + p11;
                l3 += p02 + p03 + p12 + p13;
                pah1[jp][0] = pack_f16(p00, p01);
                pah1[jp][1] = pack_f16(p02, p03);
                pah1[jp][2] = pack_f16(p10, p11);
                pah1[jp][3] = pack_f16(p12, p13);
            }
        }

        // ---- O += P V for both m-frags ----
#pragma unroll
        for (int jph = 0; jph < 2; ++jph) {
#pragma unroll
            for (int ntd = 0; ntd < 13; ++ntd) {
                const int vrow = ntd * 8 + (lane & 7);
                const int vchn = 4 * jph + (lane >> 3);
                const uint32_t addr = st + AT_Q + 0;  // placeholder (unused)
                (void)addr;
                const uint32_t vaddr = st + AT_V + vrow * 128 + ((vchn ^ (vrow & 7)) << 4);
                uint32_t vh4[4];
                ldmatrix_x4(vh4, vaddr);
                mma_f16(oc0[ntd], pah0[2 * jph],     &vh4[0]);
                mma_f16(oc0[ntd], pah0[2 * jph + 1], &vh4[2]);
                mma_f16(oc1[ntd], pah1[2 * jph],     &vh4[0]);
                mma_f16(oc1[ntd], pah1[2 * jph + 1], &vh4[2]);
            }
        }
    }

    // ---- epilogue ----
    l0 += __shfl_xor_sync(0xffffffffu, l0, 1);
    l0 += __shfl_xor_sync(0xffffffffu, l0, 2);
    l1 += __shfl_xor_sync(0xffffffffu, l1, 1);
    l1 += __shfl_xor_sync(0xffffffffu, l1, 2);
    l2 += __shfl_xor_sync(0xffffffffu, l2, 1);
    l2 += __shfl_xor_sync(0xffffffffu, l2, 2);
    l3 += __shfl_xor_sync(0xffffffffu, l3, 1);
    l3 += __shfl_xor_sync(0xffffffffu, l3, 2);
    const float inv0 = 1.0f / l0, inv1 = 1.0f / l1;
    const float inv2 = 1.0f / l2, inv3 = 1.0f / l3;
    const int erow = lane >> 2;
    const int row0 = qt * 256 + wid * 32 + erow;
    const size_t tok0 = (size_t)b * NN + row0;
    const int colbase = h * DD + 2 * (lane & 3);
#pragma unroll
    for (int ntd = 0; ntd < 13; ++ntd) {
        const int col = colbase + ntd * 8;
        *reinterpret_cast<uint32_t*>(Oh + tok0 * CC + col) =
            pack_f16(oc0[ntd][0] * inv0, oc0[ntd][1] * inv0);
        *reinterpret_cast<uint32_t*>(Oh + (tok0 + 8) * CC + col) =
            pack_f16(oc0[ntd][2] * inv1, oc0[ntd][3] * inv1);
        *reinterpret_cast<uint32_t*>(Oh + (tok0 + 16) * CC + col) =
            pack_f16(oc1[ntd][0] * inv2, oc1[ntd][1] * inv2);
        *reinterpret_cast<uint32_t*>(Oh + (tok0 + 24) * CC + col) =
            pack_f16(oc1[ntd][2] * inv3, oc1[ntd][3] * inv3);
    }
}

// ---------------------------------------------------------------------------
// Launch
// ---------------------------------------------------------------------------
extern "C" void kernel_launch(void* const* d_in, const int* in_sizes, int n_in,
                              void* d_out, int out_size) {
    const float* x = nullptr;
    const int*   coords = nullptr;
    const float* qkv_w = nullptr;
    const float* qkv_b = nullptr;
    const float* proj_w = nullptr;
    const float* proj_b = nullptr;
    for (int i = 0; i < n_in; ++i) {
        switch (in_sizes[i]) {
            case TOKENS * CC:      x      = (const float*)d_in[i]; break;
            case TOKENS * 3:       coords = (const int*)d_in[i];   break;
            case CC * C3:          qkv_w  = (const float*)d_in[i]; break;
            case C3:               qkv_b  = (const float*)d_in[i]; break;
            case CC * CC:          proj_w = (const float*)d_in[i]; break;
            case CC:               proj_b = (const float*)d_in[i]; break;
            default: break;
        }
    }
    float* out = (float*)d_out;

    __half *qkv, *xh, *ah, *wq, *wp, *qh, *kh, *vth;
    cudaGetSymbolAddress((void**)&qkv, g_qkv);
    cudaGetSymbolAddress((void**)&xh,  g_xh);
    cudaGetSymbolAddress((void**)&ah,  g_ah);
    cudaGetSymbolAddress((void**)&wq,  g_wq);
    cudaGetSymbolAddress((void**)&wp,  g_wp);
    cudaGetSymbolAddress((void**)&qh,  g_qh);
    cudaGetSymbolAddress((void**)&kh,  g_kh);
    cudaGetSymbolAddress((void**)&vth, g_vth);

    const int gemm_smem_qkv = 3 * (128 * 128 + 128 * 128);   // 98304
    const int gemm_smem_prj = 3 * (64 * 128 + 128 * 128);    // 73728
    cudaFuncSetAttribute((void*)mma_gemm_kernel<__half, 4>, cudaFuncAttributeMaxDynamicSharedMemorySize, gemm_smem_qkv);
    cudaFuncSetAttribute((void*)mma_gemm_kernel<float, 2>,  cudaFuncAttributeMaxDynamicSharedMemorySize, gemm_smem_prj);
    const int attn_smem = AT_Q + 3 * AT_STAGE;   // 154624
    cudaFuncSetAttribute(attn_mma_kernel, cudaFuncAttributeMaxDynamicSharedMemorySize, attn_smem);

    // 1) convert x -> single fp16
    convert_f16_kernel<<<4096, 256>>>(x, xh, TOKENS * CC);

    // 2) transpose qkv_w -> single fp16
    {
        dim3 grid(C3 / 32, CC / 32);
        transpose_f16_kernel<<<grid, dim3(32, 8)>>>(qkv_w, wq, CC, C3);
    }

    // 3) transpose proj_w -> single fp16
    {
        dim3 grid(CC / 32, CC / 32);
        transpose_f16_kernel<<<grid, dim3(32, 8)>>>(proj_w, wp, CC, CC);
    }

    // 4) QKV GEMM (BM=128, BK=64)
    {
        dim3 grid(C3 / 128, TOKENS / 128);
        mma_gemm_kernel<__half, 4><<<grid, 256, gemm_smem_qkv>>>(xh, wq, qkv_b, qkv,
                                                                 TOKENS, C3, CC);
    }

    // 5) RoPE + scale -> Q, K fp16; 6) transpose V -> fp16
    qk_prep_kernel<<<TOKENS, 128>>>(coords, qkv, qh, kh);
    {
        dim3 grid(NN / 32, (DD + 31) / 32, BB * HH);
        vt_prep_kernel<<<grid, dim3(32, 8)>>>(qkv, vth);
    }

    // 7) Flash attention (256 queries/CTA) -> writes proj input
    {
        dim3 grid(NN / 256, HH, BB);
        attn_mma_kernel<<<grid, 256, attn_smem>>>(qh, kh, vth, ah);
    }

    // 8) Projection GEMM (BM=64, BK=64, writes fp32 output)
    {
        dim3 grid(CC / 128, TOKENS / 64);
        mma_gemm_kernel<float, 2><<<grid, 256, gemm_smem_prj>>>(ah, wp, proj_b, out,
                                                                TOKENS, CC, CC);
    }
}

// round 15
// speedup vs baseline: 2.5088x; 1.0480x over previous
#include <cuda_runtime.h>
#include <cuda_bf16.h>
#include <cuda_fp16.h>
#include <math.h>
#include <stdint.h>

// Problem constants
#define BB 2
#define NN 2048
#define CC 1664
#define HH 16
#define DD 104
#define C3 (3 * CC)          // 4992
#define TOKENS (BB * NN)     // 4096

// ---------------------------------------------------------------------------
// Scratch (no allocations allowed)
// ---------------------------------------------------------------------------
__device__ __align__(256) __half g_qkv[(size_t)TOKENS * C3];
__device__ __align__(256) __half g_xh[(size_t)TOKENS * CC];
__device__ __align__(256) __half g_ah[(size_t)TOKENS * CC];
__device__ __align__(256) __half g_wq[(size_t)C3 * CC];
__device__ __align__(256) __half g_wp[(size_t)CC * CC];
__device__ __align__(256) __half g_qh[(size_t)BB * HH * NN * DD];
__device__ __align__(256) __half g_kh[(size_t)BB * HH * NN * DD];
__device__ __align__(256) __half g_vth[(size_t)BB * HH * DD * NN];

// ---------------------------------------------------------------------------
// Helpers
// ---------------------------------------------------------------------------
__device__ __forceinline__ uint32_t smem_u32(const void* p) {
    uint32_t a;
    asm("{ .reg .u64 t; cvta.to.shared.u64 t, %1; cvt.u32.u64 %0, t; }" : "=r"(a) : "l"(p));
    return a;
}
__device__ __forceinline__ void cp_async16(uint32_t dst, const void* src) {
    asm volatile("cp.async.cg.shared.global [%0], [%1], 16;" :: "r"(dst), "l"(src));
}
__device__ __forceinline__ void cp_commit() {
    asm volatile("cp.async.commit_group;");
}
__device__ __forceinline__ void ldmatrix_x4(uint32_t* r, uint32_t addr) {
    asm volatile("ldmatrix.sync.aligned.m8n8.x4.shared.b16 {%0,%1,%2,%3}, [%4];"
                 : "=r"(r[0]), "=r"(r[1]), "=r"(r[2]), "=r"(r[3]) : "r"(addr));
}
__device__ __forceinline__ void ldmatrix_x2(uint32_t* r, uint32_t addr) {
    asm volatile("ldmatrix.sync.aligned.m8n8.x2.shared.b16 {%0,%1}, [%2];"
                 : "=r"(r[0]), "=r"(r[1]) : "r"(addr));
}
__device__ __forceinline__ void ldmatrix_x1(uint32_t& r, uint32_t addr) {
    asm volatile("ldmatrix.sync.aligned.m8n8.x1.shared.b16 {%0}, [%1];"
                 : "=r"(r) : "r"(addr));
}
__device__ __forceinline__ void mma_f16(float* c, const uint32_t* a, const uint32_t* b) {
    asm volatile("mma.sync.aligned.m16n8k16.row.col.f32.f16.f16.f32 "
                 "{%0,%1,%2,%3}, {%4,%5,%6,%7}, {%8,%9}, {%0,%1,%2,%3};"
                 : "+f"(c[0]), "+f"(c[1]), "+f"(c[2]), "+f"(c[3])
                 : "r"(a[0]), "r"(a[1]), "r"(a[2]), "r"(a[3]), "r"(b[0]), "r"(b[1]));
}
__device__ __forceinline__ void mma_f16_k8(float* c, const uint32_t* a, uint32_t b) {
    asm volatile("mma.sync.aligned.m16n8k8.row.col.f32.f16.f16.f32 "
                 "{%0,%1,%2,%3}, {%4,%5}, {%6}, {%0,%1,%2,%3};"
                 : "+f"(c[0]), "+f"(c[1]), "+f"(c[2]), "+f"(c[3])
                 : "r"(a[0]), "r"(a[1]), "r"(b));
}
__device__ __forceinline__ uint32_t pack_f16(float a, float b) {
    __half2 h = __floats2half2_rn(a, b);
    return *reinterpret_cast<uint32_t*>(&h);
}

// ---------------------------------------------------------------------------
// Fused input prep: convert x (blocks [0,4096)), transpose wq ([4096,12208)),
// transpose wp ([12208,14912)). 256 threads (32x8).
// ---------------------------------------------------------------------------
#define PREP_X_BLK 4096
#define PREP_WQ_BLK (PREP_X_BLK + (C3 / 32) * (CC / 32))   // 4096 + 8112
#define PREP_TOTAL (PREP_WQ_BLK + (CC / 32) * (CC / 32))   // + 2704

__global__ void prep_inputs_kernel(const float* __restrict__ x,
                                   const float* __restrict__ wq_src,
                                   const float* __restrict__ wp_src,
                                   __half* __restrict__ xh,
                                   __half* __restrict__ wq,
                                   __half* __restrict__ wp) {
    __shared__ float t[32][33];
    const int bid = blockIdx.x;
    const int tx = threadIdx.x, ty = threadIdx.y;
    const int tid = ty * 32 + tx;

    if (bid < PREP_X_BLK) {
        const int n = TOKENS * CC;
        for (int i = bid * 256 + tid; i < n; i += PREP_X_BLK * 256)
            xh[i] = __float2half_rn(x[i]);
        return;
    }
    // transpose part: W[Kr][Nc] -> T[Nc][Kr]
    const float* W;
    __half* T;
    int Kr, Nc, bx, by;
    if (bid < PREP_WQ_BLK) {
        const int idx = bid - PREP_X_BLK;
        W = wq_src; T = wq; Kr = CC; Nc = C3;
        bx = idx % (C3 / 32); by = idx / (C3 / 32);
    } else {
        const int idx = bid - PREP_WQ_BLK;
        W = wp_src; T = wp; Kr = CC; Nc = CC;
        bx = idx % (CC / 32); by = idx / (CC / 32);
    }
    const int xcol = bx * 32 + tx;
    const int y0 = by * 32;
    for (int j = ty; j < 32; j += 8)
        t[j][tx] = W[(size_t)(y0 + j) * Nc + xcol];
    __syncthreads();
    const int ox = y0 + tx;
    const int oy0 = bx * 32;
    for (int j = ty; j < 32; j += 8)
        T[(size_t)(oy0 + j) * Kr + ox] = __float2half_rn(t[tx][j]);
}

// ---------------------------------------------------------------------------
// mma.sync GEMM: BK=64, 3-stage, 2 CTAs/SM. MT=4 -> BM=128.
// ---------------------------------------------------------------------------
template <typename OutT, int MT>
__global__ __launch_bounds__(256, 2)
void mma_gemm_kernel(const __half* __restrict__ A,
                     const __half* __restrict__ B,
                     const float* __restrict__ bias,
                     OutT* __restrict__ Cout,
                     int M, int N, int K) {
    constexpr int BM = MT * 32;
    constexpr int A_TILE = BM * 128;
    constexpr int B_TILE = 128 * 128;
    constexpr int STG = A_TILE + B_TILE;

    extern __shared__ char smem[];
    const uint32_t sbase = smem_u32(smem);
    const int tid  = threadIdx.x;
    const int lane = tid & 31;
    const int wid  = tid >> 5;
    const int wm   = wid & 1;
    const int wn   = wid >> 1;
    const int crow = blockIdx.y * BM;
    const int ccol = blockIdx.x * 128;

    const __half* Abase = A + (size_t)crow * K;
    const __half* Bbase = B + (size_t)ccol * K;

    const int lc = tid & 7;
    const int lr = tid >> 3;

    float acc[MT][4][4];
#pragma unroll
    for (int mt = 0; mt < MT; ++mt)
#pragma unroll
        for (int nt = 0; nt < 4; ++nt)
#pragma unroll
            for (int j = 0; j < 4; ++j) acc[mt][nt][j] = 0.0f;

    const int nch = K / 64;

    auto load_stage = [&](int stage, int k0) {
        const uint32_t sb = sbase + (uint32_t)stage * STG;
#pragma unroll
        for (int rr = 0; rr < BM / 32; ++rr) {
            const int row = lr + rr * 32;
            const uint32_t sw = (uint32_t)((lc ^ (row & 7)) << 4);
            cp_async16(sb + row * 128 + sw, Abase + (size_t)row * K + k0 + lc * 8);
        }
#pragma unroll
        for (int rr = 0; rr < 4; ++rr) {
            const int row = lr + rr * 32;
            const uint32_t sw = (uint32_t)((lc ^ (row & 7)) << 4);
            cp_async16(sb + A_TILE + row * 128 + sw, Bbase + (size_t)row * K + k0 + lc * 8);
        }
        cp_commit();
    };

    load_stage(0, 0);
    load_stage(1, 64);

    const int a_lrow   = (lane & 7) + ((lane >> 3) & 1) * 8;
    const int a_lchunk = lane >> 4;
    const int b_lrow   = lane & 7;
    const int b_lchunk = (lane >> 3) & 1;

    for (int ch = 0; ch < nch; ++ch) {
        if (ch + 2 <= nch) {
            asm volatile("cp.async.wait_group 1;");
        } else {
            asm volatile("cp.async.wait_group 0;");
        }
        __syncthreads();
        if (ch + 2 < nch) load_stage((ch + 2) % 3, (ch + 2) * 64);

        const uint32_t sb = sbase + (uint32_t)(ch % 3) * STG;

#pragma unroll
        for (int ks = 0; ks < 4; ++ks) {
            uint32_t af[MT][4], bf[4][2];
#pragma unroll
            for (int mt = 0; mt < MT; ++mt) {
                const int row = wm * (MT * 16) + mt * 16 + a_lrow;
                const int chn = 2 * ks + a_lchunk;
                const uint32_t addr = sb + (uint32_t)(row * 128)
                                    + (uint32_t)((chn ^ (row & 7)) << 4);
                ldmatrix_x4(af[mt], addr);
            }
#pragma unroll
            for (int nt = 0; nt < 4; ++nt) {
                const int row = wn * 32 + nt * 8 + b_lrow;
                const int chn = 2 * ks + b_lchunk;
                const uint32_t addr = sb + A_TILE + (uint32_t)(row * 128)
                                    + (uint32_t)((chn ^ (row & 7)) << 4);
                ldmatrix_x2(bf[nt], addr);
            }
#pragma unroll
            for (int mt = 0; mt < MT; ++mt)
#pragma unroll
                for (int nt = 0; nt < 4; ++nt)
                    mma_f16(acc[mt][nt], af[mt], bf[nt]);
        }
    }

    const int erow = lane >> 2;
    const int ecol = (lane & 3) * 2;
#pragma unroll
    for (int mt = 0; mt < MT; ++mt) {
#pragma unroll
        for (int nt = 0; nt < 4; ++nt) {
            const int col = ccol + wn * 32 + nt * 8 + ecol;
            const float b0 = bias[col], b1 = bias[col + 1];
            const int r0 = crow + wm * (MT * 16) + mt * 16 + erow;
            if constexpr (sizeof(OutT) == 4) {
                float2* p0 = reinterpret_cast<float2*>((float*)Cout + (size_t)r0 * N + col);
                *p0 = make_float2(acc[mt][nt][0] + b0, acc[mt][nt][1] + b1);
                float2* p1 = reinterpret_cast<float2*>((float*)Cout + (size_t)(r0 + 8) * N + col);
                *p1 = make_float2(acc[mt][nt][2] + b0, acc[mt][nt][3] + b1);
            } else {
                *reinterpret_cast<uint32_t*>((__half*)Cout + (size_t)r0 * N + col) =
                    pack_f16(acc[mt][nt][0] + b0, acc[mt][nt][1] + b1);
                *reinterpret_cast<uint32_t*>((__half*)Cout + (size_t)(r0 + 8) * N + col) =
                    pack_f16(acc[mt][nt][2] + b0, acc[mt][nt][3] + b1);
            }
        }
    }
}

// ---------------------------------------------------------------------------
// Fused qkv-derived prep: blocks [0,4096) = rope (q scaled by log2e/sqrt(D));
// blocks [4096, 4096+8192) = V transpose. 256 threads (32x8).
// ---------------------------------------------------------------------------
#define P2_ROPE 4096
#define P2_TOTAL (P2_ROPE + (NN / 32) * 4 * (BB * HH))

__global__ void qkv_prep_kernel(const int* __restrict__ coords,
                                const __half* __restrict__ qkv,
                                __half* __restrict__ Qh,
                                __half* __restrict__ Kh,
                                __half* __restrict__ Vth) {
    const int bid = blockIdx.x;
    const int tid = threadIdx.y * 32 + threadIdx.x;

    if (bid < P2_ROPE) {
        // rope: token = bid; 256 threads: tid = j + 128*half, halves over heads
        __shared__ float cs[DD], sn[DD];
        const int token = bid;
        const int c0 = coords[token * 3 + 0];
        const int c1 = coords[token * 3 + 1];
        const int c2 = coords[token * 3 + 2];
        if (tid < DD) {
            const int j = tid;
            int jj, dd, coord;
            if (j < 34)      { const int u = j;      jj = (u < 17) ? u : u - 17; dd = 34; coord = c0; }
            else if (j < 68) { const int u = j - 34; jj = (u < 17) ? u : u - 17; dd = 34; coord = c1; }
            else             { const int u = j - 68; jj = (u < 18) ? u : u - 18; dd = 36; coord = c2; }
            const float inv = powf(10000.0f, -(2.0f * (float)jj) / (float)dd);
            const float ang = (float)coord * inv;
            cs[j] = cosf(ang);
            sn[j] = sinf(ang);
        }
        __syncthreads();

        const int half = tid >> 7;           // 0 or 1
        const int j = tid & 127;
        if (j >= DD) return;
        const int b = token >> 11, n = token & (NN - 1);
        const float scale = rsqrtf((float)DD) * 1.4426950408889634f;  // log2(e) folded
        const __half* base = qkv + (size_t)token * C3;

        for (int hh = half * 8; hh < half * 8 + 8; ++hh) {
            const size_t o = ((size_t)(b * HH + hh) * NN + n) * DD + j;
            const float qa = __half2float(base[hh * DD + j]);
            const float qrot = (j < 52) ? -__half2float(base[hh * DD + j + 52])
                                        :  __half2float(base[hh * DD + j - 52]);
            Qh[o] = __float2half_rn((qa * cs[j] + qrot * sn[j]) * scale);

            const float ka = __half2float(base[CC + hh * DD + j]);
            const float krot = (j < 52) ? -__half2float(base[CC + hh * DD + j + 52])
                                        :  __half2float(base[CC + hh * DD + j - 52]);
            Kh[o] = __float2half_rn(ka * cs[j] + krot * sn[j]);
        }
        return;
    }

    // V transpose
    __shared__ float t[32][33];
    const int idx = bid - P2_ROPE;
    const int nb = idx % (NN / 32);
    const int db = (idx / (NN / 32)) % 4;
    const int bh = idx / ((NN / 32) * 4);
    const int b = bh >> 4, h = bh & 15;
    const int n0 = nb * 32;
    const int d0 = db * 32;
    const int tx = threadIdx.x, ty = threadIdx.y;
#pragma unroll
    for (int j = 0; j < 4; ++j) {
        const int d = d0 + tx, n = n0 + ty + 8 * j;
        if (d < DD)
            t[ty + 8 * j][tx] = __half2float(qkv[(size_t)(b * NN + n) * C3 + 2 * CC + h * DD + d]);
    }
    __syncthreads();
#pragma unroll
    for (int j = 0; j < 4; ++j) {
        const int d = d0 + ty + 8 * j, n = n0 + tx;
        if (d < DD)
            Vth[((size_t)bh * DD + d) * NN + n] = __float2half_rn(t[tx][ty + 8 * j]);
    }
}

// ---------------------------------------------------------------------------
// Flash attention, single fp16, exp2-domain softmax (log2e pre-folded in Q).
// 256 queries/CTA, warp tile m32 x n64. Q resident in smem.
// ---------------------------------------------------------------------------
#define AT_Q     65536
#define AT_V     16384
#define AT_STAGE 29696

__global__ __launch_bounds__(256, 1)
void attn_mma_kernel(const __half* __restrict__ Qh,
                     const __half* __restrict__ Kh,
                     const __half* __restrict__ Vth,
                     __half* __restrict__ Oh) {
    extern __shared__ char smem[];
    const uint32_t sb = smem_u32(smem);
    const int tid = threadIdx.x, lane = tid & 31, wid = tid >> 5;
    const int qt = blockIdx.x, h = blockIdx.y, b = blockIdx.z;
    const int bh = b * HH + h;

    const __half* qh_p = Qh + ((size_t)bh * NN + qt * 256) * DD;
    const __half* kh_p = Kh + (size_t)bh * NN * DD;
    const __half* vh_p = Vth + (size_t)bh * DD * NN;

    for (int i = tid; i < 256 * 13; i += 256) {
        const int row = i / 13, c = i % 13;
        const uint32_t off = row * 256 + ((c ^ (row & 7)) << 4);
        cp_async16(sb + off, qh_p + (size_t)row * DD + c * 8);
    }
    cp_commit();

    auto load_stage = [&](int s, int kt) {
        const uint32_t st = sb + AT_Q + (uint32_t)s * AT_STAGE;
        const __half* kh_t = kh_p + (size_t)kt * 64 * DD;
        for (int i = tid; i < 64 * 13; i += 256) {
            const int row = i / 13, c = i % 13;
            const uint32_t off = row * 256 + ((c ^ (row & 7)) << 4);
            cp_async16(st + off, kh_t + (size_t)row * DD + c * 8);
        }
        const __half* vh_t = vh_p + kt * 64;
        for (int i = tid; i < 832; i += 256) {
            const int row = i >> 3, c = i & 7;
            const uint32_t off = row * 128 + ((c ^ (row & 7)) << 4);
            cp_async16(st + AT_V + off, vh_t + (size_t)row * NN + c * 8);
        }
        cp_commit();
    };

    load_stage(0, 0);
    load_stage(1, 1);
    asm volatile("cp.async.wait_group 2;");
    __syncthreads();

    const int a_lrow = (lane & 7) + ((lane >> 3) & 1) * 8;
    const int arow0 = wid * 32 + a_lrow;
    const int arow1 = arow0 + 16;

    uint32_t qah0[6][4], qa80[2], qa81[2];
#pragma unroll
    for (int j = 0; j < 6; ++j) {
        const int chn = 2 * j + (lane >> 4);
        ldmatrix_x4(qah0[j], sb + arow0 * 256 + ((chn ^ (arow0 & 7)) << 4));
    }
    ldmatrix_x2(qa80, sb + arow0 * 256 + ((12 ^ (arow0 & 7)) << 4));
    ldmatrix_x2(qa81, sb + arow1 * 256 + ((12 ^ (arow1 & 7)) << 4));

    float oc0[13][4], oc1[13][4];
#pragma unroll
    for (int i = 0; i < 13; ++i) {
        oc0[i][0] = oc0[i][1] = oc0[i][2] = oc0[i][3] = 0.0f;
        oc1[i][0] = oc1[i][1] = oc1[i][2] = oc1[i][3] = 0.0f;
    }
    float m0 = -1e30f, m1 = -1e30f, m2 = -1e30f, m3 = -1e30f;
    float l0 = 0.0f, l1 = 0.0f, l2 = 0.0f, l3 = 0.0f;

    const int nkt = NN / 64;
    for (int kt = 0; kt < nkt; ++kt) {
        if (kt + 2 <= nkt) {
            asm volatile("cp.async.wait_group 1;");
        } else {
            asm volatile("cp.async.wait_group 0;");
        }
        __syncthreads();
        if (kt + 2 < nkt) load_stage((kt + 2) % 3, kt + 2);

        const uint32_t st = sb + AT_Q + (uint32_t)(kt % 3) * AT_STAGE;

        float sc0[8][4], sc1[8][4];
#pragma unroll
        for (int nt = 0; nt < 8; ++nt) {
            sc0[nt][0] = sc0[nt][1] = sc0[nt][2] = sc0[nt][3] = 0.0f;
            sc1[nt][0] = sc1[nt][1] = sc1[nt][2] = sc1[nt][3] = 0.0f;
        }

#pragma unroll
        for (int jp = 0; jp < 3; ++jp) {
            uint32_t q1a[4], q1b[4];
            {
                const int c0n = 4 * jp + (lane >> 4);
                ldmatrix_x4(q1a, sb + arow1 * 256 + ((c0n ^ (arow1 & 7)) << 4));
                const int c1n = 4 * jp + 2 + (lane >> 4);
                ldmatrix_x4(q1b, sb + arow1 * 256 + ((c1n ^ (arow1 & 7)) << 4));
            }
#pragma unroll
            for (int nt = 0; nt < 8; ++nt) {
                const int brow = nt * 8 + (lane & 7);
                const int bchn = 4 * jp + (lane >> 3);
                const uint32_t addr = st + brow * 256 + ((bchn ^ (brow & 7)) << 4);
                uint32_t bh4[4];
                ldmatrix_x4(bh4, addr);
                mma_f16(sc0[nt], qah0[2 * jp],     &bh4[0]);
                mma_f16(sc0[nt], qah0[2 * jp + 1], &bh4[2]);
                mma_f16(sc1[nt], q1a, &bh4[0]);
                mma_f16(sc1[nt], q1b, &bh4[2]);
            }
        }
#pragma unroll
        for (int nt = 0; nt < 8; ++nt) {
            const int brow = nt * 8 + (lane & 7);
            const uint32_t addr = st + brow * 256 + ((12 ^ (brow & 7)) << 4);
            uint32_t bh1;
            ldmatrix_x1(bh1, addr);
            mma_f16_k8(sc0[nt], qa80, bh1);
            mma_f16_k8(sc1[nt], qa81, bh1);
        }

        // ---- online softmax in exp2 domain ----
        float mx0 = m0, mx1 = m1, mx2 = m2, mx3 = m3;
#pragma unroll
        for (int nt = 0; nt < 8; ++nt) {
            mx0 = fmaxf(mx0, fmaxf(sc0[nt][0], sc0[nt][1]));
            mx1 = fmaxf(mx1, fmaxf(sc0[nt][2], sc0[nt][3]));
            mx2 = fmaxf(mx2, fmaxf(sc1[nt][0], sc1[nt][1]));
            mx3 = fmaxf(mx3, fmaxf(sc1[nt][2], sc1[nt][3]));
        }
        mx0 = fmaxf(mx0, __shfl_xor_sync(0xffffffffu, mx0, 1));
        mx0 = fmaxf(mx0, __shfl_xor_sync(0xffffffffu, mx0, 2));
        mx1 = fmaxf(mx1, __shfl_xor_sync(0xffffffffu, mx1, 1));
        mx1 = fmaxf(mx1, __shfl_xor_sync(0xffffffffu, mx1, 2));
        mx2 = fmaxf(mx2, __shfl_xor_sync(0xffffffffu, mx2, 1));
        mx2 = fmaxf(mx2, __shfl_xor_sync(0xffffffffu, mx2, 2));
        mx3 = fmaxf(mx3, __shfl_xor_sync(0xffffffffu, mx3, 1));
        mx3 = fmaxf(mx3, __shfl_xor_sync(0xffffffffu, mx3, 2));
        const float a0 = exp2f(m0 - mx0), a1 = exp2f(m1 - mx1);
        const float a2 = exp2f(m2 - mx2), a3 = exp2f(m3 - mx3);
        m0 = mx0; m1 = mx1; m2 = mx2; m3 = mx3;
        l0 *= a0; l1 *= a1; l2 *= a2; l3 *= a3;
#pragma unroll
        for (int i = 0; i < 13; ++i) {
            oc0[i][0] *= a0; oc0[i][1] *= a0; oc0[i][2] *= a1; oc0[i][3] *= a1;
            oc1[i][0] *= a2; oc1[i][1] *= a2; oc1[i][2] *= a3; oc1[i][3] *= a3;
        }

        uint32_t pah0[4][4], pah1[4][4];
#pragma unroll
        for (int jp = 0; jp < 4; ++jp) {
            {
                const float p00 = exp2f(sc0[2 * jp][0] - mx0);
                const float p01 = exp2f(sc0[2 * jp][1] - mx0);
                const float p02 = exp2f(sc0[2 * jp][2] - mx1);
                const float p03 = exp2f(sc0[2 * jp][3] - mx1);
                const float p10 = exp2f(sc0[2 * jp + 1][0] - mx0);
                const float p11 = exp2f(sc0[2 * jp + 1][1] - mx0);
                const float p12 = exp2f(sc0[2 * jp + 1][2] - mx1);
                const float p13 = exp2f(sc0[2 * jp + 1][3] - mx1);
                l0 += p00 + p01 + p10 + p11;
                l1 += p02 + p03 + p12 + p13;
                pah0[jp][0] = pack_f16(p00, p01);
                pah0[jp][1] = pack_f16(p02, p03);
                pah0[jp][2] = pack_f16(p10, p11);
                pah0[jp][3] = pack_f16(p12, p13);
            }
            {
                const float p00 = exp2f(sc1[2 * jp][0] - mx2);
                const float p01 = exp2f(sc1[2 * jp][1] - mx2);
                const float p02 = exp2f(sc1[2 * jp][2] - mx3);
                const float p03 = exp2f(sc1[2 * jp][3] - mx3);
                const float p10 = exp2f(sc1[2 * jp + 1][0] - mx2);
                const float p11 = exp2f(sc1[2 * jp + 1][1] - mx2);
                const float p12 = exp2f(sc1[2 * jp + 1][2] - mx3);
                const float p13 = exp2f(sc1[2 * jp + 1][3] - mx3);
                l2 += p00 + p01 + p10 + p11;
                l3 += p02 + p03 + p12 + p13;
                pah1[jp][0] = pack_f16(p00, p01);
                pah1[jp][1] = pack_f16(p02, p03);
                pah1[jp][2] = pack_f16(p10, p11);
                pah1[jp][3] = pack_f16(p12, p13);
            }
        }

#pragma unroll
        for (int jph = 0; jph < 2; ++jph) {
#pragma unroll
            for (int ntd = 0; ntd < 13; ++ntd) {
                const int vrow = ntd * 8 + (lane & 7);
                const int vchn = 4 * jph + (lane >> 3);
                const uint32_t vaddr = st + AT_V + vrow * 128 + ((vchn ^ (vrow & 7)) << 4);
                uint32_t vh4[4];
                ldmatrix_x4(vh4, vaddr);
                mma_f16(oc0[ntd], pah0[2 * jph],     &vh4[0]);
                mma_f16(oc0[ntd], pah0[2 * jph + 1], &vh4[2]);
                mma_f16(oc1[ntd], pah1[2 * jph],     &vh4[0]);
                mma_f16(oc1[ntd], pah1[2 * jph + 1], &vh4[2]);
            }
        }
    }

    l0 += __shfl_xor_sync(0xffffffffu, l0, 1);
    l0 += __shfl_xor_sync(0xffffffffu, l0, 2);
    l1 += __shfl_xor_sync(0xffffffffu, l1, 1);
    l1 += __shfl_xor_sync(0xffffffffu, l1, 2);
    l2 += __shfl_xor_sync(0xffffffffu, l2, 1);
    l2 += __shfl_xor_sync(0xffffffffu, l2, 2);
    l3 += __shfl_xor_sync(0xffffffffu, l3, 1);
    l3 += __shfl_xor_sync(0xffffffffu, l3, 2);
    const float inv0 = 1.0f / l0, inv1 = 1.0f / l1;
    const float inv2 = 1.0f / l2, inv3 = 1.0f / l3;
    const int erow = lane >> 2;
    const int row0 = qt * 256 + wid * 32 + erow;
    const size_t tok0 = (size_t)b * NN + row0;
    const int colbase = h * DD + 2 * (lane & 3);
#pragma unroll
    for (int ntd = 0; ntd < 13; ++ntd) {
        const int col = colbase + ntd * 8;
        *reinterpret_cast<uint32_t*>(Oh + tok0 * CC + col) =
            pack_f16(oc0[ntd][0] * inv0, oc0[ntd][1] * inv0);
        *reinterpret_cast<uint32_t*>(Oh + (tok0 + 8) * CC + col) =
            pack_f16(oc0[ntd][2] * inv1, oc0[ntd][3] * inv1);
        *reinterpret_cast<uint32_t*>(Oh + (tok0 + 16) * CC + col) =
            pack_f16(oc1[ntd][0] * inv2, oc1[ntd][1] * inv2);
        *reinterpret_cast<uint32_t*>(Oh + (tok0 + 24) * CC + col) =
            pack_f16(oc1[ntd][2] * inv3, oc1[ntd][3] * inv3);
    }
}

// ---------------------------------------------------------------------------
// Launch: prep(1) -> QKV GEMM(2) -> qkv_prep(3) -> attention(4) -> proj(5)
// ---------------------------------------------------------------------------
extern "C" void kernel_launch(void* const* d_in, const int* in_sizes, int n_in,
                              void* d_out, int out_size) {
    const float* x = nullptr;
    const int*   coords = nullptr;
    const float* qkv_w = nullptr;
    const float* qkv_b = nullptr;
    const float* proj_w = nullptr;
    const float* proj_b = nullptr;
    for (int i = 0; i < n_in; ++i) {
        switch (in_sizes[i]) {
            case TOKENS * CC:      x      = (const float*)d_in[i]; break;
            case TOKENS * 3:       coords = (const int*)d_in[i];   break;
            case CC * C3:          qkv_w  = (const float*)d_in[i]; break;
            case C3:               qkv_b  = (const float*)d_in[i]; break;
            case CC * CC:          proj_w = (const float*)d_in[i]; break;
            case CC:               proj_b = (const float*)d_in[i]; break;
            default: break;
        }
    }
    float* out = (float*)d_out;

    __half *qkv, *xh, *ah, *wq, *wp, *qh, *kh, *vth;
    cudaGetSymbolAddress((void**)&qkv, g_qkv);
    cudaGetSymbolAddress((void**)&xh,  g_xh);
    cudaGetSymbolAddress((void**)&ah,  g_ah);
    cudaGetSymbolAddress((void**)&wq,  g_wq);
    cudaGetSymbolAddress((void**)&wp,  g_wp);
    cudaGetSymbolAddress((void**)&qh,  g_qh);
    cudaGetSymbolAddress((void**)&kh,  g_kh);
    cudaGetSymbolAddress((void**)&vth, g_vth);

    const int gemm_smem = 3 * (128 * 128 + 128 * 128);   // 98304 (BM=128)
    cudaFuncSetAttribute((void*)mma_gemm_kernel<__half, 4>, cudaFuncAttributeMaxDynamicSharedMemorySize, gemm_smem);
    cudaFuncSetAttribute((void*)mma_gemm_kernel<float, 4>,  cudaFuncAttributeMaxDynamicSharedMemorySize, gemm_smem);
    const int attn_smem = AT_Q + 3 * AT_STAGE;   // 154624
    cudaFuncSetAttribute(attn_mma_kernel, cudaFuncAttributeMaxDynamicSharedMemorySize, attn_smem);

    // 1) fused input prep (convert x + transpose wq + transpose wp)
    prep_inputs_kernel<<<PREP_TOTAL, dim3(32, 8)>>>(x, qkv_w, proj_w, xh, wq, wp);

    // 2) QKV GEMM (BM=128, BK=64)
    {
        dim3 grid(C3 / 128, TOKENS / 128);
        mma_gemm_kernel<__half, 4><<<grid, 256, gemm_smem>>>(xh, wq, qkv_b, qkv,
                                                             TOKENS, C3, CC);
    }

    // 3) fused rope + V transpose
    qkv_prep_kernel<<<P2_TOTAL, dim3(32, 8)>>>(coords, qkv, qh, kh, vth);

    // 4) Flash attention (256 queries/CTA)
    {
        dim3 grid(NN / 256, HH, BB);
        attn_mma_kernel<<<grid, 256, attn_smem>>>(qh, kh, vth, ah);
    }

    // 5) Projection GEMM (BM=128, BK=64, fp32 output)
    {
        dim3 grid(CC / 128, TOKENS / 128);
        mma_gemm_kernel<float, 4><<<grid, 256, gemm_smem>>>(ah, wp, proj_b, out,
                                                            TOKENS, CC, CC);
    }
}

// round 16
// speedup vs baseline: 2.5165x; 1.0031x over previous
#include <cuda_runtime.h>
#include <cuda_bf16.h>
#include <cuda_fp16.h>
#include <math.h>
#include <stdint.h>

// Problem constants
#define BB 2
#define NN 2048
#define CC 1664
#define HH 16
#define DD 104
#define C3 (3 * CC)          // 4992
#define TOKENS (BB * NN)     // 4096

// ---------------------------------------------------------------------------
// Scratch (no allocations allowed)
// ---------------------------------------------------------------------------
__device__ __align__(256) __half g_qkv[(size_t)TOKENS * C3];
__device__ __align__(256) __half g_xh[(size_t)TOKENS * CC];
__device__ __align__(256) __half g_ah[(size_t)TOKENS * CC];
__device__ __align__(256) __half g_wq[(size_t)C3 * CC];
__device__ __align__(256) __half g_wp[(size_t)CC * CC];
__device__ __align__(256) __half g_qh[(size_t)BB * HH * NN * DD];
__device__ __align__(256) __half g_kh[(size_t)BB * HH * NN * DD];
__device__ __align__(256) __half g_vth[(size_t)BB * HH * DD * NN];

// ---------------------------------------------------------------------------
// Helpers
// ---------------------------------------------------------------------------
__device__ __forceinline__ uint32_t smem_u32(const void* p) {
    uint32_t a;
    asm("{ .reg .u64 t; cvta.to.shared.u64 t, %1; cvt.u32.u64 %0, t; }" : "=r"(a) : "l"(p));
    return a;
}
__device__ __forceinline__ void cp_async16(uint32_t dst, const void* src) {
    asm volatile("cp.async.cg.shared.global [%0], [%1], 16;" :: "r"(dst), "l"(src));
}
__device__ __forceinline__ void cp_commit() {
    asm volatile("cp.async.commit_group;");
}
__device__ __forceinline__ void ldmatrix_x4(uint32_t* r, uint32_t addr) {
    asm volatile("ldmatrix.sync.aligned.m8n8.x4.shared.b16 {%0,%1,%2,%3}, [%4];"
                 : "=r"(r[0]), "=r"(r[1]), "=r"(r[2]), "=r"(r[3]) : "r"(addr));
}
__device__ __forceinline__ void ldmatrix_x2(uint32_t* r, uint32_t addr) {
    asm volatile("ldmatrix.sync.aligned.m8n8.x2.shared.b16 {%0,%1}, [%2];"
                 : "=r"(r[0]), "=r"(r[1]) : "r"(addr));
}
__device__ __forceinline__ void ldmatrix_x1(uint32_t& r, uint32_t addr) {
    asm volatile("ldmatrix.sync.aligned.m8n8.x1.shared.b16 {%0}, [%1];"
                 : "=r"(r) : "r"(addr));
}
__device__ __forceinline__ void mma_f16(float* c, const uint32_t* a, const uint32_t* b) {
    asm volatile("mma.sync.aligned.m16n8k16.row.col.f32.f16.f16.f32 "
                 "{%0,%1,%2,%3}, {%4,%5,%6,%7}, {%8,%9}, {%0,%1,%2,%3};"
                 : "+f"(c[0]), "+f"(c[1]), "+f"(c[2]), "+f"(c[3])
                 : "r"(a[0]), "r"(a[1]), "r"(a[2]), "r"(a[3]), "r"(b[0]), "r"(b[1]));
}
__device__ __forceinline__ void mma_f16_k8(float* c, const uint32_t* a, uint32_t b) {
    asm volatile("mma.sync.aligned.m16n8k8.row.col.f32.f16.f16.f32 "
                 "{%0,%1,%2,%3}, {%4,%5}, {%6}, {%0,%1,%2,%3};"
                 : "+f"(c[0]), "+f"(c[1]), "+f"(c[2]), "+f"(c[3])
                 : "r"(a[0]), "r"(a[1]), "r"(b));
}
__device__ __forceinline__ uint32_t pack_f16(float a, float b) {
    __half2 h = __floats2half2_rn(a, b);
    return *reinterpret_cast<uint32_t*>(&h);
}

// ---------------------------------------------------------------------------
// Fused input prep (unchanged from R15)
// ---------------------------------------------------------------------------
#define PREP_X_BLK 4096
#define PREP_WQ_BLK (PREP_X_BLK + (C3 / 32) * (CC / 32))
#define PREP_TOTAL (PREP_WQ_BLK + (CC / 32) * (CC / 32))

__global__ void prep_inputs_kernel(const float* __restrict__ x,
                                   const float* __restrict__ wq_src,
                                   const float* __restrict__ wp_src,
                                   __half* __restrict__ xh,
                                   __half* __restrict__ wq,
                                   __half* __restrict__ wp) {
    __shared__ float t[32][33];
    const int bid = blockIdx.x;
    const int tx = threadIdx.x, ty = threadIdx.y;
    const int tid = ty * 32 + tx;

    if (bid < PREP_X_BLK) {
        const int n = TOKENS * CC;
        for (int i = bid * 256 + tid; i < n; i += PREP_X_BLK * 256)
            xh[i] = __float2half_rn(x[i]);
        return;
    }
    const float* W;
    __half* T;
    int Kr, Nc, bx, by;
    if (bid < PREP_WQ_BLK) {
        const int idx = bid - PREP_X_BLK;
        W = wq_src; T = wq; Kr = CC; Nc = C3;
        bx = idx % (C3 / 32); by = idx / (C3 / 32);
    } else {
        const int idx = bid - PREP_WQ_BLK;
        W = wp_src; T = wp; Kr = CC; Nc = CC;
        bx = idx % (CC / 32); by = idx / (CC / 32);
    }
    const int xcol = bx * 32 + tx;
    const int y0 = by * 32;
    for (int j = ty; j < 32; j += 8)
        t[j][tx] = W[(size_t)(y0 + j) * Nc + xcol];
    __syncthreads();
    const int ox = y0 + tx;
    const int oy0 = bx * 32;
    for (int j = ty; j < 32; j += 8)
        T[(size_t)(oy0 + j) * Kr + ox] = __float2half_rn(t[tx][j]);
}

// ---------------------------------------------------------------------------
// mma.sync GEMM (unchanged): BK=64, 3-stage, 2 CTAs/SM, BM=128.
// ---------------------------------------------------------------------------
template <typename OutT, int MT>
__global__ __launch_bounds__(256, 2)
void mma_gemm_kernel(const __half* __restrict__ A,
                     const __half* __restrict__ B,
                     const float* __restrict__ bias,
                     OutT* __restrict__ Cout,
                     int M, int N, int K) {
    constexpr int BM = MT * 32;
    constexpr int A_TILE = BM * 128;
    constexpr int B_TILE = 128 * 128;
    constexpr int STG = A_TILE + B_TILE;

    extern __shared__ char smem[];
    const uint32_t sbase = smem_u32(smem);
    const int tid  = threadIdx.x;
    const int lane = tid & 31;
    const int wid  = tid >> 5;
    const int wm   = wid & 1;
    const int wn   = wid >> 1;
    const int crow = blockIdx.y * BM;
    const int ccol = blockIdx.x * 128;

    const __half* Abase = A + (size_t)crow * K;
    const __half* Bbase = B + (size_t)ccol * K;

    const int lc = tid & 7;
    const int lr = tid >> 3;

    float acc[MT][4][4];
#pragma unroll
    for (int mt = 0; mt < MT; ++mt)
#pragma unroll
        for (int nt = 0; nt < 4; ++nt)
#pragma unroll
            for (int j = 0; j < 4; ++j) acc[mt][nt][j] = 0.0f;

    const int nch = K / 64;

    auto load_stage = [&](int stage, int k0) {
        const uint32_t sb = sbase + (uint32_t)stage * STG;
#pragma unroll
        for (int rr = 0; rr < BM / 32; ++rr) {
            const int row = lr + rr * 32;
            const uint32_t sw = (uint32_t)((lc ^ (row & 7)) << 4);
            cp_async16(sb + row * 128 + sw, Abase + (size_t)row * K + k0 + lc * 8);
        }
#pragma unroll
        for (int rr = 0; rr < 4; ++rr) {
            const int row = lr + rr * 32;
            const uint32_t sw = (uint32_t)((lc ^ (row & 7)) << 4);
            cp_async16(sb + A_TILE + row * 128 + sw, Bbase + (size_t)row * K + k0 + lc * 8);
        }
        cp_commit();
    };

    load_stage(0, 0);
    load_stage(1, 64);

    const int a_lrow   = (lane & 7) + ((lane >> 3) & 1) * 8;
    const int a_lchunk = lane >> 4;
    const int b_lrow   = lane & 7;
    const int b_lchunk = (lane >> 3) & 1;

    for (int ch = 0; ch < nch; ++ch) {
        if (ch + 2 <= nch) {
            asm volatile("cp.async.wait_group 1;");
        } else {
            asm volatile("cp.async.wait_group 0;");
        }
        __syncthreads();
        if (ch + 2 < nch) load_stage((ch + 2) % 3, (ch + 2) * 64);

        const uint32_t sb = sbase + (uint32_t)(ch % 3) * STG;

#pragma unroll
        for (int ks = 0; ks < 4; ++ks) {
            uint32_t af[MT][4], bf[4][2];
#pragma unroll
            for (int mt = 0; mt < MT; ++mt) {
                const int row = wm * (MT * 16) + mt * 16 + a_lrow;
                const int chn = 2 * ks + a_lchunk;
                const uint32_t addr = sb + (uint32_t)(row * 128)
                                    + (uint32_t)((chn ^ (row & 7)) << 4);
                ldmatrix_x4(af[mt], addr);
            }
#pragma unroll
            for (int nt = 0; nt < 4; ++nt) {
                const int row = wn * 32 + nt * 8 + b_lrow;
                const int chn = 2 * ks + b_lchunk;
                const uint32_t addr = sb + A_TILE + (uint32_t)(row * 128)
                                    + (uint32_t)((chn ^ (row & 7)) << 4);
                ldmatrix_x2(bf[nt], addr);
            }
#pragma unroll
            for (int mt = 0; mt < MT; ++mt)
#pragma unroll
                for (int nt = 0; nt < 4; ++nt)
                    mma_f16(acc[mt][nt], af[mt], bf[nt]);
        }
    }

    const int erow = lane >> 2;
    const int ecol = (lane & 3) * 2;
#pragma unroll
    for (int mt = 0; mt < MT; ++mt) {
#pragma unroll
        for (int nt = 0; nt < 4; ++nt) {
            const int col = ccol + wn * 32 + nt * 8 + ecol;
            const float b0 = bias[col], b1 = bias[col + 1];
            const int r0 = crow + wm * (MT * 16) + mt * 16 + erow;
            if constexpr (sizeof(OutT) == 4) {
                float2* p0 = reinterpret_cast<float2*>((float*)Cout + (size_t)r0 * N + col);
                *p0 = make_float2(acc[mt][nt][0] + b0, acc[mt][nt][1] + b1);
                float2* p1 = reinterpret_cast<float2*>((float*)Cout + (size_t)(r0 + 8) * N + col);
                *p1 = make_float2(acc[mt][nt][2] + b0, acc[mt][nt][3] + b1);
            } else {
                *reinterpret_cast<uint32_t*>((__half*)Cout + (size_t)r0 * N + col) =
                    pack_f16(acc[mt][nt][0] + b0, acc[mt][nt][1] + b1);
                *reinterpret_cast<uint32_t*>((__half*)Cout + (size_t)(r0 + 8) * N + col) =
                    pack_f16(acc[mt][nt][2] + b0, acc[mt][nt][3] + b1);
            }
        }
    }
}

// ---------------------------------------------------------------------------
// Fused qkv-derived prep (unchanged): rope + V transpose
// ---------------------------------------------------------------------------
#define P2_ROPE 4096
#define P2_TOTAL (P2_ROPE + (NN / 32) * 4 * (BB * HH))

__global__ void qkv_prep_kernel(const int* __restrict__ coords,
                                const __half* __restrict__ qkv,
                                __half* __restrict__ Qh,
                                __half* __restrict__ Kh,
                                __half* __restrict__ Vth) {
    const int bid = blockIdx.x;
    const int tid = threadIdx.y * 32 + threadIdx.x;

    if (bid < P2_ROPE) {
        __shared__ float cs[DD], sn[DD];
        const int token = bid;
        const int c0 = coords[token * 3 + 0];
        const int c1 = coords[token * 3 + 1];
        const int c2 = coords[token * 3 + 2];
        if (tid < DD) {
            const int j = tid;
            int jj, dd, coord;
            if (j < 34)      { const int u = j;      jj = (u < 17) ? u : u - 17; dd = 34; coord = c0; }
            else if (j < 68) { const int u = j - 34; jj = (u < 17) ? u : u - 17; dd = 34; coord = c1; }
            else             { const int u = j - 68; jj = (u < 18) ? u : u - 18; dd = 36; coord = c2; }
            const float inv = powf(10000.0f, -(2.0f * (float)jj) / (float)dd);
            const float ang = (float)coord * inv;
            cs[j] = cosf(ang);
            sn[j] = sinf(ang);
        }
        __syncthreads();

        const int half = tid >> 7;
        const int j = tid & 127;
        if (j >= DD) return;
        const int b = token >> 11, n = token & (NN - 1);
        const float scale = rsqrtf((float)DD) * 1.4426950408889634f;  // log2(e) folded
        const __half* base = qkv + (size_t)token * C3;

        for (int hh = half * 8; hh < half * 8 + 8; ++hh) {
            const size_t o = ((size_t)(b * HH + hh) * NN + n) * DD + j;
            const float qa = __half2float(base[hh * DD + j]);
            const float qrot = (j < 52) ? -__half2float(base[hh * DD + j + 52])
                                        :  __half2float(base[hh * DD + j - 52]);
            Qh[o] = __float2half_rn((qa * cs[j] + qrot * sn[j]) * scale);

            const float ka = __half2float(base[CC + hh * DD + j]);
            const float krot = (j < 52) ? -__half2float(base[CC + hh * DD + j + 52])
                                        :  __half2float(base[CC + hh * DD + j - 52]);
            Kh[o] = __float2half_rn(ka * cs[j] + krot * sn[j]);
        }
        return;
    }

    __shared__ float t[32][33];
    const int idx = bid - P2_ROPE;
    const int nb = idx % (NN / 32);
    const int db = (idx / (NN / 32)) % 4;
    const int bh = idx / ((NN / 32) * 4);
    const int b = bh >> 4, h = bh & 15;
    const int n0 = nb * 32;
    const int d0 = db * 32;
    const int tx = threadIdx.x, ty = threadIdx.y;
#pragma unroll
    for (int j = 0; j < 4; ++j) {
        const int d = d0 + tx, n = n0 + ty + 8 * j;
        if (d < DD)
            t[ty + 8 * j][tx] = __half2float(qkv[(size_t)(b * NN + n) * C3 + 2 * CC + h * DD + d]);
    }
    __syncthreads();
#pragma unroll
    for (int j = 0; j < 4; ++j) {
        const int d = d0 + ty + 8 * j, n = n0 + tx;
        if (d < DD)
            Vth[((size_t)bh * DD + d) * NN + n] = __float2half_rn(t[tx][ty + 8 * j]);
    }
}

// ---------------------------------------------------------------------------
// Flash attention, single fp16, exp2 softmax. 256 q/CTA, warp tile m32 x n64.
// Spill-free restructure: S+softmax per m-frag sequentially (sc regs reused),
// then joint PV pass (V read once). K b-frags are read twice per tile.
// ---------------------------------------------------------------------------
#define AT_Q     65536
#define AT_V     16384
#define AT_STAGE 29696

__global__ __launch_bounds__(256, 1)
void attn_mma_kernel(const __half* __restrict__ Qh,
                     const __half* __restrict__ Kh,
                     const __half* __restrict__ Vth,
                     __half* __restrict__ Oh) {
    extern __shared__ char smem[];
    const uint32_t sb = smem_u32(smem);
    const int tid = threadIdx.x, lane = tid & 31, wid = tid >> 5;
    const int qt = blockIdx.x, h = blockIdx.y, b = blockIdx.z;
    const int bh = b * HH + h;

    const __half* qh_p = Qh + ((size_t)bh * NN + qt * 256) * DD;
    const __half* kh_p = Kh + (size_t)bh * NN * DD;
    const __half* vh_p = Vth + (size_t)bh * DD * NN;

    for (int i = tid; i < 256 * 13; i += 256) {
        const int row = i / 13, c = i % 13;
        const uint32_t off = row * 256 + ((c ^ (row & 7)) << 4);
        cp_async16(sb + off, qh_p + (size_t)row * DD + c * 8);
    }
    cp_commit();

    auto load_stage = [&](int s, int kt) {
        const uint32_t st = sb + AT_Q + (uint32_t)s * AT_STAGE;
        const __half* kh_t = kh_p + (size_t)kt * 64 * DD;
        for (int i = tid; i < 64 * 13; i += 256) {
            const int row = i / 13, c = i % 13;
            const uint32_t off = row * 256 + ((c ^ (row & 7)) << 4);
            cp_async16(st + off, kh_t + (size_t)row * DD + c * 8);
        }
        const __half* vh_t = vh_p + kt * 64;
        for (int i = tid; i < 832; i += 256) {
            const int row = i >> 3, c = i & 7;
            const uint32_t off = row * 128 + ((c ^ (row & 7)) << 4);
            cp_async16(st + AT_V + off, vh_t + (size_t)row * NN + c * 8);
        }
        cp_commit();
    };

    load_stage(0, 0);
    load_stage(1, 1);
    asm volatile("cp.async.wait_group 2;");
    __syncthreads();

    const int a_lrow = (lane & 7) + ((lane >> 3) & 1) * 8;
    const int arow0 = wid * 32 + a_lrow;
    const int arow1 = arow0 + 16;

    // persistent m0 frags + both k8 frags (28 regs)
    uint32_t qah0[6][4], qa80[2], qa81[2];
#pragma unroll
    for (int j = 0; j < 6; ++j) {
        const int chn = 2 * j + (lane >> 4);
        ldmatrix_x4(qah0[j], sb + arow0 * 256 + ((chn ^ (arow0 & 7)) << 4));
    }
    ldmatrix_x2(qa80, sb + arow0 * 256 + ((12 ^ (arow0 & 7)) << 4));
    ldmatrix_x2(qa81, sb + arow1 * 256 + ((12 ^ (arow1 & 7)) << 4));

    float oc0[13][4], oc1[13][4];
#pragma unroll
    for (int i = 0; i < 13; ++i) {
        oc0[i][0] = oc0[i][1] = oc0[i][2] = oc0[i][3] = 0.0f;
        oc1[i][0] = oc1[i][1] = oc1[i][2] = oc1[i][3] = 0.0f;
    }
    float m0 = -1e30f, m1 = -1e30f, m2 = -1e30f, m3 = -1e30f;
    float l0 = 0.0f, l1 = 0.0f, l2 = 0.0f, l3 = 0.0f;

    const int nkt = NN / 64;
    for (int kt = 0; kt < nkt; ++kt) {
        if (kt + 2 <= nkt) {
            asm volatile("cp.async.wait_group 1;");
        } else {
            asm volatile("cp.async.wait_group 0;");
        }
        __syncthreads();
        if (kt + 2 < nkt) load_stage((kt + 2) % 3, kt + 2);

        const uint32_t st = sb + AT_Q + (uint32_t)(kt % 3) * AT_STAGE;

        uint32_t pah0[4][4], pah1[4][4];

        // ============ m-frag 0: S -> softmax -> pah0 ============
        {
            float sc[8][4];
#pragma unroll
            for (int nt = 0; nt < 8; ++nt) { sc[nt][0] = sc[nt][1] = sc[nt][2] = sc[nt][3] = 0.0f; }
#pragma unroll
            for (int jp = 0; jp < 3; ++jp) {
#pragma unroll
                for (int nt = 0; nt < 8; ++nt) {
                    const int brow = nt * 8 + (lane & 7);
                    const int bchn = 4 * jp + (lane >> 3);
                    const uint32_t addr = st + brow * 256 + ((bchn ^ (brow & 7)) << 4);
                    uint32_t bh4[4];
                    ldmatrix_x4(bh4, addr);
                    mma_f16(sc[nt], qah0[2 * jp],     &bh4[0]);
                    mma_f16(sc[nt], qah0[2 * jp + 1], &bh4[2]);
                }
            }
#pragma unroll
            for (int nt = 0; nt < 8; ++nt) {
                const int brow = nt * 8 + (lane & 7);
                uint32_t bh1;
                ldmatrix_x1(bh1, st + brow * 256 + ((12 ^ (brow & 7)) << 4));
                mma_f16_k8(sc[nt], qa80, bh1);
            }

            float mx0 = m0, mx1 = m1;
#pragma unroll
            for (int nt = 0; nt < 8; ++nt) {
                mx0 = fmaxf(mx0, fmaxf(sc[nt][0], sc[nt][1]));
                mx1 = fmaxf(mx1, fmaxf(sc[nt][2], sc[nt][3]));
            }
            mx0 = fmaxf(mx0, __shfl_xor_sync(0xffffffffu, mx0, 1));
            mx0 = fmaxf(mx0, __shfl_xor_sync(0xffffffffu, mx0, 2));
            mx1 = fmaxf(mx1, __shfl_xor_sync(0xffffffffu, mx1, 1));
            mx1 = fmaxf(mx1, __shfl_xor_sync(0xffffffffu, mx1, 2));
            const float a0 = exp2f(m0 - mx0), a1 = exp2f(m1 - mx1);
            m0 = mx0; m1 = mx1;
            l0 *= a0; l1 *= a1;
#pragma unroll
            for (int i = 0; i < 13; ++i) {
                oc0[i][0] *= a0; oc0[i][1] *= a0; oc0[i][2] *= a1; oc0[i][3] *= a1;
            }
#pragma unroll
            for (int jp = 0; jp < 4; ++jp) {
                const float p00 = exp2f(sc[2 * jp][0] - mx0);
                const float p01 = exp2f(sc[2 * jp][1] - mx0);
                const float p02 = exp2f(sc[2 * jp][2] - mx1);
                const float p03 = exp2f(sc[2 * jp][3] - mx1);
                const float p10 = exp2f(sc[2 * jp + 1][0] - mx0);
                const float p11 = exp2f(sc[2 * jp + 1][1] - mx0);
                const float p12 = exp2f(sc[2 * jp + 1][2] - mx1);
                const float p13 = exp2f(sc[2 * jp + 1][3] - mx1);
                l0 += p00 + p01 + p10 + p11;
                l1 += p02 + p03 + p12 + p13;
                pah0[jp][0] = pack_f16(p00, p01);
                pah0[jp][1] = pack_f16(p02, p03);
                pah0[jp][2] = pack_f16(p10, p11);
                pah0[jp][3] = pack_f16(p12, p13);
            }
        }

        // ============ m-frag 1: S -> softmax -> pah1 (sc regs reused) ======
        {
            float sc[8][4];
#pragma unroll
            for (int nt = 0; nt < 8; ++nt) { sc[nt][0] = sc[nt][1] = sc[nt][2] = sc[nt][3] = 0.0f; }
#pragma unroll
            for (int jp = 0; jp < 3; ++jp) {
                uint32_t q1a[4], q1b[4];
                const int c0n = 4 * jp + (lane >> 4);
                ldmatrix_x4(q1a, sb + arow1 * 256 + ((c0n ^ (arow1 & 7)) << 4));
                const int c1n = 4 * jp + 2 + (lane >> 4);
                ldmatrix_x4(q1b, sb + arow1 * 256 + ((c1n ^ (arow1 & 7)) << 4));
#pragma unroll
                for (int nt = 0; nt < 8; ++nt) {
                    const int brow = nt * 8 + (lane & 7);
                    const int bchn = 4 * jp + (lane >> 3);
                    const uint32_t addr = st + brow * 256 + ((bchn ^ (brow & 7)) << 4);
                    uint32_t bh4[4];
                    ldmatrix_x4(bh4, addr);
                    mma_f16(sc[nt], q1a, &bh4[0]);
                    mma_f16(sc[nt], q1b, &bh4[2]);
                }
            }
#pragma unroll
            for (int nt = 0; nt < 8; ++nt) {
                const int brow = nt * 8 + (lane & 7);
                uint32_t bh1;
                ldmatrix_x1(bh1, st + brow * 256 + ((12 ^ (brow & 7)) << 4));
                mma_f16_k8(sc[nt], qa81, bh1);
            }

            float mx2 = m2, mx3 = m3;
#pragma unroll
            for (int nt = 0; nt < 8; ++nt) {
                mx2 = fmaxf(mx2, fmaxf(sc[nt][0], sc[nt][1]));
                mx3 = fmaxf(mx3, fmaxf(sc[nt][2], sc[nt][3]));
            }
            mx2 = fmaxf(mx2, __shfl_xor_sync(0xffffffffu, mx2, 1));
            mx2 = fmaxf(mx2, __shfl_xor_sync(0xffffffffu, mx2, 2));
            mx3 = fmaxf(mx3, __shfl_xor_sync(0xffffffffu, mx3, 1));
            mx3 = fmaxf(mx3, __shfl_xor_sync(0xffffffffu, mx3, 2));
            const float a2 = exp2f(m2 - mx2), a3 = exp2f(m3 - mx3);
            m2 = mx2; m3 = mx3;
            l2 *= a2; l3 *= a3;
#pragma unroll
            for (int i = 0; i < 13; ++i) {
                oc1[i][0] *= a2; oc1[i][1] *= a2; oc1[i][2] *= a3; oc1[i][3] *= a3;
            }
#pragma unroll
            for (int jp = 0; jp < 4; ++jp) {
                const float p00 = exp2f(sc[2 * jp][0] - mx2);
                const float p01 = exp2f(sc[2 * jp][1] - mx2);
                const float p02 = exp2f(sc[2 * jp][2] - mx3);
                const float p03 = exp2f(sc[2 * jp][3] - mx3);
                const float p10 = exp2f(sc[2 * jp + 1][0] - mx2);
                const float p11 = exp2f(sc[2 * jp + 1][1] - mx2);
                const float p12 = exp2f(sc[2 * jp + 1][2] - mx3);
                const float p13 = exp2f(sc[2 * jp + 1][3] - mx3);
                l2 += p00 + p01 + p10 + p11;
                l3 += p02 + p03 + p12 + p13;
                pah1[jp][0] = pack_f16(p00, p01);
                pah1[jp][1] = pack_f16(p02, p03);
                pah1[jp][2] = pack_f16(p10, p11);
                pah1[jp][3] = pack_f16(p12, p13);
            }
        }

        // ============ joint PV: V read once, both frags ============
#pragma unroll
        for (int jph = 0; jph < 2; ++jph) {
#pragma unroll
            for (int ntd = 0; ntd < 13; ++ntd) {
                const int vrow = ntd * 8 + (lane & 7);
                const int vchn = 4 * jph + (lane >> 3);
                const uint32_t vaddr = st + AT_V + vrow * 128 + ((vchn ^ (vrow & 7)) << 4);
                uint32_t vh4[4];
                ldmatrix_x4(vh4, vaddr);
                mma_f16(oc0[ntd], pah0[2 * jph],     &vh4[0]);
                mma_f16(oc0[ntd], pah0[2 * jph + 1], &vh4[2]);
                mma_f16(oc1[ntd], pah1[2 * jph],     &vh4[0]);
                mma_f16(oc1[ntd], pah1[2 * jph + 1], &vh4[2]);
            }
        }
    }

    l0 += __shfl_xor_sync(0xffffffffu, l0, 1);
    l0 += __shfl_xor_sync(0xffffffffu, l0, 2);
    l1 += __shfl_xor_sync(0xffffffffu, l1, 1);
    l1 += __shfl_xor_sync(0xffffffffu, l1, 2);
    l2 += __shfl_xor_sync(0xffffffffu, l2, 1);
    l2 += __shfl_xor_sync(0xffffffffu, l2, 2);
    l3 += __shfl_xor_sync(0xffffffffu, l3, 1);
    l3 += __shfl_xor_sync(0xffffffffu, l3, 2);
    const float inv0 = 1.0f / l0, inv1 = 1.0f / l1;
    const float inv2 = 1.0f / l2, inv3 = 1.0f / l3;
    const int erow = lane >> 2;
    const int row0 = qt * 256 + wid * 32 + erow;
    const size_t tok0 = (size_t)b * NN + row0;
    const int colbase = h * DD + 2 * (lane & 3);
#pragma unroll
    for (int ntd = 0; ntd < 13; ++ntd) {
        const int col = colbase + ntd * 8;
        *reinterpret_cast<uint32_t*>(Oh + tok0 * CC + col) =
            pack_f16(oc0[ntd][0] * inv0, oc0[ntd][1] * inv0);
        *reinterpret_cast<uint32_t*>(Oh + (tok0 + 8) * CC + col) =
            pack_f16(oc0[ntd][2] * inv1, oc0[ntd][3] * inv1);
        *reinterpret_cast<uint32_t*>(Oh + (tok0 + 16) * CC + col) =
            pack_f16(oc1[ntd][0] * inv2, oc1[ntd][1] * inv2);
        *reinterpret_cast<uint32_t*>(Oh + (tok0 + 24) * CC + col) =
            pack_f16(oc1[ntd][2] * inv3, oc1[ntd][3] * inv3);
    }
}

// ---------------------------------------------------------------------------
// Launch
// ---------------------------------------------------------------------------
extern "C" void kernel_launch(void* const* d_in, const int* in_sizes, int n_in,
                              void* d_out, int out_size) {
    const float* x = nullptr;
    const int*   coords = nullptr;
    const float* qkv_w = nullptr;
    const float* qkv_b = nullptr;
    const float* proj_w = nullptr;
    const float* proj_b = nullptr;
    for (int i = 0; i < n_in; ++i) {
        switch (in_sizes[i]) {
            case TOKENS * CC:      x      = (const float*)d_in[i]; break;
            case TOKENS * 3:       coords = (const int*)d_in[i];   break;
            case CC * C3:          qkv_w  = (const float*)d_in[i]; break;
            case C3:               qkv_b  = (const float*)d_in[i]; break;
            case CC * CC:          proj_w = (const float*)d_in[i]; break;
            case CC:               proj_b = (const float*)d_in[i]; break;
            default: break;
        }
    }
    float* out = (float*)d_out;

    __half *qkv, *xh, *ah, *wq, *wp, *qh, *kh, *vth;
    cudaGetSymbolAddress((void**)&qkv, g_qkv);
    cudaGetSymbolAddress((void**)&xh,  g_xh);
    cudaGetSymbolAddress((void**)&ah,  g_ah);
    cudaGetSymbolAddress((void**)&wq,  g_wq);
    cudaGetSymbolAddress((void**)&wp,  g_wp);
    cudaGetSymbolAddress((void**)&qh,  g_qh);
    cudaGetSymbolAddress((void**)&kh,  g_kh);
    cudaGetSymbolAddress((void**)&vth, g_vth);

    const int gemm_smem = 3 * (128 * 128 + 128 * 128);   // 98304
    cudaFuncSetAttribute((void*)mma_gemm_kernel<__half, 4>, cudaFuncAttributeMaxDynamicSharedMemorySize, gemm_smem);
    cudaFuncSetAttribute((void*)mma_gemm_kernel<float, 4>,  cudaFuncAttributeMaxDynamicSharedMemorySize, gemm_smem);
    const int attn_smem = AT_Q + 3 * AT_STAGE;   // 154624
    cudaFuncSetAttribute(attn_mma_kernel, cudaFuncAttributeMaxDynamicSharedMemorySize, attn_smem);

    // 1) fused input prep
    prep_inputs_kernel<<<PREP_TOTAL, dim3(32, 8)>>>(x, qkv_w, proj_w, xh, wq, wp);

    // 2) QKV GEMM
    {
        dim3 grid(C3 / 128, TOKENS / 128);
        mma_gemm_kernel<__half, 4><<<grid, 256, gemm_smem>>>(xh, wq, qkv_b, qkv,
                                                             TOKENS, C3, CC);
    }

    // 3) fused rope + V transpose
    qkv_prep_kernel<<<P2_TOTAL, dim3(32, 8)>>>(coords, qkv, qh, kh, vth);

    // 4) Flash attention (256 q/CTA, spill-free)
    {
        dim3 grid(NN / 256, HH, BB);
        attn_mma_kernel<<<grid, 256, attn_smem>>>(qh, kh, vth, ah);
    }

    // 5) Projection GEMM
    {
        dim3 grid(CC / 128, TOKENS / 128);
        mma_gemm_kernel<float, 4><<<grid, 256, gemm_smem>>>(ah, wp, proj_b, out,
                                                            TOKENS, CC, CC);
    }
}